// round 10
// baseline (speedup 1.0000x reference)
#include <cuda_runtime.h>
#include <math.h>
#include <stdint.h>

#define INF_F (__int_as_float(0x7f800000))

// ---------------- problem constants ----------------
#define BQN 16
#define T0 1024
#define CD 256
#define ED 512
#define MAXROWS 131072

// ---------------- static device scratch ----------------
__device__ float g_tokens_t[BQN*T0*CD];
__device__ float g_tokens_q[BQN*512*CD];
__device__ float g_tq      [BQN*512*CD];
__device__ float g_QH      [BQN*512*CD];
__device__ float g_KH      [BQN*T0*CD];
__device__ float g_V       [BQN*T0*CD];
__device__ float g_mlph    [BQN*512*2*CD];
__device__ float g_wqh     [CD*CD];
__device__ float g_wkh     [CD*CD];
__device__ float g_centers_a[BQN*T0*3];
__device__ float g_centers_b[BQN*512*3];
__device__ int   g_rep[BQN*512];
__device__ int   g_nn [MAXROWS];
__device__ float g_psum[64*CD];
__device__ float g_psq [64*CD];
__device__ float g_stats[2*CD];   // [scale | shift]
__device__ float g_pool[BQN*CD];
__device__ float g_embv[BQN*ED];

// ---------------- FPS ----------------
__global__ void fps_kernel(const float* __restrict__ centers, int Tt, int Tq,
                           int* __restrict__ rep_idx) {
    int b = blockIdx.x;
    const float* P = centers + (size_t)b * Tt * 3;
    __shared__ float sx[1024], sy[1024], sz[1024];
    __shared__ float s_bv[8];
    __shared__ int   s_bi[8];
    __shared__ int   s_cur;
    int tid = threadIdx.x;
    int npt = Tt >> 8;
    float d[4];
#pragma unroll
    for (int j = 0; j < 4; j++) d[j] = INF_F;
    for (int j = tid; j < Tt; j += 256) {
        sx[j] = P[j*3+0]; sy[j] = P[j*3+1]; sz[j] = P[j*3+2];
    }
    if (tid == 0) s_cur = 0;
    __syncthreads();

    for (int step = 0; step < Tq; step++) {
        int cur = s_cur;
        if (tid == 0) rep_idx[b*Tq + step] = cur;
        float cx = sx[cur], cy = sy[cur], cz = sz[cur];
        float bv = -INF_F; int bi = 0x7fffffff;
#pragma unroll
        for (int j = 0; j < 4; j++) {
            if (j < npt) {
                int p = j*256 + tid;
                float dx = sx[p]-cx, dy = sy[p]-cy, dz = sz[p]-cz;
                float dist = dx*dx + dy*dy + dz*dz;
                float dj = fminf(d[j], dist);
                d[j] = dj;
                if (dj > bv || (dj == bv && p < bi)) { bv = dj; bi = p; }
            }
        }
#pragma unroll
        for (int off = 16; off > 0; off >>= 1) {
            float ov = __shfl_down_sync(0xffffffffu, bv, off);
            int   oi = __shfl_down_sync(0xffffffffu, bi, off);
            if (ov > bv || (ov == bv && oi < bi)) { bv = ov; bi = oi; }
        }
        if ((tid & 31) == 0) { s_bv[tid>>5] = bv; s_bi[tid>>5] = bi; }
        __syncthreads();
        if (tid == 0) {
            bv = s_bv[0]; bi = s_bi[0];
            for (int w = 1; w < 8; w++) {
                if (s_bv[w] > bv || (s_bv[w] == bv && s_bi[w] < bi)) { bv = s_bv[w]; bi = s_bi[w]; }
            }
            s_cur = bi;
        }
        __syncthreads();
    }
}

// ---------------- gather query rows ----------------
__global__ void gather_kernel(const float* __restrict__ tok_t,
                              const float* __restrict__ cent_t,
                              const int* __restrict__ rep,
                              float* __restrict__ tok_q,
                              float* __restrict__ cent_q,
                              int Tt, int Tq) {
    int p = blockIdx.x;
    int b = p / Tq;
    int src = rep[p];
    int c = threadIdx.x;
    tok_q[(size_t)p*CD + c] = tok_t[(size_t)(b*Tt + src)*CD + c];
    if (c < 3) cent_q[p*3 + c] = cent_t[(size_t)(b*Tt + src)*3 + c];
}

// ---------------- KNN ----------------
__global__ void knn_kernel(const float* __restrict__ cent_q,
                           const float* __restrict__ cent_t,
                           int Tt, int Tq, int k, int* __restrict__ nn) {
    int p = blockIdx.x;
    int b = p / Tq;
    __shared__ float d2s[1024];
    __shared__ float s_bv[8];
    __shared__ int   s_bi[8];
    int tid = threadIdx.x;
    float qx = cent_q[p*3], qy = cent_q[p*3+1], qz = cent_q[p*3+2];
    float qq = qx*qx + qy*qy + qz*qz;
    const float* Pt = cent_t + (size_t)b*Tt*3;
    for (int t = tid; t < Tt; t += 256) {
        float tx = Pt[t*3], ty = Pt[t*3+1], tz = Pt[t*3+2];
        float tt = tx*tx + ty*ty + tz*tz;
        float dt = qx*tx + qy*ty + qz*tz;
        d2s[t] = (qq + tt) - 2.0f*dt;
    }
    __syncthreads();
    for (int sel = 0; sel < k; sel++) {
        float bv = INF_F; int bi = 0x7fffffff;
        for (int t = tid; t < Tt; t += 256) {
            float v = d2s[t];
            if (v < bv || (v == bv && t < bi)) { bv = v; bi = t; }
        }
#pragma unroll
        for (int off = 16; off > 0; off >>= 1) {
            float ov = __shfl_down_sync(0xffffffffu, bv, off);
            int   oi = __shfl_down_sync(0xffffffffu, bi, off);
            if (ov < bv || (ov == bv && oi < bi)) { bv = ov; bi = oi; }
        }
        if ((tid & 31) == 0) { s_bv[tid>>5] = bv; s_bi[tid>>5] = bi; }
        __syncthreads();
        if (tid == 0) {
            bv = s_bv[0]; bi = s_bi[0];
            for (int w = 1; w < 8; w++) {
                if (s_bv[w] < bv || (s_bv[w] == bv && s_bi[w] < bi)) { bv = s_bv[w]; bi = s_bi[w]; }
            }
            nn[p*k + sel] = bi;
            d2s[bi] = INF_F;
        }
        __syncthreads();
    }
}

// ---------------- BN stats ----------------
__global__ void bn_partial(const float* __restrict__ x1, int rows1,
                           const float* __restrict__ x2, int rows2,
                           float* __restrict__ psum, float* __restrict__ psq) {
    int c = threadIdx.x;
    int total = rows1 + rows2;
    float s = 0.f, sq = 0.f;
    for (int r = blockIdx.x; r < total; r += gridDim.x) {
        const float* row = (r < rows1) ? (x1 + (size_t)r*CD) : (x2 + (size_t)(r - rows1)*CD);
        float v = row[c];
        s += v; sq += v*v;
    }
    psum[blockIdx.x*CD + c] = s;
    psq [blockIdx.x*CD + c] = sq;
}

__global__ void bn_finalize(const float* __restrict__ psum, const float* __restrict__ psq,
                            int nb, int rows,
                            const float* __restrict__ gamma, const float* __restrict__ beta,
                            float* __restrict__ stats) {
    int c = threadIdx.x;
    float s = 0.f, sq = 0.f;
    for (int b = 0; b < nb; b++) { s += psum[b*CD + c]; sq += psq[b*CD + c]; }
    float m = s / (float)rows;
    float v = sq / (float)rows - m*m;
    float rstd = rsqrtf(v + 1e-5f);
    float sc = gamma[c] * rstd;
    stats[c]      = sc;
    stats[CD + c] = beta[c] - m * sc;
}

// ---------------- exact-fp32 weight product: C[256,256] = A @ B ----------------
// grid 32, 256 thr, 8 rows/block; 8 independent acc chains per thread
__global__ void wprod_kernel(const float* __restrict__ A, int lda,
                             const float* __restrict__ B, int ldb,
                             float* __restrict__ C) {
    __shared__ float arow[8][CD];
    int r0 = blockIdx.x*8;
    int tid = threadIdx.x;
#pragma unroll
    for (int i = 0; i < 8; i++) arow[i][tid] = A[(size_t)(r0+i)*lda + tid];
    __syncthreads();
    float acc[8];
#pragma unroll
    for (int i = 0; i < 8; i++) acc[i] = 0.f;
#pragma unroll 4
    for (int c = 0; c < CD; c++) {
        float bv = B[(size_t)c*ldb + tid];
#pragma unroll
        for (int i = 0; i < 8; i++) acc[i] += arow[i][c]*bv;
    }
#pragma unroll
    for (int i = 0; i < 8; i++) C[(size_t)(r0+i)*CD + tid] = acc[i];
}

// ---------------- TF32 tensor-core GEMM, TBK=32, 2-stage cp.async ----------------
#define TBM 128
#define TBN 128
#define TBK 32
#define AS_STRIDE 36
#define BS_STRIDE 136
#define A_ELEMS (TBM*AS_STRIDE)
#define B_ELEMS (TBK*BS_STRIDE)

__device__ __forceinline__ void mma_tf32(float* c, const uint32_t* a, const uint32_t* b) {
    asm volatile(
        "mma.sync.aligned.m16n8k8.row.col.f32.tf32.tf32.f32 "
        "{%0,%1,%2,%3}, {%4,%5,%6,%7}, {%8,%9}, {%0,%1,%2,%3};\n"
        : "+f"(c[0]), "+f"(c[1]), "+f"(c[2]), "+f"(c[3])
        : "r"(a[0]), "r"(a[1]), "r"(a[2]), "r"(a[3]),
          "r"(b[0]), "r"(b[1]));
}

__device__ __forceinline__ void cp_async16(uint32_t dst, const void* src) {
    asm volatile("cp.async.cg.shared.global [%0], [%1], 16;" :: "r"(dst), "l"(src));
}
__device__ __forceinline__ void cp_commit() {
    asm volatile("cp.async.commit_group;");
}
__device__ __forceinline__ void cp_wait1() {
    asm volatile("cp.async.wait_group 1;");
}

// MODE 0: plain A. MODE 1: A[r] = relu(QH - KH[nn] + b1) (sc_s = b1).
// MODE 2: A = A*sc_s[c] + sh_s[c]  (BN folded).
template<int MODE>
__device__ __forceinline__ void gemm_mainloop(
    float acc[4][4][4],
    const float* __restrict__ A, int lda,
    const float* __restrict__ QH, const float* __restrict__ KH,
    const int* sQoff, const int* sKoff,
    const float* sc_s, const float* sh_s,
    const float* __restrict__ B, int ldb,
    int K, int row0, int col0,
    float* smem, int STAGE,
    int tid, int lane, int wm, int wn)
{
    int ldrow = tid >> 3;
    int ldcol = (tid & 7) * 4;

    auto load_stage = [&](int s, int kt) {
        float* As_  = smem + s*STAGE;
        float* Akv_ = As_ + A_ELEMS;
        float* Bs_  = As_ + (MODE == 1 ? 2*A_ELEMS : A_ELEMS);
#pragma unroll
        for (int i = 0; i < 4; i++) {
            int arow = ldrow + 32*i;
            uint32_t dA = (uint32_t)__cvta_generic_to_shared(&As_[arow*AS_STRIDE + ldcol]);
            if (MODE == 1) {
                cp_async16(dA, QH + sQoff[arow] + kt + ldcol);
                uint32_t dK = (uint32_t)__cvta_generic_to_shared(&Akv_[arow*AS_STRIDE + ldcol]);
                cp_async16(dK, KH + sKoff[arow] + kt + ldcol);
            } else {
                cp_async16(dA, A + (size_t)(row0 + arow)*lda + kt + ldcol);
            }
        }
#pragma unroll
        for (int i = 0; i < 4; i++) {
            int bcol = ldcol + 32*i;
            uint32_t dB = (uint32_t)__cvta_generic_to_shared(&Bs_[ldrow*BS_STRIDE + bcol]);
            cp_async16(dB, B + (size_t)(kt + ldrow)*ldb + col0 + bcol);
        }
    };

    const int NIT = K / TBK;
    load_stage(0, 0);
    cp_commit();

    for (int it = 0; it < NIT; it++) {
        if (it + 1 < NIT) load_stage((it+1)&1, (it+1)*TBK);
        cp_commit();
        cp_wait1();
        __syncthreads();

        int s = it & 1;
        int ktg = it*TBK;
        const float* As_  = smem + s*STAGE;
        const float* Akv_ = As_ + A_ELEMS;
        const float* Bs_  = As_ + (MODE == 1 ? 2*A_ELEMS : A_ELEMS);

#pragma unroll
        for (int kk = 0; kk < 4; kk++) {
            int kc = kk*8;
            float cA = 0.f, cB = 0.f, hA = 0.f, hB = 0.f;
            if (MODE == 1) {
                cA = sc_s[ktg + kc + (lane&3)];
                cB = sc_s[ktg + kc + 4 + (lane&3)];
            } else if (MODE == 2) {
                cA = sc_s[ktg + kc + (lane&3)];
                cB = sc_s[ktg + kc + 4 + (lane&3)];
                hA = sh_s[ktg + kc + (lane&3)];
                hB = sh_s[ktg + kc + 4 + (lane&3)];
            }
            uint32_t a[4][4];
#pragma unroll
            for (int mf = 0; mf < 4; mf++) {
                int r1 = wm*64 + mf*16 + (lane>>2);
                int i0 = r1*AS_STRIDE      + kc + (lane&3);
                int i1 = (r1+8)*AS_STRIDE  + kc + (lane&3);
                if (MODE == 1) {
                    a[mf][0] = __float_as_uint(fmaxf(As_[i0]     - Akv_[i0]     + cA, 0.f));
                    a[mf][1] = __float_as_uint(fmaxf(As_[i1]     - Akv_[i1]     + cA, 0.f));
                    a[mf][2] = __float_as_uint(fmaxf(As_[i0 + 4] - Akv_[i0 + 4] + cB, 0.f));
                    a[mf][3] = __float_as_uint(fmaxf(As_[i1 + 4] - Akv_[i1 + 4] + cB, 0.f));
                } else if (MODE == 2) {
                    a[mf][0] = __float_as_uint(fmaf(As_[i0],     cA, hA));
                    a[mf][1] = __float_as_uint(fmaf(As_[i1],     cA, hA));
                    a[mf][2] = __float_as_uint(fmaf(As_[i0 + 4], cB, hB));
                    a[mf][3] = __float_as_uint(fmaf(As_[i1 + 4], cB, hB));
                } else {
                    a[mf][0] = __float_as_uint(As_[i0]);
                    a[mf][1] = __float_as_uint(As_[i1]);
                    a[mf][2] = __float_as_uint(As_[i0 + 4]);
                    a[mf][3] = __float_as_uint(As_[i1 + 4]);
                }
            }
            uint32_t b[4][2];
#pragma unroll
            for (int nf = 0; nf < 4; nf++) {
                int ncol = wn*32 + nf*8 + (lane>>2);
                b[nf][0] = __float_as_uint(Bs_[(kc     + (lane&3))*BS_STRIDE + ncol]);
                b[nf][1] = __float_as_uint(Bs_[(kc + 4 + (lane&3))*BS_STRIDE + ncol]);
            }
#pragma unroll
            for (int mf = 0; mf < 4; mf++)
#pragma unroll
                for (int nf = 0; nf < 4; nf++)
                    mma_tf32(acc[mf][nf], a[mf], b[nf]);
        }
        __syncthreads();
    }
}

// plain/BN GEMM: C = (A or bn(A))@B (+bias)(+resid)(relu)
template<int BN>
__global__ __launch_bounds__(256)
void tf32gemm(int M, int N, int K, int lda, int ldb,
              const float* __restrict__ A,
              const float* __restrict__ B,
              const float* __restrict__ bnstats,
              const float* __restrict__ bias, const float* __restrict__ resid,
              float* __restrict__ C, int relu) {
    extern __shared__ float smem[];
    const int STAGE = A_ELEMS + B_ELEMS;
    __shared__ float scs[CD], shs[CD];

    int tid  = threadIdx.x;
    int lane = tid & 31;
    int warp = tid >> 5;
    int wm = warp >> 2;
    int wn = warp & 3;
    int row0 = blockIdx.y*TBM;
    int col0 = blockIdx.x*TBN;

    if (BN) {
        scs[tid] = bnstats[tid];
        shs[tid] = bnstats[CD + tid];
        __syncthreads();
    }

    float acc[4][4][4];
#pragma unroll
    for (int i = 0; i < 4; i++)
#pragma unroll
        for (int j = 0; j < 4; j++)
#pragma unroll
            for (int r = 0; r < 4; r++) acc[i][j][r] = 0.f;

    gemm_mainloop<BN ? 2 : 0>(acc, A, lda, nullptr, nullptr, nullptr, nullptr,
                              scs, shs, B, ldb, K, row0, col0,
                              smem, STAGE, tid, lane, wm, wn);

#pragma unroll
    for (int mf = 0; mf < 4; mf++) {
#pragma unroll
        for (int nf = 0; nf < 4; nf++) {
            int r = row0 + wm*64 + mf*16 + (lane>>2);
            int c = col0 + wn*32 + nf*8 + (lane&3)*2;
#pragma unroll
            for (int half = 0; half < 2; half++) {
                int rr = r + half*8;
                float v0 = acc[mf][nf][half*2+0];
                float v1 = acc[mf][nf][half*2+1];
                if (bias)  { v0 += bias[c]; v1 += bias[c+1]; }
                if (resid) {
                    const float2 rv = *(const float2*)(resid + (size_t)rr*N + c);
                    v0 += rv.x; v1 += rv.y;
                }
                if (relu) { v0 = fmaxf(v0, 0.f); v1 = fmaxf(v1, 0.f); }
                float2 out; out.x = v0; out.y = v1;
                *(float2*)(C + (size_t)rr*N + c) = out;
            }
        }
    }
}

// fused attention GEMM
#define SIM_STRIDE 132
__global__ __launch_bounds__(256)
void tf32gemm_attn(int M, int N, int K,
                   const float* __restrict__ QH, const float* __restrict__ KH,
                   const float* __restrict__ b1,
                   const float* __restrict__ B,
                   const float* __restrict__ bias,
                   const float* __restrict__ V,
                   const int* __restrict__ nn, int Tq, int knn_k, int Tt,
                   const float* __restrict__ skipb,
                   float* __restrict__ out) {
    extern __shared__ float smem[];
    const int STAGE = 2*A_ELEMS + B_ELEMS;
    __shared__ int   sQoff[TBM];
    __shared__ int   sKoff[TBM];
    __shared__ float b1s[CD];

    int tid  = threadIdx.x;
    int lane = tid & 31;
    int warp = tid >> 5;
    int wm = warp >> 2;
    int wn = warp & 3;
    int row0 = blockIdx.y*TBM;
    int col0 = blockIdx.x*TBN;

    if (tid < TBM) {
        int r = row0 + tid;
        int p = r / knn_k;
        int b = p / Tq;
        sQoff[tid] = p * CD;
        sKoff[tid] = (b*Tt + nn[r]) * CD;
    }
    b1s[tid] = b1[tid];
    __syncthreads();

    float acc[4][4][4];
#pragma unroll
    for (int i = 0; i < 4; i++)
#pragma unroll
        for (int j = 0; j < 4; j++)
#pragma unroll
            for (int r = 0; r < 4; r++) acc[i][j][r] = 0.f;

    gemm_mainloop<1>(acc, nullptr, 0, QH, KH, sQoff, sKoff, b1s, nullptr,
                     B, CD, K, row0, col0, smem, STAGE, tid, lane, wm, wn);

    float* sim_s = smem;
#pragma unroll
    for (int mf = 0; mf < 4; mf++) {
#pragma unroll
        for (int nf = 0; nf < 4; nf++) {
            int r = wm*64 + mf*16 + (lane>>2);
            int c = wn*32 + nf*8 + (lane&3)*2;
#pragma unroll
            for (int half = 0; half < 2; half++) {
                int rr = r + half*8;
                float v0 = acc[mf][nf][half*2+0] + bias[col0 + c];
                float v1 = acc[mf][nf][half*2+1] + bias[col0 + c + 1];
                sim_s[rr*SIM_STRIDE + c]     = v0;
                sim_s[rr*SIM_STRIDE + c + 1] = v1;
            }
        }
    }
    __syncthreads();

    int ppb = TBM / knn_k;
    int col = tid & 127;
    int cg  = col0 + col;
    for (int pp = tid >> 7; pp < ppb; pp += 2) {
        const float* Sp = sim_s + (pp*knn_k)*SIM_STRIDE + col;
        float m = -INF_F;
        for (int n = 0; n < knn_k; n++) m = fmaxf(m, Sp[n*SIM_STRIDE]);
        float den = 0.f, accv = 0.f;
        for (int n = 0; n < knn_k; n++) {
            float e = expf(Sp[n*SIM_STRIDE] - m);
            den += e;
            accv += e * V[(size_t)sKoff[pp*knn_k + n] + cg];
        }
        int pg = row0/knn_k + pp;
        out[(size_t)pg*CD + cg] = accv/den + skipb[(size_t)pg*CD + cg];
    }
}

// ---------------- final pooling / embedding ----------------
__global__ void pool_kernel(const float* __restrict__ tok, float* __restrict__ g, int Tq) {
    int b = blockIdx.x, c = threadIdx.x;
    float s = 0.f;
    for (int t = 0; t < Tq; t++) s += tok[(size_t)(b*Tq + t)*CD + c];
    g[b*CD + c] = s / (float)Tq;
}

__global__ void emb_kernel(const float* __restrict__ g, const float* __restrict__ W,
                           const float* __restrict__ bias, float* __restrict__ out) {
    int b = blockIdx.x, e = threadIdx.x;
    __shared__ float gs[CD];
    if (e < CD) gs[e] = g[b*CD + e];
    __syncthreads();
    float s = 0.f;
    for (int c = 0; c < CD; c++) s += gs[c] * W[(size_t)c*ED + e];
    out[b*ED + e] = s + bias[e];
}

__global__ void final_bn_kernel(float* __restrict__ x, const float* __restrict__ gamma,
                                const float* __restrict__ beta) {
    int e = threadIdx.x;
    float s = 0.f;
    for (int b = 0; b < BQN; b++) s += x[b*ED + e];
    float m = s / (float)BQN;
    float v = 0.f;
    for (int b = 0; b < BQN; b++) { float d = x[b*ED + e] - m; v += d*d; }
    v /= (float)BQN;
    float rs = rsqrtf(v + 1e-5f);
    for (int b = 0; b < BQN; b++) {
        float val = (x[b*ED + e] - m) * rs * gamma[e] + beta[e];
        x[b*ED + e] = fmaxf(val, 0.f);
    }
}

__global__ void topk_norm_kernel(const float* __restrict__ x, float* __restrict__ out) {
    int b = blockIdx.x, t = threadIdx.x;
    __shared__ float vals[ED], work[ED];
    __shared__ float red[16];
    __shared__ int   redi[16];
    __shared__ float s_thr, s_norm;
    float v = x[b*ED + t];
    vals[t] = v; work[t] = v;
    __syncthreads();
    for (int it = 0; it < 64; it++) {
        float bv = work[t]; int bi = t;
#pragma unroll
        for (int off = 16; off > 0; off >>= 1) {
            float ov = __shfl_down_sync(0xffffffffu, bv, off);
            int   oi = __shfl_down_sync(0xffffffffu, bi, off);
            if (ov > bv) { bv = ov; bi = oi; }
        }
        if ((t & 31) == 0) { red[t>>5] = bv; redi[t>>5] = bi; }
        __syncthreads();
        if (t == 0) {
            bv = red[0]; bi = redi[0];
            for (int w = 1; w < 16; w++) if (red[w] > bv) { bv = red[w]; bi = redi[w]; }
            work[bi] = -INF_F;
            if (it == 63) s_thr = bv;
        }
        __syncthreads();
    }
    float thr = s_thr;
    float kept = (vals[t] >= thr) ? vals[t] : 0.f;
    float sq = kept*kept;
#pragma unroll
    for (int off = 16; off > 0; off >>= 1) sq += __shfl_down_sync(0xffffffffu, sq, off);
    if ((t & 31) == 0) red[t>>5] = sq;
    __syncthreads();
    if (t == 0) {
        float s = 0.f;
        for (int w = 0; w < 16; w++) s += red[w];
        s_norm = fmaxf(sqrtf(s), 1e-12f);
    }
    __syncthreads();
    out[b*ED + t] = kept / s_norm;
}

// ---------------- host orchestration ----------------
extern "C" void kernel_launch(void* const* d_in, const int* in_sizes, int n_in,
                              void* d_out, int out_size) {
    const float* tokens = (const float*)d_in[0];
    const float* centers = (const float*)d_in[1];
    const float* wq     = (const float*)d_in[3];
    const float* wkv    = (const float*)d_in[4];
    const float* mlp_w1 = (const float*)d_in[5];
    const float* mlp_b1 = (const float*)d_in[6];
    const float* mlp_w2 = (const float*)d_in[7];
    const float* mlp_b2 = (const float*)d_in[8];
    const float* bn1_g  = (const float*)d_in[9];
    const float* bn1_b  = (const float*)d_in[10];
    const float* bn2_g  = (const float*)d_in[11];
    const float* bn2_b  = (const float*)d_in[12];
    const float* att_w1 = (const float*)d_in[13];
    const float* att_b1 = (const float*)d_in[14];
    const float* att_w2 = (const float*)d_in[15];
    const float* att_b2 = (const float*)d_in[16];
    const float* emb_w  = (const float*)d_in[17];
    const float* emb_b  = (const float*)d_in[18];
    const float* embn_g = (const float*)d_in[19];
    const float* embn_b = (const float*)d_in[20];

    float *tok_buf, *tok_q, *tq, *QH, *KH, *V, *mlph, *wqh, *wkh;
    float *cent_a, *cent_b, *psum, *psq, *stats, *pool, *embv;
    int *rep, *nn;
    cudaGetSymbolAddress((void**)&tok_buf, g_tokens_t);
    cudaGetSymbolAddress((void**)&tok_q,  g_tokens_q);
    cudaGetSymbolAddress((void**)&tq,     g_tq);
    cudaGetSymbolAddress((void**)&QH,     g_QH);
    cudaGetSymbolAddress((void**)&KH,     g_KH);
    cudaGetSymbolAddress((void**)&V,      g_V);
    cudaGetSymbolAddress((void**)&mlph,   g_mlph);
    cudaGetSymbolAddress((void**)&wqh,    g_wqh);
    cudaGetSymbolAddress((void**)&wkh,    g_wkh);
    cudaGetSymbolAddress((void**)&cent_a, g_centers_a);
    cudaGetSymbolAddress((void**)&cent_b, g_centers_b);
    cudaGetSymbolAddress((void**)&psum,   g_psum);
    cudaGetSymbolAddress((void**)&psq,    g_psq);
    cudaGetSymbolAddress((void**)&stats,  g_stats);
    cudaGetSymbolAddress((void**)&pool,   g_pool);
    cudaGetSymbolAddress((void**)&embv,   g_embv);
    cudaGetSymbolAddress((void**)&rep,    g_rep);
    cudaGetSymbolAddress((void**)&nn,     g_nn);

    const int SMEM_PLAIN = 2*(A_ELEMS + B_ELEMS)*sizeof(float);
    const int SMEM_ATTN  = 2*(2*A_ELEMS + B_ELEMS)*sizeof(float);
    static bool attr_set = false;
    if (!attr_set) {
        cudaFuncSetAttribute(tf32gemm<0>,   cudaFuncAttributeMaxDynamicSharedMemorySize, SMEM_PLAIN);
        cudaFuncSetAttribute(tf32gemm<1>,   cudaFuncAttributeMaxDynamicSharedMemorySize, SMEM_PLAIN);
        cudaFuncSetAttribute(tf32gemm_attn, cudaFuncAttributeMaxDynamicSharedMemorySize, SMEM_ATTN);
        attr_set = true;
    }

    const int Tts[3] = {1024, 512, 256};
    const int Tqs[3] = {512, 256, 128};
    const int ks [3] = {16, 32, 64};

    const float* tok_src  = tokens;
    const float* cent_src = centers;
    float* cent_dsts[3] = {cent_a, cent_b, cent_a};

    for (int i = 0; i < 3; i++) {
        int Tt = Tts[i], Tq = Tqs[i], k = ks[i];
        int Mq = BQN*Tq, Mt = BQN*Tt, Mr = Mq*k;
        float* cent_dst = cent_dsts[i];

        fps_kernel   <<<BQN, 256>>>(cent_src, Tt, Tq, rep);
        gather_kernel<<<Mq, 256>>>(tok_src, cent_src, rep, tok_q, cent_dst, Tt, Tq);
        knn_kernel   <<<Mq, 256>>>(cent_dst, cent_src, Tt, Tq, k, nn);

        // weight products in exact fp32
        wprod_kernel<<<32, 256>>>(wq  + (size_t)i*CD*CD,   CD,   att_w1 + (size_t)i*CD*CD, CD, wqh);
        wprod_kernel<<<32, 256>>>(wkv + (size_t)i*CD*2*CD, 2*CD, att_w1 + (size_t)i*CD*CD, CD, wkh);

        if (i > 0) {
            bn_partial <<<64, 256>>>(tok_q, Mq, tok_src, Mt, psum, psq);
            bn_finalize<<<1, 256>>>(psum, psq, 64, Mq + Mt, bn1_g + i*CD, bn1_b + i*CD, stats);

            tf32gemm<1><<<dim3(CD/TBN, Mq/TBM), 256, SMEM_PLAIN>>>(Mq, CD, CD, CD, CD,
                tok_q, wqh, stats, nullptr, nullptr, QH, 0);
            tf32gemm<1><<<dim3(CD/TBN, Mt/TBM), 256, SMEM_PLAIN>>>(Mt, CD, CD, CD, CD,
                tok_src, wkh, stats, nullptr, nullptr, KH, 0);
            tf32gemm<1><<<dim3(CD/TBN, Mt/TBM), 256, SMEM_PLAIN>>>(Mt, CD, CD, CD, 2*CD,
                tok_src, wkv + (size_t)i*CD*2*CD + CD, stats, nullptr, nullptr, V, 0);
        } else {
            tf32gemm<0><<<dim3(CD/TBN, Mq/TBM), 256, SMEM_PLAIN>>>(Mq, CD, CD, CD, CD,
                tok_q, wqh, nullptr, nullptr, nullptr, QH, 0);
            tf32gemm<0><<<dim3(CD/TBN, Mt/TBM), 256, SMEM_PLAIN>>>(Mt, CD, CD, CD, CD,
                tok_src, wkh, nullptr, nullptr, nullptr, KH, 0);
            tf32gemm<0><<<dim3(CD/TBN, Mt/TBM), 256, SMEM_PLAIN>>>(Mt, CD, CD, CD, 2*CD,
                tok_src, wkv + (size_t)i*CD*2*CD + CD, nullptr, nullptr, nullptr, V, 0);
        }

        // fused: sim = relu(QH[p]-KH[nn]+b1) @ att_w2 + b2 -> softmax -> V -> +skip(tok_q)
        tf32gemm_attn<<<dim3(CD/TBN, Mr/TBM), 256, SMEM_ATTN>>>(Mr, CD, CD,
            QH, KH, att_b1 + i*CD,
            att_w2 + (size_t)i*CD*CD, att_b2 + i*CD,
            V, nn, Tq, k, Tt, tok_q, tq);

        bn_partial <<<64, 256>>>(tq, Mq, nullptr, 0, psum, psq);
        bn_finalize<<<1, 256>>>(psum, psq, 64, Mq, bn2_g + i*CD, bn2_b + i*CD, stats);

        tf32gemm<1><<<dim3(2*CD/TBN, Mq/TBM), 256, SMEM_PLAIN>>>(Mq, 2*CD, CD, CD, 2*CD,
            tq, mlp_w1 + (size_t)i*CD*2*CD, stats, mlp_b1 + i*2*CD, nullptr, mlph, 1);
        tf32gemm<0><<<dim3(CD/TBN, Mq/TBM), 256, SMEM_PLAIN>>>(Mq, CD, 2*CD, 2*CD, CD,
            mlph, mlp_w2 + (size_t)i*2*CD*CD, nullptr, mlp_b2 + i*CD, tq, tok_buf, 0);

        tok_src  = tok_buf;
        cent_src = cent_dst;
    }

    pool_kernel     <<<BQN, 256>>>(tok_buf, pool, 128);
    emb_kernel      <<<BQN, 512>>>(pool, emb_w, emb_b, embv);
    final_bn_kernel <<<1, 512>>>(embv, embn_g, embn_b);
    topk_norm_kernel<<<BQN, 512>>>(embv, (float*)d_out);
}

// round 11
// speedup vs baseline: 1.1297x; 1.1297x over previous
#include <cuda_runtime.h>
#include <math.h>
#include <stdint.h>

#define INF_F (__int_as_float(0x7f800000))

// ---------------- problem constants ----------------
#define BQN 16
#define T0 1024
#define CD 256
#define ED 512
#define MAXROWS 131072

// ---------------- static device scratch ----------------
__device__ float g_tokens_t[BQN*T0*CD];
__device__ float g_tokens_q[BQN*512*CD];
__device__ float g_tq      [BQN*512*CD];
__device__ float g_QH      [BQN*512*CD];
__device__ float g_KH      [BQN*T0*CD];
__device__ float g_V       [BQN*T0*CD];
__device__ float g_mlph    [BQN*512*2*CD];
__device__ float g_wqh     [3*CD*CD];
__device__ float g_wkh     [3*CD*CD];
__device__ float g_centers_a[BQN*T0*3];
__device__ float g_centers_b[BQN*512*3];
__device__ int   g_rep[BQN*512];
__device__ int   g_nn [MAXROWS];
__device__ float g_psum[64*CD];
__device__ float g_psq [64*CD];
__device__ float g_stats[2*CD];   // [scale | shift]
__device__ float g_pool[BQN*CD];
__device__ float g_embv[BQN*ED];

// ---------------- FPS ----------------
__global__ void fps_kernel(const float* __restrict__ centers, int Tt, int Tq,
                           int* __restrict__ rep_idx) {
    int b = blockIdx.x;
    const float* P = centers + (size_t)b * Tt * 3;
    __shared__ float sx[1024], sy[1024], sz[1024];
    __shared__ float s_bv[8];
    __shared__ int   s_bi[8];
    __shared__ int   s_cur;
    int tid = threadIdx.x;
    int npt = Tt >> 8;
    float d[4];
#pragma unroll
    for (int j = 0; j < 4; j++) d[j] = INF_F;
    for (int j = tid; j < Tt; j += 256) {
        sx[j] = P[j*3+0]; sy[j] = P[j*3+1]; sz[j] = P[j*3+2];
    }
    if (tid == 0) s_cur = 0;
    __syncthreads();

    for (int step = 0; step < Tq; step++) {
        int cur = s_cur;
        if (tid == 0) rep_idx[b*Tq + step] = cur;
        float cx = sx[cur], cy = sy[cur], cz = sz[cur];
        float bv = -INF_F; int bi = 0x7fffffff;
#pragma unroll
        for (int j = 0; j < 4; j++) {
            if (j < npt) {
                int p = j*256 + tid;
                float dx = sx[p]-cx, dy = sy[p]-cy, dz = sz[p]-cz;
                float dist = dx*dx + dy*dy + dz*dz;
                float dj = fminf(d[j], dist);
                d[j] = dj;
                if (dj > bv || (dj == bv && p < bi)) { bv = dj; bi = p; }
            }
        }
#pragma unroll
        for (int off = 16; off > 0; off >>= 1) {
            float ov = __shfl_down_sync(0xffffffffu, bv, off);
            int   oi = __shfl_down_sync(0xffffffffu, bi, off);
            if (ov > bv || (ov == bv && oi < bi)) { bv = ov; bi = oi; }
        }
        if ((tid & 31) == 0) { s_bv[tid>>5] = bv; s_bi[tid>>5] = bi; }
        __syncthreads();
        if (tid == 0) {
            bv = s_bv[0]; bi = s_bi[0];
            for (int w = 1; w < 8; w++) {
                if (s_bv[w] > bv || (s_bv[w] == bv && s_bi[w] < bi)) { bv = s_bv[w]; bi = s_bi[w]; }
            }
            s_cur = bi;
        }
        __syncthreads();
    }
}

// ---------------- gather query rows ----------------
__global__ void gather_kernel(const float* __restrict__ tok_t,
                              const float* __restrict__ cent_t,
                              const int* __restrict__ rep,
                              float* __restrict__ tok_q,
                              float* __restrict__ cent_q,
                              int Tt, int Tq) {
    int p = blockIdx.x;
    int b = p / Tq;
    int src = rep[p];
    int c = threadIdx.x;
    tok_q[(size_t)p*CD + c] = tok_t[(size_t)(b*Tt + src)*CD + c];
    if (c < 3) cent_q[p*3 + c] = cent_t[(size_t)(b*Tt + src)*3 + c];
}

// ---------------- KNN ----------------
__global__ void knn_kernel(const float* __restrict__ cent_q,
                           const float* __restrict__ cent_t,
                           int Tt, int Tq, int k, int* __restrict__ nn) {
    int p = blockIdx.x;
    int b = p / Tq;
    __shared__ float d2s[1024];
    __shared__ float s_bv[8];
    __shared__ int   s_bi[8];
    int tid = threadIdx.x;
    float qx = cent_q[p*3], qy = cent_q[p*3+1], qz = cent_q[p*3+2];
    float qq = qx*qx + qy*qy + qz*qz;
    const float* Pt = cent_t + (size_t)b*Tt*3;
    for (int t = tid; t < Tt; t += 256) {
        float tx = Pt[t*3], ty = Pt[t*3+1], tz = Pt[t*3+2];
        float tt = tx*tx + ty*ty + tz*tz;
        float dt = qx*tx + qy*ty + qz*tz;
        d2s[t] = (qq + tt) - 2.0f*dt;
    }
    __syncthreads();
    for (int sel = 0; sel < k; sel++) {
        float bv = INF_F; int bi = 0x7fffffff;
        for (int t = tid; t < Tt; t += 256) {
            float v = d2s[t];
            if (v < bv || (v == bv && t < bi)) { bv = v; bi = t; }
        }
#pragma unroll
        for (int off = 16; off > 0; off >>= 1) {
            float ov = __shfl_down_sync(0xffffffffu, bv, off);
            int   oi = __shfl_down_sync(0xffffffffu, bi, off);
            if (ov < bv || (ov == bv && oi < bi)) { bv = ov; bi = oi; }
        }
        if ((tid & 31) == 0) { s_bv[tid>>5] = bv; s_bi[tid>>5] = bi; }
        __syncthreads();
        if (tid == 0) {
            bv = s_bv[0]; bi = s_bi[0];
            for (int w = 1; w < 8; w++) {
                if (s_bv[w] < bv || (s_bv[w] == bv && s_bi[w] < bi)) { bv = s_bv[w]; bi = s_bi[w]; }
            }
            nn[p*k + sel] = bi;
            d2s[bi] = INF_F;
        }
        __syncthreads();
    }
}

// ---------------- BN stats ----------------
__global__ void bn_partial(const float* __restrict__ x1, int rows1,
                           const float* __restrict__ x2, int rows2,
                           float* __restrict__ psum, float* __restrict__ psq) {
    int c = threadIdx.x;
    int total = rows1 + rows2;
    float s = 0.f, sq = 0.f;
    for (int r = blockIdx.x; r < total; r += gridDim.x) {
        const float* row = (r < rows1) ? (x1 + (size_t)r*CD) : (x2 + (size_t)(r - rows1)*CD);
        float v = row[c];
        s += v; sq += v*v;
    }
    psum[blockIdx.x*CD + c] = s;
    psq [blockIdx.x*CD + c] = sq;
}

__global__ void bn_finalize(const float* __restrict__ psum, const float* __restrict__ psq,
                            int nb, int rows,
                            const float* __restrict__ gamma, const float* __restrict__ beta,
                            float* __restrict__ stats) {
    int c = threadIdx.x;
    float s = 0.f, sq = 0.f;
    for (int b = 0; b < nb; b++) { s += psum[b*CD + c]; sq += psq[b*CD + c]; }
    float m = s / (float)rows;
    float v = sq / (float)rows - m*m;
    float rstd = rsqrtf(v + 1e-5f);
    float sc = gamma[c] * rstd;
    stats[c]      = sc;
    stats[CD + c] = beta[c] - m * sc;
}

// ---------------- exact-fp32 weight product: C[256,256] = A @ B ----------------
// 128 blocks, 2 rows/block, unroll 16 for MLP
__global__ void wprod_kernel(const float* __restrict__ A, int lda,
                             const float* __restrict__ B, int ldb,
                             float* __restrict__ C) {
    __shared__ float arow[2][CD];
    int r0 = blockIdx.x*2;
    int tid = threadIdx.x;
    arow[0][tid] = A[(size_t)(r0+0)*lda + tid];
    arow[1][tid] = A[(size_t)(r0+1)*lda + tid];
    __syncthreads();
    float acc0 = 0.f, acc1 = 0.f;
#pragma unroll 16
    for (int c = 0; c < CD; c++) {
        float bv = __ldg(&B[(size_t)c*ldb + tid]);
        acc0 += arow[0][c]*bv;
        acc1 += arow[1][c]*bv;
    }
    C[(size_t)(r0+0)*CD + tid] = acc0;
    C[(size_t)(r0+1)*CD + tid] = acc1;
}

// ---------------- TF32 tensor-core GEMM, TBK=32, 2-stage cp.async ----------------
#define TBM 128
#define TBN 128
#define TBK 32
#define AS_STRIDE 36
#define BS_STRIDE 136
#define A_ELEMS (TBM*AS_STRIDE)
#define B_ELEMS (TBK*BS_STRIDE)

__device__ __forceinline__ void mma_tf32(float* c, const uint32_t* a, const uint32_t* b) {
    asm volatile(
        "mma.sync.aligned.m16n8k8.row.col.f32.tf32.tf32.f32 "
        "{%0,%1,%2,%3}, {%4,%5,%6,%7}, {%8,%9}, {%0,%1,%2,%3};\n"
        : "+f"(c[0]), "+f"(c[1]), "+f"(c[2]), "+f"(c[3])
        : "r"(a[0]), "r"(a[1]), "r"(a[2]), "r"(a[3]),
          "r"(b[0]), "r"(b[1]));
}

__device__ __forceinline__ void cp_async16(uint32_t dst, const void* src) {
    asm volatile("cp.async.cg.shared.global [%0], [%1], 16;" :: "r"(dst), "l"(src));
}
__device__ __forceinline__ void cp_commit() {
    asm volatile("cp.async.commit_group;");
}
__device__ __forceinline__ void cp_wait1() {
    asm volatile("cp.async.wait_group 1;");
}

// MODE 0: plain A. MODE 1: A[r] = relu(QH - KH[nn] + b1) (sc_s = b1).
// MODE 2: A = A*sc_s[c] + sh_s[c]  (BN folded).
template<int MODE>
__device__ __forceinline__ void gemm_mainloop(
    float acc[4][4][4],
    const float* __restrict__ A, int lda,
    const float* __restrict__ QH, const float* __restrict__ KH,
    const int* sQoff, const int* sKoff,
    const float* sc_s, const float* sh_s,
    const float* __restrict__ B, int ldb,
    int K, int row0, int col0,
    float* smem, int STAGE,
    int tid, int lane, int wm, int wn)
{
    int ldrow = tid >> 3;
    int ldcol = (tid & 7) * 4;

    auto load_stage = [&](int s, int kt) {
        float* As_  = smem + s*STAGE;
        float* Akv_ = As_ + A_ELEMS;
        float* Bs_  = As_ + (MODE == 1 ? 2*A_ELEMS : A_ELEMS);
#pragma unroll
        for (int i = 0; i < 4; i++) {
            int arow = ldrow + 32*i;
            uint32_t dA = (uint32_t)__cvta_generic_to_shared(&As_[arow*AS_STRIDE + ldcol]);
            if (MODE == 1) {
                cp_async16(dA, QH + sQoff[arow] + kt + ldcol);
                uint32_t dK = (uint32_t)__cvta_generic_to_shared(&Akv_[arow*AS_STRIDE + ldcol]);
                cp_async16(dK, KH + sKoff[arow] + kt + ldcol);
            } else {
                cp_async16(dA, A + (size_t)(row0 + arow)*lda + kt + ldcol);
            }
        }
#pragma unroll
        for (int i = 0; i < 4; i++) {
            int bcol = ldcol + 32*i;
            uint32_t dB = (uint32_t)__cvta_generic_to_shared(&Bs_[ldrow*BS_STRIDE + bcol]);
            cp_async16(dB, B + (size_t)(kt + ldrow)*ldb + col0 + bcol);
        }
    };

    const int NIT = K / TBK;
    load_stage(0, 0);
    cp_commit();

    for (int it = 0; it < NIT; it++) {
        if (it + 1 < NIT) load_stage((it+1)&1, (it+1)*TBK);
        cp_commit();
        cp_wait1();
        __syncthreads();

        int s = it & 1;
        int ktg = it*TBK;
        const float* As_  = smem + s*STAGE;
        const float* Akv_ = As_ + A_ELEMS;
        const float* Bs_  = As_ + (MODE == 1 ? 2*A_ELEMS : A_ELEMS);

#pragma unroll
        for (int kk = 0; kk < 4; kk++) {
            int kc = kk*8;
            float cA = 0.f, cB = 0.f, hA = 0.f, hB = 0.f;
            if (MODE == 1) {
                cA = sc_s[ktg + kc + (lane&3)];
                cB = sc_s[ktg + kc + 4 + (lane&3)];
            } else if (MODE == 2) {
                cA = sc_s[ktg + kc + (lane&3)];
                cB = sc_s[ktg + kc + 4 + (lane&3)];
                hA = sh_s[ktg + kc + (lane&3)];
                hB = sh_s[ktg + kc + 4 + (lane&3)];
            }
            uint32_t a[4][4];
#pragma unroll
            for (int mf = 0; mf < 4; mf++) {
                int r1 = wm*64 + mf*16 + (lane>>2);
                int i0 = r1*AS_STRIDE      + kc + (lane&3);
                int i1 = (r1+8)*AS_STRIDE  + kc + (lane&3);
                if (MODE == 1) {
                    a[mf][0] = __float_as_uint(fmaxf(As_[i0]     - Akv_[i0]     + cA, 0.f));
                    a[mf][1] = __float_as_uint(fmaxf(As_[i1]     - Akv_[i1]     + cA, 0.f));
                    a[mf][2] = __float_as_uint(fmaxf(As_[i0 + 4] - Akv_[i0 + 4] + cB, 0.f));
                    a[mf][3] = __float_as_uint(fmaxf(As_[i1 + 4] - Akv_[i1 + 4] + cB, 0.f));
                } else if (MODE == 2) {
                    a[mf][0] = __float_as_uint(fmaf(As_[i0],     cA, hA));
                    a[mf][1] = __float_as_uint(fmaf(As_[i1],     cA, hA));
                    a[mf][2] = __float_as_uint(fmaf(As_[i0 + 4], cB, hB));
                    a[mf][3] = __float_as_uint(fmaf(As_[i1 + 4], cB, hB));
                } else {
                    a[mf][0] = __float_as_uint(As_[i0]);
                    a[mf][1] = __float_as_uint(As_[i1]);
                    a[mf][2] = __float_as_uint(As_[i0 + 4]);
                    a[mf][3] = __float_as_uint(As_[i1 + 4]);
                }
            }
            uint32_t b[4][2];
#pragma unroll
            for (int nf = 0; nf < 4; nf++) {
                int ncol = wn*32 + nf*8 + (lane>>2);
                b[nf][0] = __float_as_uint(Bs_[(kc     + (lane&3))*BS_STRIDE + ncol]);
                b[nf][1] = __float_as_uint(Bs_[(kc + 4 + (lane&3))*BS_STRIDE + ncol]);
            }
#pragma unroll
            for (int mf = 0; mf < 4; mf++)
#pragma unroll
                for (int nf = 0; nf < 4; nf++)
                    mma_tf32(acc[mf][nf], a[mf], b[nf]);
        }
        __syncthreads();
    }
}

// plain/BN GEMM: C = (A or bn(A))@B (+bias)(+resid)(relu)
template<int BN>
__global__ __launch_bounds__(256)
void tf32gemm(int M, int N, int K, int lda, int ldb,
              const float* __restrict__ A,
              const float* __restrict__ B,
              const float* __restrict__ bnstats,
              const float* __restrict__ bias, const float* __restrict__ resid,
              float* __restrict__ C, int relu) {
    extern __shared__ float smem[];
    const int STAGE = A_ELEMS + B_ELEMS;
    __shared__ float scs[CD], shs[CD];

    int tid  = threadIdx.x;
    int lane = tid & 31;
    int warp = tid >> 5;
    int wm = warp >> 2;
    int wn = warp & 3;
    int row0 = blockIdx.y*TBM;
    int col0 = blockIdx.x*TBN;

    if (BN) {
        scs[tid] = bnstats[tid];
        shs[tid] = bnstats[CD + tid];
        __syncthreads();
    }

    float acc[4][4][4];
#pragma unroll
    for (int i = 0; i < 4; i++)
#pragma unroll
        for (int j = 0; j < 4; j++)
#pragma unroll
            for (int r = 0; r < 4; r++) acc[i][j][r] = 0.f;

    gemm_mainloop<BN ? 2 : 0>(acc, A, lda, nullptr, nullptr, nullptr, nullptr,
                              scs, shs, B, ldb, K, row0, col0,
                              smem, STAGE, tid, lane, wm, wn);

#pragma unroll
    for (int mf = 0; mf < 4; mf++) {
#pragma unroll
        for (int nf = 0; nf < 4; nf++) {
            int r = row0 + wm*64 + mf*16 + (lane>>2);
            int c = col0 + wn*32 + nf*8 + (lane&3)*2;
#pragma unroll
            for (int half = 0; half < 2; half++) {
                int rr = r + half*8;
                float v0 = acc[mf][nf][half*2+0];
                float v1 = acc[mf][nf][half*2+1];
                if (bias)  { v0 += bias[c]; v1 += bias[c+1]; }
                if (resid) {
                    const float2 rv = *(const float2*)(resid + (size_t)rr*N + c);
                    v0 += rv.x; v1 += rv.y;
                }
                if (relu) { v0 = fmaxf(v0, 0.f); v1 = fmaxf(v1, 0.f); }
                float2 out; out.x = v0; out.y = v1;
                *(float2*)(C + (size_t)rr*N + c) = out;
            }
        }
    }
}

// fused attention GEMM
#define SIM_STRIDE 132
__global__ __launch_bounds__(256)
void tf32gemm_attn(int M, int N, int K,
                   const float* __restrict__ QH, const float* __restrict__ KH,
                   const float* __restrict__ b1,
                   const float* __restrict__ B,
                   const float* __restrict__ bias,
                   const float* __restrict__ V,
                   const int* __restrict__ nn, int Tq, int knn_k, int Tt,
                   const float* __restrict__ skipb,
                   float* __restrict__ out) {
    extern __shared__ float smem[];
    const int STAGE = 2*A_ELEMS + B_ELEMS;
    __shared__ int   sQoff[TBM];
    __shared__ int   sKoff[TBM];
    __shared__ float b1s[CD];

    int tid  = threadIdx.x;
    int lane = tid & 31;
    int warp = tid >> 5;
    int wm = warp >> 2;
    int wn = warp & 3;
    int row0 = blockIdx.y*TBM;
    int col0 = blockIdx.x*TBN;

    if (tid < TBM) {
        int r = row0 + tid;
        int p = r / knn_k;
        int b = p / Tq;
        sQoff[tid] = p * CD;
        sKoff[tid] = (b*Tt + nn[r]) * CD;
    }
    b1s[tid] = b1[tid];
    __syncthreads();

    float acc[4][4][4];
#pragma unroll
    for (int i = 0; i < 4; i++)
#pragma unroll
        for (int j = 0; j < 4; j++)
#pragma unroll
            for (int r = 0; r < 4; r++) acc[i][j][r] = 0.f;

    gemm_mainloop<1>(acc, nullptr, 0, QH, KH, sQoff, sKoff, b1s, nullptr,
                     B, CD, K, row0, col0, smem, STAGE, tid, lane, wm, wn);

    float* sim_s = smem;
#pragma unroll
    for (int mf = 0; mf < 4; mf++) {
#pragma unroll
        for (int nf = 0; nf < 4; nf++) {
            int r = wm*64 + mf*16 + (lane>>2);
            int c = wn*32 + nf*8 + (lane&3)*2;
#pragma unroll
            for (int half = 0; half < 2; half++) {
                int rr = r + half*8;
                float v0 = acc[mf][nf][half*2+0] + bias[col0 + c];
                float v1 = acc[mf][nf][half*2+1] + bias[col0 + c + 1];
                sim_s[rr*SIM_STRIDE + c]     = v0;
                sim_s[rr*SIM_STRIDE + c + 1] = v1;
            }
        }
    }
    __syncthreads();

    int ppb = TBM / knn_k;
    int col = tid & 127;
    int cg  = col0 + col;
    for (int pp = tid >> 7; pp < ppb; pp += 2) {
        const float* Sp = sim_s + (pp*knn_k)*SIM_STRIDE + col;
        float m = -INF_F;
        for (int n = 0; n < knn_k; n++) m = fmaxf(m, Sp[n*SIM_STRIDE]);
        float den = 0.f, accv = 0.f;
        for (int n = 0; n < knn_k; n++) {
            float e = expf(Sp[n*SIM_STRIDE] - m);
            den += e;
            accv += e * V[(size_t)sKoff[pp*knn_k + n] + cg];
        }
        int pg = row0/knn_k + pp;
        out[(size_t)pg*CD + cg] = accv/den + skipb[(size_t)pg*CD + cg];
    }
}

// ---------------- final pooling / embedding ----------------
__global__ void pool_kernel(const float* __restrict__ tok, float* __restrict__ g, int Tq) {
    int b = blockIdx.x, c = threadIdx.x;
    float s = 0.f;
    for (int t = 0; t < Tq; t++) s += tok[(size_t)(b*Tq + t)*CD + c];
    g[b*CD + c] = s / (float)Tq;
}

__global__ void emb_kernel(const float* __restrict__ g, const float* __restrict__ W,
                           const float* __restrict__ bias, float* __restrict__ out) {
    int b = blockIdx.x, e = threadIdx.x;
    __shared__ float gs[CD];
    if (e < CD) gs[e] = g[b*CD + e];
    __syncthreads();
    float s = 0.f;
    for (int c = 0; c < CD; c++) s += gs[c] * W[(size_t)c*ED + e];
    out[b*ED + e] = s + bias[e];
}

__global__ void final_bn_kernel(float* __restrict__ x, const float* __restrict__ gamma,
                                const float* __restrict__ beta) {
    int e = threadIdx.x;
    float s = 0.f;
    for (int b = 0; b < BQN; b++) s += x[b*ED + e];
    float m = s / (float)BQN;
    float v = 0.f;
    for (int b = 0; b < BQN; b++) { float d = x[b*ED + e] - m; v += d*d; }
    v /= (float)BQN;
    float rs = rsqrtf(v + 1e-5f);
    for (int b = 0; b < BQN; b++) {
        float val = (x[b*ED + e] - m) * rs * gamma[e] + beta[e];
        x[b*ED + e] = fmaxf(val, 0.f);
    }
}

__global__ void topk_norm_kernel(const float* __restrict__ x, float* __restrict__ out) {
    int b = blockIdx.x, t = threadIdx.x;
    __shared__ float vals[ED], work[ED];
    __shared__ float red[16];
    __shared__ int   redi[16];
    __shared__ float s_thr, s_norm;
    float v = x[b*ED + t];
    vals[t] = v; work[t] = v;
    __syncthreads();
    for (int it = 0; it < 64; it++) {
        float bv = work[t]; int bi = t;
#pragma unroll
        for (int off = 16; off > 0; off >>= 1) {
            float ov = __shfl_down_sync(0xffffffffu, bv, off);
            int   oi = __shfl_down_sync(0xffffffffu, bi, off);
            if (ov > bv) { bv = ov; bi = oi; }
        }
        if ((t & 31) == 0) { red[t>>5] = bv; redi[t>>5] = bi; }
        __syncthreads();
        if (t == 0) {
            bv = red[0]; bi = redi[0];
            for (int w = 1; w < 16; w++) if (red[w] > bv) { bv = red[w]; bi = redi[w]; }
            work[bi] = -INF_F;
            if (it == 63) s_thr = bv;
        }
        __syncthreads();
    }
    float thr = s_thr;
    float kept = (vals[t] >= thr) ? vals[t] : 0.f;
    float sq = kept*kept;
#pragma unroll
    for (int off = 16; off > 0; off >>= 1) sq += __shfl_down_sync(0xffffffffu, sq, off);
    if ((t & 31) == 0) red[t>>5] = sq;
    __syncthreads();
    if (t == 0) {
        float s = 0.f;
        for (int w = 0; w < 16; w++) s += red[w];
        s_norm = fmaxf(sqrtf(s), 1e-12f);
    }
    __syncthreads();
    out[b*ED + t] = kept / s_norm;
}

// ---------------- host orchestration ----------------
extern "C" void kernel_launch(void* const* d_in, const int* in_sizes, int n_in,
                              void* d_out, int out_size) {
    const float* tokens = (const float*)d_in[0];
    const float* centers = (const float*)d_in[1];
    const float* wq     = (const float*)d_in[3];
    const float* wkv    = (const float*)d_in[4];
    const float* mlp_w1 = (const float*)d_in[5];
    const float* mlp_b1 = (const float*)d_in[6];
    const float* mlp_w2 = (const float*)d_in[7];
    const float* mlp_b2 = (const float*)d_in[8];
    const float* bn1_g  = (const float*)d_in[9];
    const float* bn1_b  = (const float*)d_in[10];
    const float* bn2_g  = (const float*)d_in[11];
    const float* bn2_b  = (const float*)d_in[12];
    const float* att_w1 = (const float*)d_in[13];
    const float* att_b1 = (const float*)d_in[14];
    const float* att_w2 = (const float*)d_in[15];
    const float* att_b2 = (const float*)d_in[16];
    const float* emb_w  = (const float*)d_in[17];
    const float* emb_b  = (const float*)d_in[18];
    const float* embn_g = (const float*)d_in[19];
    const float* embn_b = (const float*)d_in[20];

    float *tok_buf, *tok_q, *tq, *QH, *KH, *V, *mlph, *wqh, *wkh;
    float *cent_a, *cent_b, *psum, *psq, *stats, *pool, *embv;
    int *rep, *nn;
    cudaGetSymbolAddress((void**)&tok_buf, g_tokens_t);
    cudaGetSymbolAddress((void**)&tok_q,  g_tokens_q);
    cudaGetSymbolAddress((void**)&tq,     g_tq);
    cudaGetSymbolAddress((void**)&QH,     g_QH);
    cudaGetSymbolAddress((void**)&KH,     g_KH);
    cudaGetSymbolAddress((void**)&V,      g_V);
    cudaGetSymbolAddress((void**)&mlph,   g_mlph);
    cudaGetSymbolAddress((void**)&wqh,    g_wqh);
    cudaGetSymbolAddress((void**)&wkh,    g_wkh);
    cudaGetSymbolAddress((void**)&cent_a, g_centers_a);
    cudaGetSymbolAddress((void**)&cent_b, g_centers_b);
    cudaGetSymbolAddress((void**)&psum,   g_psum);
    cudaGetSymbolAddress((void**)&psq,    g_psq);
    cudaGetSymbolAddress((void**)&stats,  g_stats);
    cudaGetSymbolAddress((void**)&pool,   g_pool);
    cudaGetSymbolAddress((void**)&embv,   g_embv);
    cudaGetSymbolAddress((void**)&rep,    g_rep);
    cudaGetSymbolAddress((void**)&nn,     g_nn);

    const int SMEM_PLAIN = 2*(A_ELEMS + B_ELEMS)*sizeof(float);
    const int SMEM_ATTN  = 2*(2*A_ELEMS + B_ELEMS)*sizeof(float);
    static cudaStream_t s1, s2;
    static cudaEvent_t evFork, evJ1, evJ2;
    static bool init_done = false;
    if (!init_done) {
        cudaFuncSetAttribute(tf32gemm<0>,   cudaFuncAttributeMaxDynamicSharedMemorySize, SMEM_PLAIN);
        cudaFuncSetAttribute(tf32gemm<1>,   cudaFuncAttributeMaxDynamicSharedMemorySize, SMEM_PLAIN);
        cudaFuncSetAttribute(tf32gemm_attn, cudaFuncAttributeMaxDynamicSharedMemorySize, SMEM_ATTN);
        cudaStreamCreateWithFlags(&s1, cudaStreamNonBlocking);
        cudaStreamCreateWithFlags(&s2, cudaStreamNonBlocking);
        cudaEventCreateWithFlags(&evFork, cudaEventDisableTiming);
        cudaEventCreateWithFlags(&evJ1,   cudaEventDisableTiming);
        cudaEventCreateWithFlags(&evJ2,   cudaEventDisableTiming);
        init_done = true;
    }

    // ---- fork: all 6 weight products on side streams (depend only on inputs) ----
    cudaEventRecord(evFork, 0);
    cudaStreamWaitEvent(s1, evFork, 0);
    cudaStreamWaitEvent(s2, evFork, 0);
    for (int i = 0; i < 3; i++) {
        wprod_kernel<<<128, 256, 0, s1>>>(wq  + (size_t)i*CD*CD,   CD,
                                          att_w1 + (size_t)i*CD*CD, CD, wqh + (size_t)i*CD*CD);
        wprod_kernel<<<128, 256, 0, s2>>>(wkv + (size_t)i*CD*2*CD, 2*CD,
                                          att_w1 + (size_t)i*CD*CD, CD, wkh + (size_t)i*CD*CD);
    }
    cudaEventRecord(evJ1, s1);
    cudaEventRecord(evJ2, s2);

    const int Tts[3] = {1024, 512, 256};
    const int Tqs[3] = {512, 256, 128};
    const int ks [3] = {16, 32, 64};

    const float* tok_src  = tokens;
    const float* cent_src = centers;
    float* cent_dsts[3] = {cent_a, cent_b, cent_a};

    for (int i = 0; i < 3; i++) {
        int Tt = Tts[i], Tq = Tqs[i], k = ks[i];
        int Mq = BQN*Tq, Mt = BQN*Tt, Mr = Mq*k;
        float* cent_dst = cent_dsts[i];
        const float* wqh_i = wqh + (size_t)i*CD*CD;
        const float* wkh_i = wkh + (size_t)i*CD*CD;

        fps_kernel   <<<BQN, 256>>>(cent_src, Tt, Tq, rep);
        gather_kernel<<<Mq, 256>>>(tok_src, cent_src, rep, tok_q, cent_dst, Tt, Tq);
        knn_kernel   <<<Mq, 256>>>(cent_dst, cent_src, Tt, Tq, k, nn);

        if (i == 0) {
            // join: weight products must be done before first GEMM reads them
            cudaStreamWaitEvent(0, evJ1, 0);
            cudaStreamWaitEvent(0, evJ2, 0);
        }

        if (i > 0) {
            bn_partial <<<64, 256>>>(tok_q, Mq, tok_src, Mt, psum, psq);
            bn_finalize<<<1, 256>>>(psum, psq, 64, Mq + Mt, bn1_g + i*CD, bn1_b + i*CD, stats);

            tf32gemm<1><<<dim3(CD/TBN, Mq/TBM), 256, SMEM_PLAIN>>>(Mq, CD, CD, CD, CD,
                tok_q, wqh_i, stats, nullptr, nullptr, QH, 0);
            tf32gemm<1><<<dim3(CD/TBN, Mt/TBM), 256, SMEM_PLAIN>>>(Mt, CD, CD, CD, CD,
                tok_src, wkh_i, stats, nullptr, nullptr, KH, 0);
            tf32gemm<1><<<dim3(CD/TBN, Mt/TBM), 256, SMEM_PLAIN>>>(Mt, CD, CD, CD, 2*CD,
                tok_src, wkv + (size_t)i*CD*2*CD + CD, stats, nullptr, nullptr, V, 0);
        } else {
            tf32gemm<0><<<dim3(CD/TBN, Mq/TBM), 256, SMEM_PLAIN>>>(Mq, CD, CD, CD, CD,
                tok_q, wqh_i, nullptr, nullptr, nullptr, QH, 0);
            tf32gemm<0><<<dim3(CD/TBN, Mt/TBM), 256, SMEM_PLAIN>>>(Mt, CD, CD, CD, CD,
                tok_src, wkh_i, nullptr, nullptr, nullptr, KH, 0);
            tf32gemm<0><<<dim3(CD/TBN, Mt/TBM), 256, SMEM_PLAIN>>>(Mt, CD, CD, CD, 2*CD,
                tok_src, wkv + (size_t)i*CD*2*CD + CD, nullptr, nullptr, nullptr, V, 0);
        }

        // fused: sim = relu(QH[p]-KH[nn]+b1) @ att_w2 + b2 -> softmax -> V -> +skip(tok_q)
        tf32gemm_attn<<<dim3(CD/TBN, Mr/TBM), 256, SMEM_ATTN>>>(Mr, CD, CD,
            QH, KH, att_b1 + i*CD,
            att_w2 + (size_t)i*CD*CD, att_b2 + i*CD,
            V, nn, Tq, k, Tt, tok_q, tq);

        bn_partial <<<64, 256>>>(tq, Mq, nullptr, 0, psum, psq);
        bn_finalize<<<1, 256>>>(psum, psq, 64, Mq, bn2_g + i*CD, bn2_b + i*CD, stats);

        tf32gemm<1><<<dim3(2*CD/TBN, Mq/TBM), 256, SMEM_PLAIN>>>(Mq, 2*CD, CD, CD, 2*CD,
            tq, mlp_w1 + (size_t)i*CD*2*CD, stats, mlp_b1 + i*2*CD, nullptr, mlph, 1);
        tf32gemm<0><<<dim3(CD/TBN, Mq/TBM), 256, SMEM_PLAIN>>>(Mq, CD, 2*CD, 2*CD, CD,
            mlph, mlp_w2 + (size_t)i*2*CD*CD, nullptr, mlp_b2 + i*CD, tq, tok_buf, 0);

        tok_src  = tok_buf;
        cent_src = cent_dst;
    }

    pool_kernel     <<<BQN, 256>>>(tok_buf, pool, 128);
    emb_kernel      <<<BQN, 512>>>(pool, emb_w, emb_b, embv);
    final_bn_kernel <<<1, 512>>>(embv, embn_g, embn_b);
    topk_norm_kernel<<<BQN, 512>>>(embv, (float*)d_out);
}

// round 13
// speedup vs baseline: 1.1333x; 1.0032x over previous
#include <cuda_runtime.h>
#include <math.h>
#include <stdint.h>

#define INF_F (__int_as_float(0x7f800000))

// ---------------- problem constants ----------------
#define BQN 16
#define T0 1024
#define CD 256
#define ED 512
#define MAXROWS 131072

// ---------------- static device scratch ----------------
__device__ float g_tokens_t[BQN*T0*CD];
__device__ float g_tokens_q[BQN*512*CD];
__device__ float g_tq      [BQN*512*CD];
__device__ float g_QH      [BQN*512*CD];
__device__ float g_KH      [BQN*T0*CD];
__device__ float g_V       [BQN*T0*CD];
__device__ float g_mlph    [BQN*512*2*CD];
__device__ float g_wqh     [3*CD*CD];
__device__ float g_wkh     [3*CD*CD];
__device__ float g_centers_a[BQN*T0*3];
__device__ float g_centers_b[BQN*512*3];
__device__ int   g_rep[BQN*512];
__device__ int   g_nn [MAXROWS];
__device__ float g_psum[64*CD];
__device__ float g_psq [64*CD];
__device__ float g_stats[2*CD];   // [scale | shift]
__device__ float g_pool[BQN*CD];
__device__ float g_embv[BQN*ED];

// ---------------- FPS ----------------
__global__ void fps_kernel(const float* __restrict__ centers, int Tt, int Tq,
                           int* __restrict__ rep_idx) {
    int b = blockIdx.x;
    const float* P = centers + (size_t)b * Tt * 3;
    __shared__ float sx[1024], sy[1024], sz[1024];
    __shared__ float s_bv[8];
    __shared__ int   s_bi[8];
    __shared__ int   s_cur;
    int tid = threadIdx.x;
    int npt = Tt >> 8;
    float d[4];
#pragma unroll
    for (int j = 0; j < 4; j++) d[j] = INF_F;
    for (int j = tid; j < Tt; j += 256) {
        sx[j] = P[j*3+0]; sy[j] = P[j*3+1]; sz[j] = P[j*3+2];
    }
    if (tid == 0) s_cur = 0;
    __syncthreads();

    for (int step = 0; step < Tq; step++) {
        int cur = s_cur;
        if (tid == 0) rep_idx[b*Tq + step] = cur;
        float cx = sx[cur], cy = sy[cur], cz = sz[cur];
        float bv = -INF_F; int bi = 0x7fffffff;
#pragma unroll
        for (int j = 0; j < 4; j++) {
            if (j < npt) {
                int p = j*256 + tid;
                float dx = sx[p]-cx, dy = sy[p]-cy, dz = sz[p]-cz;
                float dist = dx*dx + dy*dy + dz*dz;
                float dj = fminf(d[j], dist);
                d[j] = dj;
                if (dj > bv || (dj == bv && p < bi)) { bv = dj; bi = p; }
            }
        }
#pragma unroll
        for (int off = 16; off > 0; off >>= 1) {
            float ov = __shfl_down_sync(0xffffffffu, bv, off);
            int   oi = __shfl_down_sync(0xffffffffu, bi, off);
            if (ov > bv || (ov == bv && oi < bi)) { bv = ov; bi = oi; }
        }
        if ((tid & 31) == 0) { s_bv[tid>>5] = bv; s_bi[tid>>5] = bi; }
        __syncthreads();
        if (tid == 0) {
            bv = s_bv[0]; bi = s_bi[0];
            for (int w = 1; w < 8; w++) {
                if (s_bv[w] > bv || (s_bv[w] == bv && s_bi[w] < bi)) { bv = s_bv[w]; bi = s_bi[w]; }
            }
            s_cur = bi;
        }
        __syncthreads();
    }
}

// ---------------- gather query rows ----------------
__global__ void gather_kernel(const float* __restrict__ tok_t,
                              const float* __restrict__ cent_t,
                              const int* __restrict__ rep,
                              float* __restrict__ tok_q,
                              float* __restrict__ cent_q,
                              int Tt, int Tq) {
    int p = blockIdx.x;
    int b = p / Tq;
    int src = rep[p];
    int c = threadIdx.x;
    tok_q[(size_t)p*CD + c] = tok_t[(size_t)(b*Tt + src)*CD + c];
    if (c < 3) cent_q[p*3 + c] = cent_t[(size_t)(b*Tt + src)*3 + c];
}

// ---------------- KNN ----------------
__global__ void knn_kernel(const float* __restrict__ cent_q,
                           const float* __restrict__ cent_t,
                           int Tt, int Tq, int k, int* __restrict__ nn) {
    int p = blockIdx.x;
    int b = p / Tq;
    __shared__ float d2s[1024];
    __shared__ float s_bv[8];
    __shared__ int   s_bi[8];
    int tid = threadIdx.x;
    float qx = cent_q[p*3], qy = cent_q[p*3+1], qz = cent_q[p*3+2];
    float qq = qx*qx + qy*qy + qz*qz;
    const float* Pt = cent_t + (size_t)b*Tt*3;
    for (int t = tid; t < Tt; t += 256) {
        float tx = Pt[t*3], ty = Pt[t*3+1], tz = Pt[t*3+2];
        float tt = tx*tx + ty*ty + tz*tz;
        float dt = qx*tx + qy*ty + qz*tz;
        d2s[t] = (qq + tt) - 2.0f*dt;
    }
    __syncthreads();
    for (int sel = 0; sel < k; sel++) {
        float bv = INF_F; int bi = 0x7fffffff;
        for (int t = tid; t < Tt; t += 256) {
            float v = d2s[t];
            if (v < bv || (v == bv && t < bi)) { bv = v; bi = t; }
        }
#pragma unroll
        for (int off = 16; off > 0; off >>= 1) {
            float ov = __shfl_down_sync(0xffffffffu, bv, off);
            int   oi = __shfl_down_sync(0xffffffffu, bi, off);
            if (ov < bv || (ov == bv && oi < bi)) { bv = ov; bi = oi; }
        }
        if ((tid & 31) == 0) { s_bv[tid>>5] = bv; s_bi[tid>>5] = bi; }
        __syncthreads();
        if (tid == 0) {
            bv = s_bv[0]; bi = s_bi[0];
            for (int w = 1; w < 8; w++) {
                if (s_bv[w] < bv || (s_bv[w] == bv && s_bi[w] < bi)) { bv = s_bv[w]; bi = s_bi[w]; }
            }
            nn[p*k + sel] = bi;
            d2s[bi] = INF_F;
        }
        __syncthreads();
    }
}

// ---------------- BN stats ----------------
__global__ void bn_partial(const float* __restrict__ x1, int rows1,
                           const float* __restrict__ x2, int rows2,
                           float* __restrict__ psum, float* __restrict__ psq) {
    int c = threadIdx.x;
    int total = rows1 + rows2;
    float s = 0.f, sq = 0.f;
    for (int r = blockIdx.x; r < total; r += gridDim.x) {
        const float* row = (r < rows1) ? (x1 + (size_t)r*CD) : (x2 + (size_t)(r - rows1)*CD);
        float v = row[c];
        s += v; sq += v*v;
    }
    psum[blockIdx.x*CD + c] = s;
    psq [blockIdx.x*CD + c] = sq;
}

__global__ void bn_finalize(const float* __restrict__ psum, const float* __restrict__ psq,
                            int nb, int rows,
                            const float* __restrict__ gamma, const float* __restrict__ beta,
                            float* __restrict__ stats) {
    int c = threadIdx.x;
    float s = 0.f, sq = 0.f;
    for (int b = 0; b < nb; b++) { s += psum[b*CD + c]; sq += psq[b*CD + c]; }
    float m = s / (float)rows;
    float v = sq / (float)rows - m*m;
    float rstd = rsqrtf(v + 1e-5f);
    float sc = gamma[c] * rstd;
    stats[c]      = sc;
    stats[CD + c] = beta[c] - m * sc;
}

// ---------------- exact-fp32 weight product ----------------
__global__ void wprod_kernel(const float* __restrict__ A, int lda,
                             const float* __restrict__ B, int ldb,
                             float* __restrict__ C) {
    __shared__ float arow[2][CD];
    int r0 = blockIdx.x*2;
    int tid = threadIdx.x;
    arow[0][tid] = A[(size_t)(r0+0)*lda + tid];
    arow[1][tid] = A[(size_t)(r0+1)*lda + tid];
    __syncthreads();
    float acc0 = 0.f, acc1 = 0.f;
#pragma unroll 16
    for (int c = 0; c < CD; c++) {
        float bv = __ldg(&B[(size_t)c*ldb + tid]);
        acc0 += arow[0][c]*bv;
        acc1 += arow[1][c]*bv;
    }
    C[(size_t)(r0+0)*CD + tid] = acc0;
    C[(size_t)(r0+1)*CD + tid] = acc1;
}

// ---------------- TF32 tensor-core GEMM, TBK=32, 2-stage cp.async, 2 CTA/SM ----------------
#define TBM 128
#define TBN 128
#define TBK 32
#define AS_STRIDE 36
#define BS_STRIDE 136
#define A_ELEMS (TBM*AS_STRIDE)
#define B_ELEMS (TBK*BS_STRIDE)

__device__ __forceinline__ void mma_tf32(float* c, const uint32_t* a, const uint32_t* b) {
    asm volatile(
        "mma.sync.aligned.m16n8k8.row.col.f32.tf32.tf32.f32 "
        "{%0,%1,%2,%3}, {%4,%5,%6,%7}, {%8,%9}, {%0,%1,%2,%3};\n"
        : "+f"(c[0]), "+f"(c[1]), "+f"(c[2]), "+f"(c[3])
        : "r"(a[0]), "r"(a[1]), "r"(a[2]), "r"(a[3]),
          "r"(b[0]), "r"(b[1]));
}

__device__ __forceinline__ void cp_async16(uint32_t dst, const void* src) {
    asm volatile("cp.async.cg.shared.global [%0], [%1], 16;" :: "r"(dst), "l"(src));
}
__device__ __forceinline__ void cp_commit() {
    asm volatile("cp.async.commit_group;");
}
__device__ __forceinline__ void cp_wait1() {
    asm volatile("cp.async.wait_group 1;");
}

// MODE 0: plain A. MODE 1: A[r]=relu(QH-KH[nn]+b1). MODE 2: A*sc+sh (BN folded).
template<int MODE>
__device__ __forceinline__ void gemm_mainloop(
    float acc[4][4][4],
    const float* __restrict__ A, int lda,
    const float* __restrict__ QH, const float* __restrict__ KH,
    const int* sQoff, const int* sKoff,
    const float* sc_s, const float* sh_s,
    const float* __restrict__ B, int ldb,
    int K, int row0, int col0,
    float* smem, int STAGE,
    int tid, int lane, int wm, int wn)
{
    int ldrow = tid >> 3;
    int ldcol = (tid & 7) * 4;

    auto load_stage = [&](int s, int kt) {
        float* As_  = smem + s*STAGE;
        float* Akv_ = As_ + A_ELEMS;
        float* Bs_  = As_ + (MODE == 1 ? 2*A_ELEMS : A_ELEMS);
#pragma unroll
        for (int i = 0; i < 4; i++) {
            int arow = ldrow + 32*i;
            uint32_t dA = (uint32_t)__cvta_generic_to_shared(&As_[arow*AS_STRIDE + ldcol]);
            if (MODE == 1) {
                cp_async16(dA, QH + sQoff[arow] + kt + ldcol);
                uint32_t dK = (uint32_t)__cvta_generic_to_shared(&Akv_[arow*AS_STRIDE + ldcol]);
                cp_async16(dK, KH + sKoff[arow] + kt + ldcol);
            } else {
                cp_async16(dA, A + (size_t)(row0 + arow)*lda + kt + ldcol);
            }
        }
#pragma unroll
        for (int i = 0; i < 4; i++) {
            int bcol = ldcol + 32*i;
            uint32_t dB = (uint32_t)__cvta_generic_to_shared(&Bs_[ldrow*BS_STRIDE + bcol]);
            cp_async16(dB, B + (size_t)(kt + ldrow)*ldb + col0 + bcol);
        }
    };

    const int NIT = K / TBK;
    load_stage(0, 0);
    cp_commit();

    for (int it = 0; it < NIT; it++) {
        if (it + 1 < NIT) load_stage((it+1)&1, (it+1)*TBK);
        cp_commit();
        cp_wait1();
        __syncthreads();

        int s = it & 1;
        int ktg = it*TBK;
        const float* As_  = smem + s*STAGE;
        const float* Akv_ = As_ + A_ELEMS;
        const float* Bs_  = As_ + (MODE == 1 ? 2*A_ELEMS : A_ELEMS);

#pragma unroll
        for (int kk = 0; kk < 4; kk++) {
            int kc = kk*8;
            float cA = 0.f, cB = 0.f, hA = 0.f, hB = 0.f;
            if (MODE == 1) {
                cA = sc_s[ktg + kc + (lane&3)];
                cB = sc_s[ktg + kc + 4 + (lane&3)];
            } else if (MODE == 2) {
                cA = sc_s[ktg + kc + (lane&3)];
                cB = sc_s[ktg + kc + 4 + (lane&3)];
                hA = sh_s[ktg + kc + (lane&3)];
                hB = sh_s[ktg + kc + 4 + (lane&3)];
            }
            uint32_t a[4][4];
#pragma unroll
            for (int mf = 0; mf < 4; mf++) {
                int r1 = wm*64 + mf*16 + (lane>>2);
                int i0 = r1*AS_STRIDE      + kc + (lane&3);
                int i1 = (r1+8)*AS_STRIDE  + kc + (lane&3);
                if (MODE == 1) {
                    a[mf][0] = __float_as_uint(fmaxf(As_[i0]     - Akv_[i0]     + cA, 0.f));
                    a[mf][1] = __float_as_uint(fmaxf(As_[i1]     - Akv_[i1]     + cA, 0.f));
                    a[mf][2] = __float_as_uint(fmaxf(As_[i0 + 4] - Akv_[i0 + 4] + cB, 0.f));
                    a[mf][3] = __float_as_uint(fmaxf(As_[i1 + 4] - Akv_[i1 + 4] + cB, 0.f));
                } else if (MODE == 2) {
                    a[mf][0] = __float_as_uint(fmaf(As_[i0],     cA, hA));
                    a[mf][1] = __float_as_uint(fmaf(As_[i1],     cA, hA));
                    a[mf][2] = __float_as_uint(fmaf(As_[i0 + 4], cB, hB));
                    a[mf][3] = __float_as_uint(fmaf(As_[i1 + 4], cB, hB));
                } else {
                    a[mf][0] = __float_as_uint(As_[i0]);
                    a[mf][1] = __float_as_uint(As_[i1]);
                    a[mf][2] = __float_as_uint(As_[i0 + 4]);
                    a[mf][3] = __float_as_uint(As_[i1 + 4]);
                }
            }
            uint32_t b[4][2];
#pragma unroll
            for (int nf = 0; nf < 4; nf++) {
                int ncol = wn*32 + nf*8 + (lane>>2);
                b[nf][0] = __float_as_uint(Bs_[(kc     + (lane&3))*BS_STRIDE + ncol]);
                b[nf][1] = __float_as_uint(Bs_[(kc + 4 + (lane&3))*BS_STRIDE + ncol]);
            }
#pragma unroll
            for (int mf = 0; mf < 4; mf++)
#pragma unroll
                for (int nf = 0; nf < 4; nf++)
                    mma_tf32(acc[mf][nf], a[mf], b[nf]);
        }
        __syncthreads();
    }
}

template<int BN>
__global__ __launch_bounds__(256, 2)
void tf32gemm(int M, int N, int K, int lda, int ldb,
              const float* __restrict__ A,
              const float* __restrict__ B,
              const float* __restrict__ bnstats,
              const float* __restrict__ bias, const float* __restrict__ resid,
              float* __restrict__ C, int relu) {
    extern __shared__ float smem[];
    const int STAGE = A_ELEMS + B_ELEMS;
    __shared__ float scs[CD], shs[CD];

    int tid  = threadIdx.x;
    int lane = tid & 31;
    int warp = tid >> 5;
    int wm = warp >> 2;
    int wn = warp & 3;
    int row0 = blockIdx.y*TBM;
    int col0 = blockIdx.x*TBN;

    if (BN) {
        scs[tid] = bnstats[tid];
        shs[tid] = bnstats[CD + tid];
        __syncthreads();
    }

    float acc[4][4][4];
#pragma unroll
    for (int i = 0; i < 4; i++)
#pragma unroll
        for (int j = 0; j < 4; j++)
#pragma unroll
            for (int r = 0; r < 4; r++) acc[i][j][r] = 0.f;

    gemm_mainloop<BN ? 2 : 0>(acc, A, lda, nullptr, nullptr, nullptr, nullptr,
                              scs, shs, B, ldb, K, row0, col0,
                              smem, STAGE, tid, lane, wm, wn);

#pragma unroll
    for (int mf = 0; mf < 4; mf++) {
#pragma unroll
        for (int nf = 0; nf < 4; nf++) {
            int r = row0 + wm*64 + mf*16 + (lane>>2);
            int c = col0 + wn*32 + nf*8 + (lane&3)*2;
#pragma unroll
            for (int half = 0; half < 2; half++) {
                int rr = r + half*8;
                float v0 = acc[mf][nf][half*2+0];
                float v1 = acc[mf][nf][half*2+1];
                if (bias)  { v0 += bias[c]; v1 += bias[c+1]; }
                if (resid) {
                    const float2 rv = *(const float2*)(resid + (size_t)rr*N + c);
                    v0 += rv.x; v1 += rv.y;
                }
                if (relu) { v0 = fmaxf(v0, 0.f); v1 = fmaxf(v1, 0.f); }
                float2 out; out.x = v0; out.y = v1;
                *(float2*)(C + (size_t)rr*N + c) = out;
            }
        }
    }
}

// fused attention GEMM (108.5KB smem -> 2 CTA/SM still fits 228KB)
#define SIM_STRIDE 132
__global__ __launch_bounds__(256, 2)
void tf32gemm_attn(int M, int N, int K,
                   const float* __restrict__ QH, const float* __restrict__ KH,
                   const float* __restrict__ b1,
                   const float* __restrict__ B,
                   const float* __restrict__ bias,
                   const float* __restrict__ V,
                   const int* __restrict__ nn, int Tq, int knn_k, int Tt,
                   const float* __restrict__ skipb,
                   float* __restrict__ out) {
    extern __shared__ float smem[];
    const int STAGE = 2*A_ELEMS + B_ELEMS;
    __shared__ int   sQoff[TBM];
    __shared__ int   sKoff[TBM];
    __shared__ float b1s[CD];

    int tid  = threadIdx.x;
    int lane = tid & 31;
    int warp = tid >> 5;
    int wm = warp >> 2;
    int wn = warp & 3;
    int row0 = blockIdx.y*TBM;
    int col0 = blockIdx.x*TBN;

    if (tid < TBM) {
        int r = row0 + tid;
        int p = r / knn_k;
        int b = p / Tq;
        sQoff[tid] = p * CD;
        sKoff[tid] = (b*Tt + nn[r]) * CD;
    }
    b1s[tid] = b1[tid];
    __syncthreads();

    float acc[4][4][4];
#pragma unroll
    for (int i = 0; i < 4; i++)
#pragma unroll
        for (int j = 0; j < 4; j++)
#pragma unroll
            for (int r = 0; r < 4; r++) acc[i][j][r] = 0.f;

    gemm_mainloop<1>(acc, nullptr, 0, QH, KH, sQoff, sKoff, b1s, nullptr,
                     B, CD, K, row0, col0, smem, STAGE, tid, lane, wm, wn);

    float* sim_s = smem;
#pragma unroll
    for (int mf = 0; mf < 4; mf++) {
#pragma unroll
        for (int nf = 0; nf < 4; nf++) {
            int r = wm*64 + mf*16 + (lane>>2);
            int c = wn*32 + nf*8 + (lane&3)*2;
#pragma unroll
            for (int half = 0; half < 2; half++) {
                int rr = r + half*8;
                float v0 = acc[mf][nf][half*2+0] + bias[col0 + c];
                float v1 = acc[mf][nf][half*2+1] + bias[col0 + c + 1];
                sim_s[rr*SIM_STRIDE + c]     = v0;
                sim_s[rr*SIM_STRIDE + c + 1] = v1;
            }
        }
    }
    __syncthreads();

    int ppb = TBM / knn_k;
    int col = tid & 127;
    int cg  = col0 + col;
    for (int pp = tid >> 7; pp < ppb; pp += 2) {
        const float* Sp = sim_s + (pp*knn_k)*SIM_STRIDE + col;
        float m = -INF_F;
        for (int n = 0; n < knn_k; n++) m = fmaxf(m, Sp[n*SIM_STRIDE]);
        float den = 0.f, accv = 0.f;
        for (int n = 0; n < knn_k; n++) {
            float e = expf(Sp[n*SIM_STRIDE] - m);
            den += e;
            accv += e * V[(size_t)sKoff[pp*knn_k + n] + cg];
        }
        int pg = row0/knn_k + pp;
        out[(size_t)pg*CD + cg] = accv/den + skipb[(size_t)pg*CD + cg];
    }
}

// ---------------- final pooling / embedding ----------------
__global__ void pool_kernel(const float* __restrict__ tok, float* __restrict__ g, int Tq) {
    int b = blockIdx.x, c = threadIdx.x;
    float s = 0.f;
    for (int t = 0; t < Tq; t++) s += tok[(size_t)(b*Tq + t)*CD + c];
    g[b*CD + c] = s / (float)Tq;
}

__global__ void emb_kernel(const float* __restrict__ g, const float* __restrict__ W,
                           const float* __restrict__ bias, float* __restrict__ out) {
    int b = blockIdx.x, e = threadIdx.x;
    __shared__ float gs[CD];
    if (e < CD) gs[e] = g[b*CD + e];
    __syncthreads();
    float s = 0.f;
    for (int c = 0; c < CD; c++) s += gs[c] * W[(size_t)c*ED + e];
    out[b*ED + e] = s + bias[e];
}

__global__ void final_bn_kernel(float* __restrict__ x, const float* __restrict__ gamma,
                                const float* __restrict__ beta) {
    int e = threadIdx.x;
    float s = 0.f;
    for (int b = 0; b < BQN; b++) s += x[b*ED + e];
    float m = s / (float)BQN;
    float v = 0.f;
    for (int b = 0; b < BQN; b++) { float d = x[b*ED + e] - m; v += d*d; }
    v /= (float)BQN;
    float rs = rsqrtf(v + 1e-5f);
    for (int b = 0; b < BQN; b++) {
        float val = (x[b*ED + e] - m) * rs * gamma[e] + beta[e];
        x[b*ED + e] = fmaxf(val, 0.f);
    }
}

__global__ void topk_norm_kernel(const float* __restrict__ x, float* __restrict__ out) {
    int b = blockIdx.x, t = threadIdx.x;
    __shared__ float vals[ED], work[ED];
    __shared__ float red[16];
    __shared__ int   redi[16];
    __shared__ float s_thr, s_norm;
    float v = x[b*ED + t];
    vals[t] = v; work[t] = v;
    __syncthreads();
    for (int it = 0; it < 64; it++) {
        float bv = work[t]; int bi = t;
#pragma unroll
        for (int off = 16; off > 0; off >>= 1) {
            float ov = __shfl_down_sync(0xffffffffu, bv, off);
            int   oi = __shfl_down_sync(0xffffffffu, bi, off);
            if (ov > bv) { bv = ov; bi = oi; }
        }
        if ((t & 31) == 0) { red[t>>5] = bv; redi[t>>5] = bi; }
        __syncthreads();
        if (t == 0) {
            bv = red[0]; bi = redi[0];
            for (int w = 1; w < 16; w++) if (red[w] > bv) { bv = red[w]; bi = redi[w]; }
            work[bi] = -INF_F;
            if (it == 63) s_thr = bv;
        }
        __syncthreads();
    }
    float thr = s_thr;
    float kept = (vals[t] >= thr) ? vals[t] : 0.f;
    float sq = kept*kept;
#pragma unroll
    for (int off = 16; off > 0; off >>= 1) sq += __shfl_down_sync(0xffffffffu, sq, off);
    if ((t & 31) == 0) red[t>>5] = sq;
    __syncthreads();
    if (t == 0) {
        float s = 0.f;
        for (int w = 0; w < 16; w++) s += red[w];
        s_norm = fmaxf(sqrtf(s), 1e-12f);
    }
    __syncthreads();
    out[b*ED + t] = kept / s_norm;
}

// ---------------- host orchestration ----------------
extern "C" void kernel_launch(void* const* d_in, const int* in_sizes, int n_in,
                              void* d_out, int out_size) {
    const float* tokens = (const float*)d_in[0];
    const float* centers = (const float*)d_in[1];
    const float* wq     = (const float*)d_in[3];
    const float* wkv    = (const float*)d_in[4];
    const float* mlp_w1 = (const float*)d_in[5];
    const float* mlp_b1 = (const float*)d_in[6];
    const float* mlp_w2 = (const float*)d_in[7];
    const float* mlp_b2 = (const float*)d_in[8];
    const float* bn1_g  = (const float*)d_in[9];
    const float* bn1_b  = (const float*)d_in[10];
    const float* bn2_g  = (const float*)d_in[11];
    const float* bn2_b  = (const float*)d_in[12];
    const float* att_w1 = (const float*)d_in[13];
    const float* att_b1 = (const float*)d_in[14];
    const float* att_w2 = (const float*)d_in[15];
    const float* att_b2 = (const float*)d_in[16];
    const float* emb_w  = (const float*)d_in[17];
    const float* emb_b  = (const float*)d_in[18];
    const float* embn_g = (const float*)d_in[19];
    const float* embn_b = (const float*)d_in[20];

    float *tok_buf, *tok_q, *tq, *QH, *KH, *V, *mlph, *wqh, *wkh;
    float *cent_a, *cent_b, *psum, *psq, *stats, *pool, *embv;
    int *rep, *nn;
    cudaGetSymbolAddress((void**)&tok_buf, g_tokens_t);
    cudaGetSymbolAddress((void**)&tok_q,  g_tokens_q);
    cudaGetSymbolAddress((void**)&tq,     g_tq);
    cudaGetSymbolAddress((void**)&QH,     g_QH);
    cudaGetSymbolAddress((void**)&KH,     g_KH);
    cudaGetSymbolAddress((void**)&V,      g_V);
    cudaGetSymbolAddress((void**)&mlph,   g_mlph);
    cudaGetSymbolAddress((void**)&wqh,    g_wqh);
    cudaGetSymbolAddress((void**)&wkh,    g_wkh);
    cudaGetSymbolAddress((void**)&cent_a, g_centers_a);
    cudaGetSymbolAddress((void**)&cent_b, g_centers_b);
    cudaGetSymbolAddress((void**)&psum,   g_psum);
    cudaGetSymbolAddress((void**)&psq,    g_psq);
    cudaGetSymbolAddress((void**)&stats,  g_stats);
    cudaGetSymbolAddress((void**)&pool,   g_pool);
    cudaGetSymbolAddress((void**)&embv,   g_embv);
    cudaGetSymbolAddress((void**)&rep,    g_rep);
    cudaGetSymbolAddress((void**)&nn,     g_nn);

    const int SMEM_PLAIN = 2*(A_ELEMS + B_ELEMS)*sizeof(float);
    const int SMEM_ATTN  = 2*(2*A_ELEMS + B_ELEMS)*sizeof(float);
    static cudaStream_t s1, s2;
    static cudaEvent_t evFork, evJ1, evJ2;
    static bool init_done = false;
    if (!init_done) {
        cudaFuncSetAttribute(tf32gemm<0>,   cudaFuncAttributeMaxDynamicSharedMemorySize, SMEM_PLAIN);
        cudaFuncSetAttribute(tf32gemm<1>,   cudaFuncAttributeMaxDynamicSharedMemorySize, SMEM_PLAIN);
        cudaFuncSetAttribute(tf32gemm_attn, cudaFuncAttributeMaxDynamicSharedMemorySize, SMEM_ATTN);
        cudaStreamCreateWithFlags(&s1, cudaStreamNonBlocking);
        cudaStreamCreateWithFlags(&s2, cudaStreamNonBlocking);
        cudaEventCreateWithFlags(&evFork, cudaEventDisableTiming);
        cudaEventCreateWithFlags(&evJ1,   cudaEventDisableTiming);
        cudaEventCreateWithFlags(&evJ2,   cudaEventDisableTiming);
        init_done = true;
    }

    // ---- fork: all 6 weight products on side streams (depend only on inputs) ----
    cudaEventRecord(evFork, 0);
    cudaStreamWaitEvent(s1, evFork, 0);
    cudaStreamWaitEvent(s2, evFork, 0);
    for (int i = 0; i < 3; i++) {
        wprod_kernel<<<128, 256, 0, s1>>>(wq  + (size_t)i*CD*CD,   CD,
                                          att_w1 + (size_t)i*CD*CD, CD, wqh + (size_t)i*CD*CD);
        wprod_kernel<<<128, 256, 0, s2>>>(wkv + (size_t)i*CD*2*CD, 2*CD,
                                          att_w1 + (size_t)i*CD*CD, CD, wkh + (size_t)i*CD*CD);
    }
    cudaEventRecord(evJ1, s1);
    cudaEventRecord(evJ2, s2);

    const int Tts[3] = {1024, 512, 256};
    const int Tqs[3] = {512, 256, 128};
    const int ks [3] = {16, 32, 64};

    const float* tok_src  = tokens;
    const float* cent_src = centers;
    float* cent_dsts[3] = {cent_a, cent_b, cent_a};

    for (int i = 0; i < 3; i++) {
        int Tt = Tts[i], Tq = Tqs[i], k = ks[i];
        int Mq = BQN*Tq, Mt = BQN*Tt, Mr = Mq*k;
        float* cent_dst = cent_dsts[i];
        const float* wqh_i = wqh + (size_t)i*CD*CD;
        const float* wkh_i = wkh + (size_t)i*CD*CD;

        fps_kernel   <<<BQN, 256>>>(cent_src, Tt, Tq, rep);
        gather_kernel<<<Mq, 256>>>(tok_src, cent_src, rep, tok_q, cent_dst, Tt, Tq);
        knn_kernel   <<<Mq, 256>>>(cent_dst, cent_src, Tt, Tq, k, nn);

        if (i == 0) {
            cudaStreamWaitEvent(0, evJ1, 0);
            cudaStreamWaitEvent(0, evJ2, 0);
        }

        if (i > 0) {
            bn_partial <<<64, 256>>>(tok_q, Mq, tok_src, Mt, psum, psq);
            bn_finalize<<<1, 256>>>(psum, psq, 64, Mq + Mt, bn1_g + i*CD, bn1_b + i*CD, stats);

            tf32gemm<1><<<dim3(CD/TBN, Mq/TBM), 256, SMEM_PLAIN>>>(Mq, CD, CD, CD, CD,
                tok_q, wqh_i, stats, nullptr, nullptr, QH, 0);
            tf32gemm<1><<<dim3(CD/TBN, Mt/TBM), 256, SMEM_PLAIN>>>(Mt, CD, CD, CD, CD,
                tok_src, wkh_i, stats, nullptr, nullptr, KH, 0);
            tf32gemm<1><<<dim3(CD/TBN, Mt/TBM), 256, SMEM_PLAIN>>>(Mt, CD, CD, CD, 2*CD,
                tok_src, wkv + (size_t)i*CD*2*CD + CD, stats, nullptr, nullptr, V, 0);
        } else {
            tf32gemm<0><<<dim3(CD/TBN, Mq/TBM), 256, SMEM_PLAIN>>>(Mq, CD, CD, CD, CD,
                tok_q, wqh_i, nullptr, nullptr, nullptr, QH, 0);
            tf32gemm<0><<<dim3(CD/TBN, Mt/TBM), 256, SMEM_PLAIN>>>(Mt, CD, CD, CD, CD,
                tok_src, wkh_i, nullptr, nullptr, nullptr, KH, 0);
            tf32gemm<0><<<dim3(CD/TBN, Mt/TBM), 256, SMEM_PLAIN>>>(Mt, CD, CD, CD, 2*CD,
                tok_src, wkv + (size_t)i*CD*2*CD + CD, nullptr, nullptr, nullptr, V, 0);
        }

        // fused: sim = relu(QH[p]-KH[nn]+b1) @ att_w2 + b2 -> softmax -> V -> +skip(tok_q)
        tf32gemm_attn<<<dim3(CD/TBN, Mr/TBM), 256, SMEM_ATTN>>>(Mr, CD, CD,
            QH, KH, att_b1 + i*CD,
            att_w2 + (size_t)i*CD*CD, att_b2 + i*CD,
            V, nn, Tq, k, Tt, tok_q, tq);

        bn_partial <<<64, 256>>>(tq, Mq, nullptr, 0, psum, psq);
        bn_finalize<<<1, 256>>>(psum, psq, 64, Mq, bn2_g + i*CD, bn2_b + i*CD, stats);

        tf32gemm<1><<<dim3(2*CD/TBN, Mq/TBM), 256, SMEM_PLAIN>>>(Mq, 2*CD, CD, CD, 2*CD,
            tq, mlp_w1 + (size_t)i*CD*2*CD, stats, mlp_b1 + i*2*CD, nullptr, mlph, 1);
        tf32gemm<0><<<dim3(CD/TBN, Mq/TBM), 256, SMEM_PLAIN>>>(Mq, CD, 2*CD, 2*CD, CD,
            mlph, mlp_w2 + (size_t)i*2*CD*CD, nullptr, mlp_b2 + i*CD, tq, tok_buf, 0);

        tok_src  = tok_buf;
        cent_src = cent_dst;
    }

    pool_kernel     <<<BQN, 256>>>(tok_buf, pool, 128);
    emb_kernel      <<<BQN, 512>>>(pool, emb_w, emb_b, embv);
    final_bn_kernel <<<1, 512>>>(embv, embn_g, embn_b);
    topk_norm_kernel<<<BQN, 512>>>(embv, (float*)d_out);
}

// round 14
// speedup vs baseline: 1.1739x; 1.0358x over previous
#include <cuda_runtime.h>
#include <math.h>
#include <stdint.h>

#define INF_F (__int_as_float(0x7f800000))

// ---------------- problem constants ----------------
#define BQN 16
#define T0 1024
#define CD 256
#define ED 512
#define MAXROWS 131072
#define BN_BLOCKS 256

// ---------------- static device scratch ----------------
__device__ float g_tokens_t[BQN*T0*CD];
__device__ float g_tokens_q[BQN*512*CD];
__device__ float g_tq      [BQN*512*CD];
__device__ float g_QH      [BQN*512*CD];
__device__ float g_KH      [BQN*T0*CD];
__device__ float g_V       [BQN*T0*CD];
__device__ float g_mlph    [BQN*512*2*CD];
__device__ float g_wqh     [3*CD*CD];
__device__ float g_wkh     [3*CD*CD];
__device__ float g_centers_a[BQN*T0*3];
__device__ float g_centers_b[BQN*512*3];
__device__ int   g_rep[BQN*512];
__device__ int   g_nn [MAXROWS];
__device__ float g_psum[BN_BLOCKS*CD];
__device__ float g_psq [BN_BLOCKS*CD];
__device__ float g_stats[2*CD];   // [scale | shift]
__device__ float g_pool[BQN*CD];
__device__ float g_embv[BQN*ED];

// ---------------- FPS ----------------
__global__ void fps_kernel(const float* __restrict__ centers, int Tt, int Tq,
                           int* __restrict__ rep_idx) {
    int b = blockIdx.x;
    const float* P = centers + (size_t)b * Tt * 3;
    __shared__ float sx[1024], sy[1024], sz[1024];
    __shared__ float s_bv[8];
    __shared__ int   s_bi[8];
    __shared__ int   s_cur;
    int tid = threadIdx.x;
    int npt = Tt >> 8;
    float d[4];
#pragma unroll
    for (int j = 0; j < 4; j++) d[j] = INF_F;
    for (int j = tid; j < Tt; j += 256) {
        sx[j] = P[j*3+0]; sy[j] = P[j*3+1]; sz[j] = P[j*3+2];
    }
    if (tid == 0) s_cur = 0;
    __syncthreads();

    for (int step = 0; step < Tq; step++) {
        int cur = s_cur;
        if (tid == 0) rep_idx[b*Tq + step] = cur;
        float cx = sx[cur], cy = sy[cur], cz = sz[cur];
        float bv = -INF_F; int bi = 0x7fffffff;
#pragma unroll
        for (int j = 0; j < 4; j++) {
            if (j < npt) {
                int p = j*256 + tid;
                float dx = sx[p]-cx, dy = sy[p]-cy, dz = sz[p]-cz;
                float dist = dx*dx + dy*dy + dz*dz;
                float dj = fminf(d[j], dist);
                d[j] = dj;
                if (dj > bv || (dj == bv && p < bi)) { bv = dj; bi = p; }
            }
        }
#pragma unroll
        for (int off = 16; off > 0; off >>= 1) {
            float ov = __shfl_down_sync(0xffffffffu, bv, off);
            int   oi = __shfl_down_sync(0xffffffffu, bi, off);
            if (ov > bv || (ov == bv && oi < bi)) { bv = ov; bi = oi; }
        }
        if ((tid & 31) == 0) { s_bv[tid>>5] = bv; s_bi[tid>>5] = bi; }
        __syncthreads();
        if (tid == 0) {
            bv = s_bv[0]; bi = s_bi[0];
            for (int w = 1; w < 8; w++) {
                if (s_bv[w] > bv || (s_bv[w] == bv && s_bi[w] < bi)) { bv = s_bv[w]; bi = s_bi[w]; }
            }
            s_cur = bi;
        }
        __syncthreads();
    }
}

// ---------------- gather query rows ----------------
__global__ void gather_kernel(const float* __restrict__ tok_t,
                              const float* __restrict__ cent_t,
                              const int* __restrict__ rep,
                              float* __restrict__ tok_q,
                              float* __restrict__ cent_q,
                              int Tt, int Tq) {
    int p = blockIdx.x;
    int b = p / Tq;
    int src = rep[p];
    int c = threadIdx.x;
    tok_q[(size_t)p*CD + c] = tok_t[(size_t)(b*Tt + src)*CD + c];
    if (c < 3) cent_q[p*3 + c] = cent_t[(size_t)(b*Tt + src)*3 + c];
}

// ---------------- KNN ----------------
__global__ void knn_kernel(const float* __restrict__ cent_q,
                           const float* __restrict__ cent_t,
                           int Tt, int Tq, int k, int* __restrict__ nn) {
    int p = blockIdx.x;
    int b = p / Tq;
    __shared__ float d2s[1024];
    __shared__ float s_bv[8];
    __shared__ int   s_bi[8];
    int tid = threadIdx.x;
    float qx = cent_q[p*3], qy = cent_q[p*3+1], qz = cent_q[p*3+2];
    float qq = qx*qx + qy*qy + qz*qz;
    const float* Pt = cent_t + (size_t)b*Tt*3;
    for (int t = tid; t < Tt; t += 256) {
        float tx = Pt[t*3], ty = Pt[t*3+1], tz = Pt[t*3+2];
        float tt = tx*tx + ty*ty + tz*tz;
        float dt = qx*tx + qy*ty + qz*tz;
        d2s[t] = (qq + tt) - 2.0f*dt;
    }
    __syncthreads();
    for (int sel = 0; sel < k; sel++) {
        float bv = INF_F; int bi = 0x7fffffff;
        for (int t = tid; t < Tt; t += 256) {
            float v = d2s[t];
            if (v < bv || (v == bv && t < bi)) { bv = v; bi = t; }
        }
#pragma unroll
        for (int off = 16; off > 0; off >>= 1) {
            float ov = __shfl_down_sync(0xffffffffu, bv, off);
            int   oi = __shfl_down_sync(0xffffffffu, bi, off);
            if (ov < bv || (ov == bv && oi < bi)) { bv = ov; bi = oi; }
        }
        if ((tid & 31) == 0) { s_bv[tid>>5] = bv; s_bi[tid>>5] = bi; }
        __syncthreads();
        if (tid == 0) {
            bv = s_bv[0]; bi = s_bi[0];
            for (int w = 1; w < 8; w++) {
                if (s_bv[w] < bv || (s_bv[w] == bv && s_bi[w] < bi)) { bv = s_bv[w]; bi = s_bi[w]; }
            }
            nn[p*k + sel] = bi;
            d2s[bi] = INF_F;
        }
        __syncthreads();
    }
}

// ---------------- BN stats: 256 blocks, float4 channels, 4 row-subsets ----------------
__global__ void bn_partial(const float* __restrict__ x1, int rows1,
                           const float* __restrict__ x2, int rows2,
                           float* __restrict__ psum, float* __restrict__ psq) {
    __shared__ float ssum[4][CD];
    __shared__ float ssq [4][CD];
    int tid  = threadIdx.x;
    int cg   = (tid & 63) * 4;     // channel group (float4)
    int rsub = tid >> 6;           // 0..3 row subset
    int total = rows1 + rows2;
    float4 s  = make_float4(0.f, 0.f, 0.f, 0.f);
    float4 sq = make_float4(0.f, 0.f, 0.f, 0.f);
    for (int r = blockIdx.x*4 + rsub; r < total; r += gridDim.x*4) {
        const float* row = (r < rows1) ? (x1 + (size_t)r*CD) : (x2 + (size_t)(r - rows1)*CD);
        float4 v = *(const float4*)(row + cg);
        s.x += v.x; s.y += v.y; s.z += v.z; s.w += v.w;
        sq.x += v.x*v.x; sq.y += v.y*v.y; sq.z += v.z*v.z; sq.w += v.w*v.w;
    }
    *(float4*)(&ssum[rsub][cg]) = s;
    *(float4*)(&ssq [rsub][cg]) = sq;
    __syncthreads();
    if (rsub == 0) {
#pragma unroll
        for (int j = 0; j < 4; j++) {
            int c = cg + j;
            float a = ssum[0][c] + ssum[1][c] + ssum[2][c] + ssum[3][c];
            float b = ssq [0][c] + ssq [1][c] + ssq [2][c] + ssq [3][c];
            psum[blockIdx.x*CD + c] = a;
            psq [blockIdx.x*CD + c] = b;
        }
    }
}

__global__ void bn_finalize(const float* __restrict__ psum, const float* __restrict__ psq,
                            int nb, int rows,
                            const float* __restrict__ gamma, const float* __restrict__ beta,
                            float* __restrict__ stats) {
    int c = threadIdx.x;
    float s = 0.f, sq = 0.f;
#pragma unroll 8
    for (int b = 0; b < nb; b++) { s += psum[b*CD + c]; sq += psq[b*CD + c]; }
    float m = s / (float)rows;
    float v = sq / (float)rows - m*m;
    float rstd = rsqrtf(v + 1e-5f);
    float sc = gamma[c] * rstd;
    stats[c]      = sc;
    stats[CD + c] = beta[c] - m * sc;
}

// ---------------- exact-fp32 weight product ----------------
__global__ void wprod_kernel(const float* __restrict__ A, int lda,
                             const float* __restrict__ B, int ldb,
                             float* __restrict__ C) {
    __shared__ float arow[2][CD];
    int r0 = blockIdx.x*2;
    int tid = threadIdx.x;
    arow[0][tid] = A[(size_t)(r0+0)*lda + tid];
    arow[1][tid] = A[(size_t)(r0+1)*lda + tid];
    __syncthreads();
    float acc0 = 0.f, acc1 = 0.f;
#pragma unroll 16
    for (int c = 0; c < CD; c++) {
        float bv = __ldg(&B[(size_t)c*ldb + tid]);
        acc0 += arow[0][c]*bv;
        acc1 += arow[1][c]*bv;
    }
    C[(size_t)(r0+0)*CD + tid] = acc0;
    C[(size_t)(r0+1)*CD + tid] = acc1;
}

// ---------------- TF32 tensor-core GEMM, TBK=32, 2-stage cp.async ----------------
#define TBM 128
#define TBN 128
#define TBK 32
#define AS_STRIDE 36
#define BS_STRIDE 136
#define A_ELEMS (TBM*AS_STRIDE)
#define B_ELEMS (TBK*BS_STRIDE)

__device__ __forceinline__ void mma_tf32(float* c, const uint32_t* a, const uint32_t* b) {
    asm volatile(
        "mma.sync.aligned.m16n8k8.row.col.f32.tf32.tf32.f32 "
        "{%0,%1,%2,%3}, {%4,%5,%6,%7}, {%8,%9}, {%0,%1,%2,%3};\n"
        : "+f"(c[0]), "+f"(c[1]), "+f"(c[2]), "+f"(c[3])
        : "r"(a[0]), "r"(a[1]), "r"(a[2]), "r"(a[3]),
          "r"(b[0]), "r"(b[1]));
}

__device__ __forceinline__ void cp_async16(uint32_t dst, const void* src) {
    asm volatile("cp.async.cg.shared.global [%0], [%1], 16;" :: "r"(dst), "l"(src));
}
__device__ __forceinline__ void cp_commit() {
    asm volatile("cp.async.commit_group;");
}
__device__ __forceinline__ void cp_wait1() {
    asm volatile("cp.async.wait_group 1;");
}

// MODE 0: plain A. MODE 1: A[r]=relu(QH-KH[nn]+b1). MODE 2: A*sc+sh (BN folded).
template<int MODE>
__device__ __forceinline__ void gemm_mainloop(
    float acc[4][4][4],
    const float* __restrict__ A, int lda,
    const float* __restrict__ QH, const float* __restrict__ KH,
    const int* sQoff, const int* sKoff,
    const float* sc_s, const float* sh_s,
    const float* __restrict__ B, int ldb,
    int K, int row0, int col0,
    float* smem, int STAGE,
    int tid, int lane, int wm, int wn)
{
    int ldrow = tid >> 3;
    int ldcol = (tid & 7) * 4;

    auto load_stage = [&](int s, int kt) {
        float* As_  = smem + s*STAGE;
        float* Akv_ = As_ + A_ELEMS;
        float* Bs_  = As_ + (MODE == 1 ? 2*A_ELEMS : A_ELEMS);
#pragma unroll
        for (int i = 0; i < 4; i++) {
            int arow = ldrow + 32*i;
            uint32_t dA = (uint32_t)__cvta_generic_to_shared(&As_[arow*AS_STRIDE + ldcol]);
            if (MODE == 1) {
                cp_async16(dA, QH + sQoff[arow] + kt + ldcol);
                uint32_t dK = (uint32_t)__cvta_generic_to_shared(&Akv_[arow*AS_STRIDE + ldcol]);
                cp_async16(dK, KH + sKoff[arow] + kt + ldcol);
            } else {
                cp_async16(dA, A + (size_t)(row0 + arow)*lda + kt + ldcol);
            }
        }
#pragma unroll
        for (int i = 0; i < 4; i++) {
            int bcol = ldcol + 32*i;
            uint32_t dB = (uint32_t)__cvta_generic_to_shared(&Bs_[ldrow*BS_STRIDE + bcol]);
            cp_async16(dB, B + (size_t)(kt + ldrow)*ldb + col0 + bcol);
        }
    };

    const int NIT = K / TBK;
    load_stage(0, 0);
    cp_commit();

    for (int it = 0; it < NIT; it++) {
        if (it + 1 < NIT) load_stage((it+1)&1, (it+1)*TBK);
        cp_commit();
        cp_wait1();
        __syncthreads();

        int s = it & 1;
        int ktg = it*TBK;
        const float* As_  = smem + s*STAGE;
        const float* Akv_ = As_ + A_ELEMS;
        const float* Bs_  = As_ + (MODE == 1 ? 2*A_ELEMS : A_ELEMS);

#pragma unroll
        for (int kk = 0; kk < 4; kk++) {
            int kc = kk*8;
            float cA = 0.f, cB = 0.f, hA = 0.f, hB = 0.f;
            if (MODE == 1) {
                cA = sc_s[ktg + kc + (lane&3)];
                cB = sc_s[ktg + kc + 4 + (lane&3)];
            } else if (MODE == 2) {
                cA = sc_s[ktg + kc + (lane&3)];
                cB = sc_s[ktg + kc + 4 + (lane&3)];
                hA = sh_s[ktg + kc + (lane&3)];
                hB = sh_s[ktg + kc + 4 + (lane&3)];
            }
            uint32_t a[4][4];
#pragma unroll
            for (int mf = 0; mf < 4; mf++) {
                int r1 = wm*64 + mf*16 + (lane>>2);
                int i0 = r1*AS_STRIDE      + kc + (lane&3);
                int i1 = (r1+8)*AS_STRIDE  + kc + (lane&3);
                if (MODE == 1) {
                    a[mf][0] = __float_as_uint(fmaxf(As_[i0]     - Akv_[i0]     + cA, 0.f));
                    a[mf][1] = __float_as_uint(fmaxf(As_[i1]     - Akv_[i1]     + cA, 0.f));
                    a[mf][2] = __float_as_uint(fmaxf(As_[i0 + 4] - Akv_[i0 + 4] + cB, 0.f));
                    a[mf][3] = __float_as_uint(fmaxf(As_[i1 + 4] - Akv_[i1 + 4] + cB, 0.f));
                } else if (MODE == 2) {
                    a[mf][0] = __float_as_uint(fmaf(As_[i0],     cA, hA));
                    a[mf][1] = __float_as_uint(fmaf(As_[i1],     cA, hA));
                    a[mf][2] = __float_as_uint(fmaf(As_[i0 + 4], cB, hB));
                    a[mf][3] = __float_as_uint(fmaf(As_[i1 + 4], cB, hB));
                } else {
                    a[mf][0] = __float_as_uint(As_[i0]);
                    a[mf][1] = __float_as_uint(As_[i1]);
                    a[mf][2] = __float_as_uint(As_[i0 + 4]);
                    a[mf][3] = __float_as_uint(As_[i1 + 4]);
                }
            }
            uint32_t b[4][2];
#pragma unroll
            for (int nf = 0; nf < 4; nf++) {
                int ncol = wn*32 + nf*8 + (lane>>2);
                b[nf][0] = __float_as_uint(Bs_[(kc     + (lane&3))*BS_STRIDE + ncol]);
                b[nf][1] = __float_as_uint(Bs_[(kc + 4 + (lane&3))*BS_STRIDE + ncol]);
            }
#pragma unroll
            for (int mf = 0; mf < 4; mf++)
#pragma unroll
                for (int nf = 0; nf < 4; nf++)
                    mma_tf32(acc[mf][nf], a[mf], b[nf]);
        }
        __syncthreads();
    }
}

template<int BN>
__global__ __launch_bounds__(256, 2)
void tf32gemm(int M, int N, int K, int lda, int ldb,
              const float* __restrict__ A,
              const float* __restrict__ B,
              const float* __restrict__ bnstats,
              const float* __restrict__ bias, const float* __restrict__ resid,
              float* __restrict__ C, int relu) {
    extern __shared__ float smem[];
    const int STAGE = A_ELEMS + B_ELEMS;
    __shared__ float scs[CD], shs[CD];

    int tid  = threadIdx.x;
    int lane = tid & 31;
    int warp = tid >> 5;
    int wm = warp >> 2;
    int wn = warp & 3;
    int row0 = blockIdx.y*TBM;
    int col0 = blockIdx.x*TBN;

    if (BN) {
        scs[tid] = bnstats[tid];
        shs[tid] = bnstats[CD + tid];
        __syncthreads();
    }

    float acc[4][4][4];
#pragma unroll
    for (int i = 0; i < 4; i++)
#pragma unroll
        for (int j = 0; j < 4; j++)
#pragma unroll
            for (int r = 0; r < 4; r++) acc[i][j][r] = 0.f;

    gemm_mainloop<BN ? 2 : 0>(acc, A, lda, nullptr, nullptr, nullptr, nullptr,
                              scs, shs, B, ldb, K, row0, col0,
                              smem, STAGE, tid, lane, wm, wn);

#pragma unroll
    for (int mf = 0; mf < 4; mf++) {
#pragma unroll
        for (int nf = 0; nf < 4; nf++) {
            int r = row0 + wm*64 + mf*16 + (lane>>2);
            int c = col0 + wn*32 + nf*8 + (lane&3)*2;
#pragma unroll
            for (int half = 0; half < 2; half++) {
                int rr = r + half*8;
                float v0 = acc[mf][nf][half*2+0];
                float v1 = acc[mf][nf][half*2+1];
                if (bias)  { v0 += bias[c]; v1 += bias[c+1]; }
                if (resid) {
                    const float2 rv = *(const float2*)(resid + (size_t)rr*N + c);
                    v0 += rv.x; v1 += rv.y;
                }
                if (relu) { v0 = fmaxf(v0, 0.f); v1 = fmaxf(v1, 0.f); }
                float2 out; out.x = v0; out.y = v1;
                *(float2*)(C + (size_t)rr*N + c) = out;
            }
        }
    }
}

// fused attention GEMM
#define SIM_STRIDE 132
__global__ __launch_bounds__(256, 2)
void tf32gemm_attn(int M, int N, int K,
                   const float* __restrict__ QH, const float* __restrict__ KH,
                   const float* __restrict__ b1,
                   const float* __restrict__ B,
                   const float* __restrict__ bias,
                   const float* __restrict__ V,
                   const int* __restrict__ nn, int Tq, int knn_k, int Tt,
                   const float* __restrict__ skipb,
                   float* __restrict__ out) {
    extern __shared__ float smem[];
    const int STAGE = 2*A_ELEMS + B_ELEMS;
    __shared__ int   sQoff[TBM];
    __shared__ int   sKoff[TBM];
    __shared__ float b1s[CD];

    int tid  = threadIdx.x;
    int lane = tid & 31;
    int warp = tid >> 5;
    int wm = warp >> 2;
    int wn = warp & 3;
    int row0 = blockIdx.y*TBM;
    int col0 = blockIdx.x*TBN;

    if (tid < TBM) {
        int r = row0 + tid;
        int p = r / knn_k;
        int b = p / Tq;
        sQoff[tid] = p * CD;
        sKoff[tid] = (b*Tt + nn[r]) * CD;
    }
    b1s[tid] = b1[tid];
    __syncthreads();

    float acc[4][4][4];
#pragma unroll
    for (int i = 0; i < 4; i++)
#pragma unroll
        for (int j = 0; j < 4; j++)
#pragma unroll
            for (int r = 0; r < 4; r++) acc[i][j][r] = 0.f;

    gemm_mainloop<1>(acc, nullptr, 0, QH, KH, sQoff, sKoff, b1s, nullptr,
                     B, CD, K, row0, col0, smem, STAGE, tid, lane, wm, wn);

    float* sim_s = smem;
#pragma unroll
    for (int mf = 0; mf < 4; mf++) {
#pragma unroll
        for (int nf = 0; nf < 4; nf++) {
            int r = wm*64 + mf*16 + (lane>>2);
            int c = wn*32 + nf*8 + (lane&3)*2;
#pragma unroll
            for (int half = 0; half < 2; half++) {
                int rr = r + half*8;
                float v0 = acc[mf][nf][half*2+0] + bias[col0 + c];
                float v1 = acc[mf][nf][half*2+1] + bias[col0 + c + 1];
                sim_s[rr*SIM_STRIDE + c]     = v0;
                sim_s[rr*SIM_STRIDE + c + 1] = v1;
            }
        }
    }
    __syncthreads();

    int ppb = TBM / knn_k;
    int col = tid & 127;
    int cg  = col0 + col;
    for (int pp = tid >> 7; pp < ppb; pp += 2) {
        const float* Sp = sim_s + (pp*knn_k)*SIM_STRIDE + col;
        float m = -INF_F;
        for (int n = 0; n < knn_k; n++) m = fmaxf(m, Sp[n*SIM_STRIDE]);
        float den = 0.f, accv = 0.f;
        for (int n = 0; n < knn_k; n++) {
            float e = expf(Sp[n*SIM_STRIDE] - m);
            den += e;
            accv += e * V[(size_t)sKoff[pp*knn_k + n] + cg];
        }
        int pg = row0/knn_k + pp;
        out[(size_t)pg*CD + cg] = accv/den + skipb[(size_t)pg*CD + cg];
    }
}

// ---------------- final pooling / embedding ----------------
__global__ void pool_kernel(const float* __restrict__ tok, float* __restrict__ g, int Tq) {
    int b = blockIdx.x, c = threadIdx.x;
    float s = 0.f;
    for (int t = 0; t < Tq; t++) s += tok[(size_t)(b*Tq + t)*CD + c];
    g[b*CD + c] = s / (float)Tq;
}

__global__ void emb_kernel(const float* __restrict__ g, const float* __restrict__ W,
                           const float* __restrict__ bias, float* __restrict__ out) {
    int b = blockIdx.x, e = threadIdx.x;
    __shared__ float gs[CD];
    if (e < CD) gs[e] = g[b*CD + e];
    __syncthreads();
    float s = 0.f;
    for (int c = 0; c < CD; c++) s += gs[c] * W[(size_t)c*ED + e];
    out[b*ED + e] = s + bias[e];
}

__global__ void final_bn_kernel(float* __restrict__ x, const float* __restrict__ gamma,
                                const float* __restrict__ beta) {
    int e = threadIdx.x;
    float s = 0.f;
    for (int b = 0; b < BQN; b++) s += x[b*ED + e];
    float m = s / (float)BQN;
    float v = 0.f;
    for (int b = 0; b < BQN; b++) { float d = x[b*ED + e] - m; v += d*d; }
    v /= (float)BQN;
    float rs = rsqrtf(v + 1e-5f);
    for (int b = 0; b < BQN; b++) {
        float val = (x[b*ED + e] - m) * rs * gamma[e] + beta[e];
        x[b*ED + e] = fmaxf(val, 0.f);
    }
}

__global__ void topk_norm_kernel(const float* __restrict__ x, float* __restrict__ out) {
    int b = blockIdx.x, t = threadIdx.x;
    __shared__ float vals[ED], work[ED];
    __shared__ float red[16];
    __shared__ int   redi[16];
    __shared__ float s_thr, s_norm;
    float v = x[b*ED + t];
    vals[t] = v; work[t] = v;
    __syncthreads();
    for (int it = 0; it < 64; it++) {
        float bv = work[t]; int bi = t;
#pragma unroll
        for (int off = 16; off > 0; off >>= 1) {
            float ov = __shfl_down_sync(0xffffffffu, bv, off);
            int   oi = __shfl_down_sync(0xffffffffu, bi, off);
            if (ov > bv) { bv = ov; bi = oi; }
        }
        if ((t & 31) == 0) { red[t>>5] = bv; redi[t>>5] = bi; }
        __syncthreads();
        if (t == 0) {
            bv = red[0]; bi = redi[0];
            for (int w = 1; w < 16; w++) if (red[w] > bv) { bv = red[w]; bi = redi[w]; }
            work[bi] = -INF_F;
            if (it == 63) s_thr = bv;
        }
        __syncthreads();
    }
    float thr = s_thr;
    float kept = (vals[t] >= thr) ? vals[t] : 0.f;
    float sq = kept*kept;
#pragma unroll
    for (int off = 16; off > 0; off >>= 1) sq += __shfl_down_sync(0xffffffffu, sq, off);
    if ((t & 31) == 0) red[t>>5] = sq;
    __syncthreads();
    if (t == 0) {
        float s = 0.f;
        for (int w = 0; w < 16; w++) s += red[w];
        s_norm = fmaxf(sqrtf(s), 1e-12f);
    }
    __syncthreads();
    out[b*ED + t] = kept / s_norm;
}

// ---------------- host orchestration ----------------
extern "C" void kernel_launch(void* const* d_in, const int* in_sizes, int n_in,
                              void* d_out, int out_size) {
    const float* tokens = (const float*)d_in[0];
    const float* centers = (const float*)d_in[1];
    const float* wq     = (const float*)d_in[3];
    const float* wkv    = (const float*)d_in[4];
    const float* mlp_w1 = (const float*)d_in[5];
    const float* mlp_b1 = (const float*)d_in[6];
    const float* mlp_w2 = (const float*)d_in[7];
    const float* mlp_b2 = (const float*)d_in[8];
    const float* bn1_g  = (const float*)d_in[9];
    const float* bn1_b  = (const float*)d_in[10];
    const float* bn2_g  = (const float*)d_in[11];
    const float* bn2_b  = (const float*)d_in[12];
    const float* att_w1 = (const float*)d_in[13];
    const float* att_b1 = (const float*)d_in[14];
    const float* att_w2 = (const float*)d_in[15];
    const float* att_b2 = (const float*)d_in[16];
    const float* emb_w  = (const float*)d_in[17];
    const float* emb_b  = (const float*)d_in[18];
    const float* embn_g = (const float*)d_in[19];
    const float* embn_b = (const float*)d_in[20];

    float *tok_buf, *tok_q, *tq, *QH, *KH, *V, *mlph, *wqh, *wkh;
    float *cent_a, *cent_b, *psum, *psq, *stats, *pool, *embv;
    int *rep, *nn;
    cudaGetSymbolAddress((void**)&tok_buf, g_tokens_t);
    cudaGetSymbolAddress((void**)&tok_q,  g_tokens_q);
    cudaGetSymbolAddress((void**)&tq,     g_tq);
    cudaGetSymbolAddress((void**)&QH,     g_QH);
    cudaGetSymbolAddress((void**)&KH,     g_KH);
    cudaGetSymbolAddress((void**)&V,      g_V);
    cudaGetSymbolAddress((void**)&mlph,   g_mlph);
    cudaGetSymbolAddress((void**)&wqh,    g_wqh);
    cudaGetSymbolAddress((void**)&wkh,    g_wkh);
    cudaGetSymbolAddress((void**)&cent_a, g_centers_a);
    cudaGetSymbolAddress((void**)&cent_b, g_centers_b);
    cudaGetSymbolAddress((void**)&psum,   g_psum);
    cudaGetSymbolAddress((void**)&psq,    g_psq);
    cudaGetSymbolAddress((void**)&stats,  g_stats);
    cudaGetSymbolAddress((void**)&pool,   g_pool);
    cudaGetSymbolAddress((void**)&embv,   g_embv);
    cudaGetSymbolAddress((void**)&rep,    g_rep);
    cudaGetSymbolAddress((void**)&nn,     g_nn);

    const int SMEM_PLAIN = 2*(A_ELEMS + B_ELEMS)*sizeof(float);
    const int SMEM_ATTN  = 2*(2*A_ELEMS + B_ELEMS)*sizeof(float);
    static cudaStream_t s1, s2;
    static cudaEvent_t evFork, evJ1, evJ2;
    static bool init_done = false;
    if (!init_done) {
        cudaFuncSetAttribute(tf32gemm<0>,   cudaFuncAttributeMaxDynamicSharedMemorySize, SMEM_PLAIN);
        cudaFuncSetAttribute(tf32gemm<1>,   cudaFuncAttributeMaxDynamicSharedMemorySize, SMEM_PLAIN);
        cudaFuncSetAttribute(tf32gemm_attn, cudaFuncAttributeMaxDynamicSharedMemorySize, SMEM_ATTN);
        cudaStreamCreateWithFlags(&s1, cudaStreamNonBlocking);
        cudaStreamCreateWithFlags(&s2, cudaStreamNonBlocking);
        cudaEventCreateWithFlags(&evFork, cudaEventDisableTiming);
        cudaEventCreateWithFlags(&evJ1,   cudaEventDisableTiming);
        cudaEventCreateWithFlags(&evJ2,   cudaEventDisableTiming);
        init_done = true;
    }

    // ---- fork: all 6 weight products on side streams ----
    cudaEventRecord(evFork, 0);
    cudaStreamWaitEvent(s1, evFork, 0);
    cudaStreamWaitEvent(s2, evFork, 0);
    for (int i = 0; i < 3; i++) {
        wprod_kernel<<<128, 256, 0, s1>>>(wq  + (size_t)i*CD*CD,   CD,
                                          att_w1 + (size_t)i*CD*CD, CD, wqh + (size_t)i*CD*CD);
        wprod_kernel<<<128, 256, 0, s2>>>(wkv + (size_t)i*CD*2*CD, 2*CD,
                                          att_w1 + (size_t)i*CD*CD, CD, wkh + (size_t)i*CD*CD);
    }
    cudaEventRecord(evJ1, s1);
    cudaEventRecord(evJ2, s2);

    const int Tts[3] = {1024, 512, 256};
    const int Tqs[3] = {512, 256, 128};
    const int ks [3] = {16, 32, 64};

    const float* tok_src  = tokens;
    const float* cent_src = centers;
    float* cent_dsts[3] = {cent_a, cent_b, cent_a};

    for (int i = 0; i < 3; i++) {
        int Tt = Tts[i], Tq = Tqs[i], k = ks[i];
        int Mq = BQN*Tq, Mt = BQN*Tt, Mr = Mq*k;
        float* cent_dst = cent_dsts[i];
        const float* wqh_i = wqh + (size_t)i*CD*CD;
        const float* wkh_i = wkh + (size_t)i*CD*CD;

        fps_kernel   <<<BQN, 256>>>(cent_src, Tt, Tq, rep);
        gather_kernel<<<Mq, 256>>>(tok_src, cent_src, rep, tok_q, cent_dst, Tt, Tq);
        knn_kernel   <<<Mq, 256>>>(cent_dst, cent_src, Tt, Tq, k, nn);

        if (i == 0) {
            cudaStreamWaitEvent(0, evJ1, 0);
            cudaStreamWaitEvent(0, evJ2, 0);
        }

        if (i > 0) {
            bn_partial <<<BN_BLOCKS, 256>>>(tok_q, Mq, tok_src, Mt, psum, psq);
            bn_finalize<<<1, 256>>>(psum, psq, BN_BLOCKS, Mq + Mt, bn1_g + i*CD, bn1_b + i*CD, stats);

            tf32gemm<1><<<dim3(CD/TBN, Mq/TBM), 256, SMEM_PLAIN>>>(Mq, CD, CD, CD, CD,
                tok_q, wqh_i, stats, nullptr, nullptr, QH, 0);
            tf32gemm<1><<<dim3(CD/TBN, Mt/TBM), 256, SMEM_PLAIN>>>(Mt, CD, CD, CD, CD,
                tok_src, wkh_i, stats, nullptr, nullptr, KH, 0);
            tf32gemm<1><<<dim3(CD/TBN, Mt/TBM), 256, SMEM_PLAIN>>>(Mt, CD, CD, CD, 2*CD,
                tok_src, wkv + (size_t)i*CD*2*CD + CD, stats, nullptr, nullptr, V, 0);
        } else {
            tf32gemm<0><<<dim3(CD/TBN, Mq/TBM), 256, SMEM_PLAIN>>>(Mq, CD, CD, CD, CD,
                tok_q, wqh_i, nullptr, nullptr, nullptr, QH, 0);
            tf32gemm<0><<<dim3(CD/TBN, Mt/TBM), 256, SMEM_PLAIN>>>(Mt, CD, CD, CD, CD,
                tok_src, wkh_i, nullptr, nullptr, nullptr, KH, 0);
            tf32gemm<0><<<dim3(CD/TBN, Mt/TBM), 256, SMEM_PLAIN>>>(Mt, CD, CD, CD, 2*CD,
                tok_src, wkv + (size_t)i*CD*2*CD + CD, nullptr, nullptr, nullptr, V, 0);
        }

        tf32gemm_attn<<<dim3(CD/TBN, Mr/TBM), 256, SMEM_ATTN>>>(Mr, CD, CD,
            QH, KH, att_b1 + i*CD,
            att_w2 + (size_t)i*CD*CD, att_b2 + i*CD,
            V, nn, Tq, k, Tt, tok_q, tq);

        bn_partial <<<BN_BLOCKS, 256>>>(tq, Mq, nullptr, 0, psum, psq);
        bn_finalize<<<1, 256>>>(psum, psq, BN_BLOCKS, Mq, bn2_g + i*CD, bn2_b + i*CD, stats);

        tf32gemm<1><<<dim3(2*CD/TBN, Mq/TBM), 256, SMEM_PLAIN>>>(Mq, 2*CD, CD, CD, 2*CD,
            tq, mlp_w1 + (size_t)i*CD*2*CD, stats, mlp_b1 + i*2*CD, nullptr, mlph, 1);
        tf32gemm<0><<<dim3(CD/TBN, Mq/TBM), 256, SMEM_PLAIN>>>(Mq, CD, 2*CD, 2*CD, CD,
            mlph, mlp_w2 + (size_t)i*2*CD*CD, nullptr, mlp_b2 + i*CD, tq, tok_buf, 0);

        tok_src  = tok_buf;
        cent_src = cent_dst;
    }

    pool_kernel     <<<BQN, 256>>>(tok_buf, pool, 128);
    emb_kernel      <<<BQN, 512>>>(pool, emb_w, emb_b, embv);
    final_bn_kernel <<<1, 512>>>(embv, embn_g, embn_b);
    topk_norm_kernel<<<BQN, 512>>>(embv, (float*)d_out);
}

// round 15
// speedup vs baseline: 1.3308x; 1.1336x over previous
#include <cuda_runtime.h>
#include <math.h>
#include <stdint.h>

#define INF_F (__int_as_float(0x7f800000))

// ---------------- problem constants ----------------
#define BQN 16
#define T0 1024
#define CD 256
#define ED 512
#define MAXROWS 131072
#define BN_BLOCKS 256

// ---------------- static device scratch ----------------
__device__ float g_tokens_t[BQN*T0*CD];
__device__ float g_tokens_q[BQN*512*CD];
__device__ float g_tq      [BQN*512*CD];
__device__ float g_QH      [BQN*512*CD];
__device__ float g_KH      [BQN*T0*CD];
__device__ float g_V       [BQN*T0*CD];
__device__ float g_mlph    [BQN*512*2*CD];
__device__ float g_wqh     [3*CD*CD];
__device__ float g_wkh     [3*CD*CD];
__device__ float g_cent0   [BQN*512*3];
__device__ float g_cent1   [BQN*256*3];
__device__ float g_cent2   [BQN*128*3];
__device__ int   g_rep[3*BQN*512];
__device__ int   g_nn [3*MAXROWS];
__device__ float g_psum[BN_BLOCKS*CD];
__device__ float g_psq [BN_BLOCKS*CD];
__device__ float g_stats[2*CD];   // [scale | shift]
__device__ float g_pool[BQN*CD];
__device__ float g_embv[BQN*ED];

// ---------------- FPS ----------------
__global__ void fps_kernel(const float* __restrict__ centers, int Tt, int Tq,
                           int* __restrict__ rep_idx) {
    int b = blockIdx.x;
    const float* P = centers + (size_t)b * Tt * 3;
    __shared__ float sx[1024], sy[1024], sz[1024];
    __shared__ float s_bv[8];
    __shared__ int   s_bi[8];
    __shared__ int   s_cur;
    int tid = threadIdx.x;
    int npt = Tt >> 8;
    float d[4];
#pragma unroll
    for (int j = 0; j < 4; j++) d[j] = INF_F;
    for (int j = tid; j < Tt; j += 256) {
        sx[j] = P[j*3+0]; sy[j] = P[j*3+1]; sz[j] = P[j*3+2];
    }
    if (tid == 0) s_cur = 0;
    __syncthreads();

    for (int step = 0; step < Tq; step++) {
        int cur = s_cur;
        if (tid == 0) rep_idx[b*Tq + step] = cur;
        float cx = sx[cur], cy = sy[cur], cz = sz[cur];
        float bv = -INF_F; int bi = 0x7fffffff;
#pragma unroll
        for (int j = 0; j < 4; j++) {
            if (j < npt) {
                int p = j*256 + tid;
                float dx = sx[p]-cx, dy = sy[p]-cy, dz = sz[p]-cz;
                float dist = dx*dx + dy*dy + dz*dz;
                float dj = fminf(d[j], dist);
                d[j] = dj;
                if (dj > bv || (dj == bv && p < bi)) { bv = dj; bi = p; }
            }
        }
#pragma unroll
        for (int off = 16; off > 0; off >>= 1) {
            float ov = __shfl_down_sync(0xffffffffu, bv, off);
            int   oi = __shfl_down_sync(0xffffffffu, bi, off);
            if (ov > bv || (ov == bv && oi < bi)) { bv = ov; bi = oi; }
        }
        if ((tid & 31) == 0) { s_bv[tid>>5] = bv; s_bi[tid>>5] = bi; }
        __syncthreads();
        if (tid == 0) {
            bv = s_bv[0]; bi = s_bi[0];
            for (int w = 1; w < 8; w++) {
                if (s_bv[w] > bv || (s_bv[w] == bv && s_bi[w] < bi)) { bv = s_bv[w]; bi = s_bi[w]; }
            }
            s_cur = bi;
        }
        __syncthreads();
    }
}

// ---------------- split gathers ----------------
__global__ void gather_cent(const float* __restrict__ cent_t,
                            const int* __restrict__ rep,
                            float* __restrict__ cent_q, int Tt, int Tq, int n3) {
    int idx = blockIdx.x*blockDim.x + threadIdx.x;
    if (idx >= n3) return;
    int p = idx/3, c = idx%3;
    int b = p / Tq;
    cent_q[idx] = cent_t[(size_t)(b*Tt + rep[p])*3 + c];
}

__global__ void gather_tok(const float* __restrict__ tok_t,
                           const int* __restrict__ rep,
                           float* __restrict__ tok_q, int Tt, int Tq) {
    int p = blockIdx.x;
    int b = p / Tq;
    int src = rep[p];
    int c = threadIdx.x;
    tok_q[(size_t)p*CD + c] = tok_t[(size_t)(b*Tt + src)*CD + c];
}

// ---------------- KNN ----------------
__global__ void knn_kernel(const float* __restrict__ cent_q,
                           const float* __restrict__ cent_t,
                           int Tt, int Tq, int k, int* __restrict__ nn) {
    int p = blockIdx.x;
    int b = p / Tq;
    __shared__ float d2s[1024];
    __shared__ float s_bv[8];
    __shared__ int   s_bi[8];
    int tid = threadIdx.x;
    float qx = cent_q[p*3], qy = cent_q[p*3+1], qz = cent_q[p*3+2];
    float qq = qx*qx + qy*qy + qz*qz;
    const float* Pt = cent_t + (size_t)b*Tt*3;
    for (int t = tid; t < Tt; t += 256) {
        float tx = Pt[t*3], ty = Pt[t*3+1], tz = Pt[t*3+2];
        float tt = tx*tx + ty*ty + tz*tz;
        float dt = qx*tx + qy*ty + qz*tz;
        d2s[t] = (qq + tt) - 2.0f*dt;
    }
    __syncthreads();
    for (int sel = 0; sel < k; sel++) {
        float bv = INF_F; int bi = 0x7fffffff;
        for (int t = tid; t < Tt; t += 256) {
            float v = d2s[t];
            if (v < bv || (v == bv && t < bi)) { bv = v; bi = t; }
        }
#pragma unroll
        for (int off = 16; off > 0; off >>= 1) {
            float ov = __shfl_down_sync(0xffffffffu, bv, off);
            int   oi = __shfl_down_sync(0xffffffffu, bi, off);
            if (ov < bv || (ov == bv && oi < bi)) { bv = ov; bi = oi; }
        }
        if ((tid & 31) == 0) { s_bv[tid>>5] = bv; s_bi[tid>>5] = bi; }
        __syncthreads();
        if (tid == 0) {
            bv = s_bv[0]; bi = s_bi[0];
            for (int w = 1; w < 8; w++) {
                if (s_bv[w] < bv || (s_bv[w] == bv && s_bi[w] < bi)) { bv = s_bv[w]; bi = s_bi[w]; }
            }
            nn[p*k + sel] = bi;
            d2s[bi] = INF_F;
        }
        __syncthreads();
    }
}

// ---------------- BN stats: 256 blocks, float4 channels, 4 row-subsets ----------------
__global__ void bn_partial(const float* __restrict__ x1, int rows1,
                           const float* __restrict__ x2, int rows2,
                           float* __restrict__ psum, float* __restrict__ psq) {
    __shared__ float ssum[4][CD];
    __shared__ float ssq [4][CD];
    int tid  = threadIdx.x;
    int cg   = (tid & 63) * 4;
    int rsub = tid >> 6;
    int total = rows1 + rows2;
    float4 s  = make_float4(0.f, 0.f, 0.f, 0.f);
    float4 sq = make_float4(0.f, 0.f, 0.f, 0.f);
    for (int r = blockIdx.x*4 + rsub; r < total; r += gridDim.x*4) {
        const float* row = (r < rows1) ? (x1 + (size_t)r*CD) : (x2 + (size_t)(r - rows1)*CD);
        float4 v = *(const float4*)(row + cg);
        s.x += v.x; s.y += v.y; s.z += v.z; s.w += v.w;
        sq.x += v.x*v.x; sq.y += v.y*v.y; sq.z += v.z*v.z; sq.w += v.w*v.w;
    }
    *(float4*)(&ssum[rsub][cg]) = s;
    *(float4*)(&ssq [rsub][cg]) = sq;
    __syncthreads();
    if (rsub == 0) {
#pragma unroll
        for (int j = 0; j < 4; j++) {
            int c = cg + j;
            float a = ssum[0][c] + ssum[1][c] + ssum[2][c] + ssum[3][c];
            float b = ssq [0][c] + ssq [1][c] + ssq [2][c] + ssq [3][c];
            psum[blockIdx.x*CD + c] = a;
            psq [blockIdx.x*CD + c] = b;
        }
    }
}

__global__ void bn_finalize(const float* __restrict__ psum, const float* __restrict__ psq,
                            int nb, int rows,
                            const float* __restrict__ gamma, const float* __restrict__ beta,
                            float* __restrict__ stats) {
    int c = threadIdx.x;
    float s = 0.f, sq = 0.f;
#pragma unroll 8
    for (int b = 0; b < nb; b++) { s += psum[b*CD + c]; sq += psq[b*CD + c]; }
    float m = s / (float)rows;
    float v = sq / (float)rows - m*m;
    float rstd = rsqrtf(v + 1e-5f);
    float sc = gamma[c] * rstd;
    stats[c]      = sc;
    stats[CD + c] = beta[c] - m * sc;
}

// ---------------- exact-fp32 weight product ----------------
__global__ void wprod_kernel(const float* __restrict__ A, int lda,
                             const float* __restrict__ B, int ldb,
                             float* __restrict__ C) {
    __shared__ float arow[2][CD];
    int r0 = blockIdx.x*2;
    int tid = threadIdx.x;
    arow[0][tid] = A[(size_t)(r0+0)*lda + tid];
    arow[1][tid] = A[(size_t)(r0+1)*lda + tid];
    __syncthreads();
    float acc0 = 0.f, acc1 = 0.f;
#pragma unroll 16
    for (int c = 0; c < CD; c++) {
        float bv = __ldg(&B[(size_t)c*ldb + tid]);
        acc0 += arow[0][c]*bv;
        acc1 += arow[1][c]*bv;
    }
    C[(size_t)(r0+0)*CD + tid] = acc0;
    C[(size_t)(r0+1)*CD + tid] = acc1;
}

// ---------------- TF32 tensor-core GEMM, TBK=32, 2-stage cp.async ----------------
#define TBM 128
#define TBN 128
#define TBK 32
#define AS_STRIDE 36
#define BS_STRIDE 136
#define A_ELEMS (TBM*AS_STRIDE)
#define B_ELEMS (TBK*BS_STRIDE)

__device__ __forceinline__ void mma_tf32(float* c, const uint32_t* a, const uint32_t* b) {
    asm volatile(
        "mma.sync.aligned.m16n8k8.row.col.f32.tf32.tf32.f32 "
        "{%0,%1,%2,%3}, {%4,%5,%6,%7}, {%8,%9}, {%0,%1,%2,%3};\n"
        : "+f"(c[0]), "+f"(c[1]), "+f"(c[2]), "+f"(c[3])
        : "r"(a[0]), "r"(a[1]), "r"(a[2]), "r"(a[3]),
          "r"(b[0]), "r"(b[1]));
}

__device__ __forceinline__ void cp_async16(uint32_t dst, const void* src) {
    asm volatile("cp.async.cg.shared.global [%0], [%1], 16;" :: "r"(dst), "l"(src));
}
__device__ __forceinline__ void cp_commit() {
    asm volatile("cp.async.commit_group;");
}
__device__ __forceinline__ void cp_wait1() {
    asm volatile("cp.async.wait_group 1;");
}

// MODE 0: plain A. MODE 1: A[r]=relu(QH-KH[nn]+b1). MODE 2: A*sc+sh (BN folded).
template<int MODE>
__device__ __forceinline__ void gemm_mainloop(
    float acc[4][4][4],
    const float* __restrict__ A, int lda,
    const float* __restrict__ QH, const float* __restrict__ KH,
    const int* sQoff, const int* sKoff,
    const float* sc_s, const float* sh_s,
    const float* __restrict__ B, int ldb,
    int K, int row0, int col0,
    float* smem, int STAGE,
    int tid, int lane, int wm, int wn)
{
    int ldrow = tid >> 3;
    int ldcol = (tid & 7) * 4;

    auto load_stage = [&](int s, int kt) {
        float* As_  = smem + s*STAGE;
        float* Akv_ = As_ + A_ELEMS;
        float* Bs_  = As_ + (MODE == 1 ? 2*A_ELEMS : A_ELEMS);
#pragma unroll
        for (int i = 0; i < 4; i++) {
            int arow = ldrow + 32*i;
            uint32_t dA = (uint32_t)__cvta_generic_to_shared(&As_[arow*AS_STRIDE + ldcol]);
            if (MODE == 1) {
                cp_async16(dA, QH + sQoff[arow] + kt + ldcol);
                uint32_t dK = (uint32_t)__cvta_generic_to_shared(&Akv_[arow*AS_STRIDE + ldcol]);
                cp_async16(dK, KH + sKoff[arow] + kt + ldcol);
            } else {
                cp_async16(dA, A + (size_t)(row0 + arow)*lda + kt + ldcol);
            }
        }
#pragma unroll
        for (int i = 0; i < 4; i++) {
            int bcol = ldcol + 32*i;
            uint32_t dB = (uint32_t)__cvta_generic_to_shared(&Bs_[ldrow*BS_STRIDE + bcol]);
            cp_async16(dB, B + (size_t)(kt + ldrow)*ldb + col0 + bcol);
        }
    };

    const int NIT = K / TBK;
    load_stage(0, 0);
    cp_commit();

    for (int it = 0; it < NIT; it++) {
        if (it + 1 < NIT) load_stage((it+1)&1, (it+1)*TBK);
        cp_commit();
        cp_wait1();
        __syncthreads();

        int s = it & 1;
        int ktg = it*TBK;
        const float* As_  = smem + s*STAGE;
        const float* Akv_ = As_ + A_ELEMS;
        const float* Bs_  = As_ + (MODE == 1 ? 2*A_ELEMS : A_ELEMS);

#pragma unroll
        for (int kk = 0; kk < 4; kk++) {
            int kc = kk*8;
            float cA = 0.f, cB = 0.f, hA = 0.f, hB = 0.f;
            if (MODE == 1) {
                cA = sc_s[ktg + kc + (lane&3)];
                cB = sc_s[ktg + kc + 4 + (lane&3)];
            } else if (MODE == 2) {
                cA = sc_s[ktg + kc + (lane&3)];
                cB = sc_s[ktg + kc + 4 + (lane&3)];
                hA = sh_s[ktg + kc + (lane&3)];
                hB = sh_s[ktg + kc + 4 + (lane&3)];
            }
            uint32_t a[4][4];
#pragma unroll
            for (int mf = 0; mf < 4; mf++) {
                int r1 = wm*64 + mf*16 + (lane>>2);
                int i0 = r1*AS_STRIDE      + kc + (lane&3);
                int i1 = (r1+8)*AS_STRIDE  + kc + (lane&3);
                if (MODE == 1) {
                    a[mf][0] = __float_as_uint(fmaxf(As_[i0]     - Akv_[i0]     + cA, 0.f));
                    a[mf][1] = __float_as_uint(fmaxf(As_[i1]     - Akv_[i1]     + cA, 0.f));
                    a[mf][2] = __float_as_uint(fmaxf(As_[i0 + 4] - Akv_[i0 + 4] + cB, 0.f));
                    a[mf][3] = __float_as_uint(fmaxf(As_[i1 + 4] - Akv_[i1 + 4] + cB, 0.f));
                } else if (MODE == 2) {
                    a[mf][0] = __float_as_uint(fmaf(As_[i0],     cA, hA));
                    a[mf][1] = __float_as_uint(fmaf(As_[i1],     cA, hA));
                    a[mf][2] = __float_as_uint(fmaf(As_[i0 + 4], cB, hB));
                    a[mf][3] = __float_as_uint(fmaf(As_[i1 + 4], cB, hB));
                } else {
                    a[mf][0] = __float_as_uint(As_[i0]);
                    a[mf][1] = __float_as_uint(As_[i1]);
                    a[mf][2] = __float_as_uint(As_[i0 + 4]);
                    a[mf][3] = __float_as_uint(As_[i1 + 4]);
                }
            }
            uint32_t b[4][2];
#pragma unroll
            for (int nf = 0; nf < 4; nf++) {
                int ncol = wn*32 + nf*8 + (lane>>2);
                b[nf][0] = __float_as_uint(Bs_[(kc     + (lane&3))*BS_STRIDE + ncol]);
                b[nf][1] = __float_as_uint(Bs_[(kc + 4 + (lane&3))*BS_STRIDE + ncol]);
            }
#pragma unroll
            for (int mf = 0; mf < 4; mf++)
#pragma unroll
                for (int nf = 0; nf < 4; nf++)
                    mma_tf32(acc[mf][nf], a[mf], b[nf]);
        }
        __syncthreads();
    }
}

template<int BN>
__global__ __launch_bounds__(256, 2)
void tf32gemm(int M, int N, int K, int lda, int ldb,
              const float* __restrict__ A,
              const float* __restrict__ B,
              const float* __restrict__ bnstats,
              const float* __restrict__ bias, const float* __restrict__ resid,
              float* __restrict__ C, int relu) {
    extern __shared__ float smem[];
    const int STAGE = A_ELEMS + B_ELEMS;
    __shared__ float scs[CD], shs[CD];

    int tid  = threadIdx.x;
    int lane = tid & 31;
    int warp = tid >> 5;
    int wm = warp >> 2;
    int wn = warp & 3;
    int row0 = blockIdx.y*TBM;
    int col0 = blockIdx.x*TBN;

    if (BN) {
        scs[tid] = bnstats[tid];
        shs[tid] = bnstats[CD + tid];
        __syncthreads();
    }

    float acc[4][4][4];
#pragma unroll
    for (int i = 0; i < 4; i++)
#pragma unroll
        for (int j = 0; j < 4; j++)
#pragma unroll
            for (int r = 0; r < 4; r++) acc[i][j][r] = 0.f;

    gemm_mainloop<BN ? 2 : 0>(acc, A, lda, nullptr, nullptr, nullptr, nullptr,
                              scs, shs, B, ldb, K, row0, col0,
                              smem, STAGE, tid, lane, wm, wn);

#pragma unroll
    for (int mf = 0; mf < 4; mf++) {
#pragma unroll
        for (int nf = 0; nf < 4; nf++) {
            int r = row0 + wm*64 + mf*16 + (lane>>2);
            int c = col0 + wn*32 + nf*8 + (lane&3)*2;
#pragma unroll
            for (int half = 0; half < 2; half++) {
                int rr = r + half*8;
                float v0 = acc[mf][nf][half*2+0];
                float v1 = acc[mf][nf][half*2+1];
                if (bias)  { v0 += bias[c]; v1 += bias[c+1]; }
                if (resid) {
                    const float2 rv = *(const float2*)(resid + (size_t)rr*N + c);
                    v0 += rv.x; v1 += rv.y;
                }
                if (relu) { v0 = fmaxf(v0, 0.f); v1 = fmaxf(v1, 0.f); }
                float2 out; out.x = v0; out.y = v1;
                *(float2*)(C + (size_t)rr*N + c) = out;
            }
        }
    }
}

// fused attention GEMM
#define SIM_STRIDE 132
__global__ __launch_bounds__(256, 2)
void tf32gemm_attn(int M, int N, int K,
                   const float* __restrict__ QH, const float* __restrict__ KH,
                   const float* __restrict__ b1,
                   const float* __restrict__ B,
                   const float* __restrict__ bias,
                   const float* __restrict__ V,
                   const int* __restrict__ nn, int Tq, int knn_k, int Tt,
                   const float* __restrict__ skipb,
                   float* __restrict__ out) {
    extern __shared__ float smem[];
    const int STAGE = 2*A_ELEMS + B_ELEMS;
    __shared__ int   sQoff[TBM];
    __shared__ int   sKoff[TBM];
    __shared__ float b1s[CD];

    int tid  = threadIdx.x;
    int lane = tid & 31;
    int warp = tid >> 5;
    int wm = warp >> 2;
    int wn = warp & 3;
    int row0 = blockIdx.y*TBM;
    int col0 = blockIdx.x*TBN;

    if (tid < TBM) {
        int r = row0 + tid;
        int p = r / knn_k;
        int b = p / Tq;
        sQoff[tid] = p * CD;
        sKoff[tid] = (b*Tt + nn[r]) * CD;
    }
    b1s[tid] = b1[tid];
    __syncthreads();

    float acc[4][4][4];
#pragma unroll
    for (int i = 0; i < 4; i++)
#pragma unroll
        for (int j = 0; j < 4; j++)
#pragma unroll
            for (int r = 0; r < 4; r++) acc[i][j][r] = 0.f;

    gemm_mainloop<1>(acc, nullptr, 0, QH, KH, sQoff, sKoff, b1s, nullptr,
                     B, CD, K, row0, col0, smem, STAGE, tid, lane, wm, wn);

    float* sim_s = smem;
#pragma unroll
    for (int mf = 0; mf < 4; mf++) {
#pragma unroll
        for (int nf = 0; nf < 4; nf++) {
            int r = wm*64 + mf*16 + (lane>>2);
            int c = wn*32 + nf*8 + (lane&3)*2;
#pragma unroll
            for (int half = 0; half < 2; half++) {
                int rr = r + half*8;
                float v0 = acc[mf][nf][half*2+0] + bias[col0 + c];
                float v1 = acc[mf][nf][half*2+1] + bias[col0 + c + 1];
                sim_s[rr*SIM_STRIDE + c]     = v0;
                sim_s[rr*SIM_STRIDE + c + 1] = v1;
            }
        }
    }
    __syncthreads();

    int ppb = TBM / knn_k;
    int col = tid & 127;
    int cg  = col0 + col;
    for (int pp = tid >> 7; pp < ppb; pp += 2) {
        const float* Sp = sim_s + (pp*knn_k)*SIM_STRIDE + col;
        float m = -INF_F;
        for (int n = 0; n < knn_k; n++) m = fmaxf(m, Sp[n*SIM_STRIDE]);
        float den = 0.f, accv = 0.f;
        for (int n = 0; n < knn_k; n++) {
            float e = expf(Sp[n*SIM_STRIDE] - m);
            den += e;
            accv += e * V[(size_t)sKoff[pp*knn_k + n] + cg];
        }
        int pg = row0/knn_k + pp;
        out[(size_t)pg*CD + cg] = accv/den + skipb[(size_t)pg*CD + cg];
    }
}

// ---------------- final pooling / embedding ----------------
__global__ void pool_kernel(const float* __restrict__ tok, float* __restrict__ g, int Tq) {
    int b = blockIdx.x, c = threadIdx.x;
    float s = 0.f;
    for (int t = 0; t < Tq; t++) s += tok[(size_t)(b*Tq + t)*CD + c];
    g[b*CD + c] = s / (float)Tq;
}

__global__ void emb_kernel(const float* __restrict__ g, const float* __restrict__ W,
                           const float* __restrict__ bias, float* __restrict__ out) {
    int b = blockIdx.x, e = threadIdx.x;
    __shared__ float gs[CD];
    if (e < CD) gs[e] = g[b*CD + e];
    __syncthreads();
    float s = 0.f;
    for (int c = 0; c < CD; c++) s += gs[c] * W[(size_t)c*ED + e];
    out[b*ED + e] = s + bias[e];
}

__global__ void final_bn_kernel(float* __restrict__ x, const float* __restrict__ gamma,
                                const float* __restrict__ beta) {
    int e = threadIdx.x;
    float s = 0.f;
    for (int b = 0; b < BQN; b++) s += x[b*ED + e];
    float m = s / (float)BQN;
    float v = 0.f;
    for (int b = 0; b < BQN; b++) { float d = x[b*ED + e] - m; v += d*d; }
    v /= (float)BQN;
    float rs = rsqrtf(v + 1e-5f);
    for (int b = 0; b < BQN; b++) {
        float val = (x[b*ED + e] - m) * rs * gamma[e] + beta[e];
        x[b*ED + e] = fmaxf(val, 0.f);
    }
}

__global__ void topk_norm_kernel(const float* __restrict__ x, float* __restrict__ out) {
    int b = blockIdx.x, t = threadIdx.x;
    __shared__ float vals[ED], work[ED];
    __shared__ float red[16];
    __shared__ int   redi[16];
    __shared__ float s_thr, s_norm;
    float v = x[b*ED + t];
    vals[t] = v; work[t] = v;
    __syncthreads();
    for (int it = 0; it < 64; it++) {
        float bv = work[t]; int bi = t;
#pragma unroll
        for (int off = 16; off > 0; off >>= 1) {
            float ov = __shfl_down_sync(0xffffffffu, bv, off);
            int   oi = __shfl_down_sync(0xffffffffu, bi, off);
            if (ov > bv) { bv = ov; bi = oi; }
        }
        if ((t & 31) == 0) { red[t>>5] = bv; redi[t>>5] = bi; }
        __syncthreads();
        if (t == 0) {
            bv = red[0]; bi = redi[0];
            for (int w = 1; w < 16; w++) if (red[w] > bv) { bv = red[w]; bi = redi[w]; }
            work[bi] = -INF_F;
            if (it == 63) s_thr = bv;
        }
        __syncthreads();
    }
    float thr = s_thr;
    float kept = (vals[t] >= thr) ? vals[t] : 0.f;
    float sq = kept*kept;
#pragma unroll
    for (int off = 16; off > 0; off >>= 1) sq += __shfl_down_sync(0xffffffffu, sq, off);
    if ((t & 31) == 0) red[t>>5] = sq;
    __syncthreads();
    if (t == 0) {
        float s = 0.f;
        for (int w = 0; w < 16; w++) s += red[w];
        s_norm = fmaxf(sqrtf(s), 1e-12f);
    }
    __syncthreads();
    out[b*ED + t] = kept / s_norm;
}

// ---------------- host orchestration ----------------
extern "C" void kernel_launch(void* const* d_in, const int* in_sizes, int n_in,
                              void* d_out, int out_size) {
    const float* tokens = (const float*)d_in[0];
    const float* centers = (const float*)d_in[1];
    const float* wq     = (const float*)d_in[3];
    const float* wkv    = (const float*)d_in[4];
    const float* mlp_w1 = (const float*)d_in[5];
    const float* mlp_b1 = (const float*)d_in[6];
    const float* mlp_w2 = (const float*)d_in[7];
    const float* mlp_b2 = (const float*)d_in[8];
    const float* bn1_g  = (const float*)d_in[9];
    const float* bn1_b  = (const float*)d_in[10];
    const float* bn2_g  = (const float*)d_in[11];
    const float* bn2_b  = (const float*)d_in[12];
    const float* att_w1 = (const float*)d_in[13];
    const float* att_b1 = (const float*)d_in[14];
    const float* att_w2 = (const float*)d_in[15];
    const float* att_b2 = (const float*)d_in[16];
    const float* emb_w  = (const float*)d_in[17];
    const float* emb_b  = (const float*)d_in[18];
    const float* embn_g = (const float*)d_in[19];
    const float* embn_b = (const float*)d_in[20];

    float *tok_buf, *tok_q, *tq, *QH, *KH, *V, *mlph, *wqh, *wkh;
    float *cent0, *cent1, *cent2, *psum, *psq, *stats, *pool, *embv;
    int *rep, *nn;
    cudaGetSymbolAddress((void**)&tok_buf, g_tokens_t);
    cudaGetSymbolAddress((void**)&tok_q,  g_tokens_q);
    cudaGetSymbolAddress((void**)&tq,     g_tq);
    cudaGetSymbolAddress((void**)&QH,     g_QH);
    cudaGetSymbolAddress((void**)&KH,     g_KH);
    cudaGetSymbolAddress((void**)&V,      g_V);
    cudaGetSymbolAddress((void**)&mlph,   g_mlph);
    cudaGetSymbolAddress((void**)&wqh,    g_wqh);
    cudaGetSymbolAddress((void**)&wkh,    g_wkh);
    cudaGetSymbolAddress((void**)&cent0,  g_cent0);
    cudaGetSymbolAddress((void**)&cent1,  g_cent1);
    cudaGetSymbolAddress((void**)&cent2,  g_cent2);
    cudaGetSymbolAddress((void**)&psum,   g_psum);
    cudaGetSymbolAddress((void**)&psq,    g_psq);
    cudaGetSymbolAddress((void**)&stats,  g_stats);
    cudaGetSymbolAddress((void**)&pool,   g_pool);
    cudaGetSymbolAddress((void**)&embv,   g_embv);
    cudaGetSymbolAddress((void**)&rep,    g_rep);
    cudaGetSymbolAddress((void**)&nn,     g_nn);

    const int SMEM_PLAIN = 2*(A_ELEMS + B_ELEMS)*sizeof(float);
    const int SMEM_ATTN  = 2*(2*A_ELEMS + B_ELEMS)*sizeof(float);
    static cudaStream_t s1, s2;
    static cudaEvent_t evFork, evW0, evW1, evJall, evG[3];
    static bool init_done = false;
    if (!init_done) {
        cudaFuncSetAttribute(tf32gemm<0>,   cudaFuncAttributeMaxDynamicSharedMemorySize, SMEM_PLAIN);
        cudaFuncSetAttribute(tf32gemm<1>,   cudaFuncAttributeMaxDynamicSharedMemorySize, SMEM_PLAIN);
        cudaFuncSetAttribute(tf32gemm_attn, cudaFuncAttributeMaxDynamicSharedMemorySize, SMEM_ATTN);
        cudaStreamCreateWithFlags(&s1, cudaStreamNonBlocking);
        cudaStreamCreateWithFlags(&s2, cudaStreamNonBlocking);
        cudaEventCreateWithFlags(&evFork, cudaEventDisableTiming);
        cudaEventCreateWithFlags(&evW0,   cudaEventDisableTiming);
        cudaEventCreateWithFlags(&evW1,   cudaEventDisableTiming);
        cudaEventCreateWithFlags(&evJall, cudaEventDisableTiming);
        for (int i = 0; i < 3; i++) cudaEventCreateWithFlags(&evG[i], cudaEventDisableTiming);
        init_done = true;
    }

    const int Tts[3] = {1024, 512, 256};
    const int Tqs[3] = {512, 256, 128};
    const int ks [3] = {16, 32, 64};
    float* cents[3] = {cent0, cent1, cent2};

    // ---- fork input-only work ----
    cudaEventRecord(evFork, 0);
    cudaStreamWaitEvent(s1, evFork, 0);
    cudaStreamWaitEvent(s2, evFork, 0);

    // s2: weight products; wkh0 first (unblocks KH0), wqh0 second (unblocks QH0)
    wprod_kernel<<<128, 256, 0, s2>>>(wkv, 2*CD, att_w1, CD, wkh);
    cudaEventRecord(evW0, s2);
    wprod_kernel<<<128, 256, 0, s2>>>(wq, CD, att_w1, CD, wqh);
    cudaEventRecord(evW1, s2);
    for (int i = 1; i < 3; i++) {
        wprod_kernel<<<128, 256, 0, s2>>>(wkv + (size_t)i*CD*2*CD, 2*CD,
                                          att_w1 + (size_t)i*CD*CD, CD, wkh + (size_t)i*CD*CD);
        wprod_kernel<<<128, 256, 0, s2>>>(wq  + (size_t)i*CD*CD,   CD,
                                          att_w1 + (size_t)i*CD*CD, CD, wqh + (size_t)i*CD*CD);
    }
    cudaEventRecord(evJall, s2);

    // s1: geometry chain (depends only on input centers)
    {
        const float* cs = centers;
        for (int i = 0; i < 3; i++) {
            int Tt = Tts[i], Tq = Tqs[i], k = ks[i];
            int Mq = BQN*Tq;
            fps_kernel<<<BQN, 256, 0, s1>>>(cs, Tt, Tq, rep + i*BQN*512);
            int n3 = Mq*3;
            gather_cent<<<(n3+255)/256, 256, 0, s1>>>(cs, rep + i*BQN*512, cents[i], Tt, Tq, n3);
            knn_kernel<<<Mq, 256, 0, s1>>>(cents[i], cs, Tt, Tq, k, nn + (size_t)i*MAXROWS);
            cudaEventRecord(evG[i], s1);
            cs = cents[i];
        }
    }

    const float* tok_src = tokens;

    for (int i = 0; i < 3; i++) {
        int Tt = Tts[i], Tq = Tqs[i], k = ks[i];
        int Mq = BQN*Tq, Mt = BQN*Tt, Mr = Mq*k;
        const float* wqh_i = wqh + (size_t)i*CD*CD;
        const float* wkh_i = wkh + (size_t)i*CD*CD;
        const int*   rep_i = rep + i*BQN*512;
        const int*   nn_i  = nn + (size_t)i*MAXROWS;

        if (i == 0) {
            // V0 first: needs only raw tokens + wkv
            tf32gemm<0><<<dim3(CD/TBN, Mt/TBM), 256, SMEM_PLAIN>>>(Mt, CD, CD, CD, 2*CD,
                tok_src, wkv + CD, nullptr, nullptr, nullptr, V, 0);
            cudaStreamWaitEvent(0, evW0, 0);
            tf32gemm<0><<<dim3(CD/TBN, Mt/TBM), 256, SMEM_PLAIN>>>(Mt, CD, CD, CD, CD,
                tok_src, wkh_i, nullptr, nullptr, nullptr, KH, 0);
            cudaStreamWaitEvent(0, evG[0], 0);
            gather_tok<<<Mq, 256>>>(tok_src, rep_i, tok_q, Tt, Tq);
            cudaStreamWaitEvent(0, evW1, 0);
            tf32gemm<0><<<dim3(CD/TBN, Mq/TBM), 256, SMEM_PLAIN>>>(Mq, CD, CD, CD, CD,
                tok_q, wqh_i, nullptr, nullptr, nullptr, QH, 0);
        } else {
            if (i == 1) cudaStreamWaitEvent(0, evJall, 0);
            cudaStreamWaitEvent(0, evG[i], 0);
            gather_tok<<<Mq, 256>>>(tok_src, rep_i, tok_q, Tt, Tq);
            bn_partial <<<BN_BLOCKS, 256>>>(tok_q, Mq, tok_src, Mt, psum, psq);
            bn_finalize<<<1, 256>>>(psum, psq, BN_BLOCKS, Mq + Mt, bn1_g + i*CD, bn1_b + i*CD, stats);

            tf32gemm<1><<<dim3(CD/TBN, Mq/TBM), 256, SMEM_PLAIN>>>(Mq, CD, CD, CD, CD,
                tok_q, wqh_i, stats, nullptr, nullptr, QH, 0);
            tf32gemm<1><<<dim3(CD/TBN, Mt/TBM), 256, SMEM_PLAIN>>>(Mt, CD, CD, CD, CD,
                tok_src, wkh_i, stats, nullptr, nullptr, KH, 0);
            tf32gemm<1><<<dim3(CD/TBN, Mt/TBM), 256, SMEM_PLAIN>>>(Mt, CD, CD, CD, 2*CD,
                tok_src, wkv + (size_t)i*CD*2*CD + CD, stats, nullptr, nullptr, V, 0);
        }

        tf32gemm_attn<<<dim3(CD/TBN, Mr/TBM), 256, SMEM_ATTN>>>(Mr, CD, CD,
            QH, KH, att_b1 + i*CD,
            att_w2 + (size_t)i*CD*CD, att_b2 + i*CD,
            V, nn_i, Tq, k, Tt, tok_q, tq);

        bn_partial <<<BN_BLOCKS, 256>>>(tq, Mq, nullptr, 0, psum, psq);
        bn_finalize<<<1, 256>>>(psum, psq, BN_BLOCKS, Mq, bn2_g + i*CD, bn2_b + i*CD, stats);

        tf32gemm<1><<<dim3(2*CD/TBN, Mq/TBM), 256, SMEM_PLAIN>>>(Mq, 2*CD, CD, CD, 2*CD,
            tq, mlp_w1 + (size_t)i*CD*2*CD, stats, mlp_b1 + i*2*CD, nullptr, mlph, 1);
        tf32gemm<0><<<dim3(CD/TBN, Mq/TBM), 256, SMEM_PLAIN>>>(Mq, CD, 2*CD, 2*CD, CD,
            mlph, mlp_w2 + (size_t)i*2*CD*CD, nullptr, mlp_b2 + i*CD, tq, tok_buf, 0);

        tok_src = tok_buf;
    }

    pool_kernel     <<<BQN, 256>>>(tok_buf, pool, 128);
    emb_kernel      <<<BQN, 512>>>(pool, emb_w, emb_b, embv);
    final_bn_kernel <<<1, 512>>>(embv, embn_g, embn_b);
    topk_norm_kernel<<<BQN, 512>>>(embv, (float*)d_out);
}

// round 16
// speedup vs baseline: 1.3325x; 1.0013x over previous
#include <cuda_runtime.h>
#include <math.h>
#include <stdint.h>

#define INF_F (__int_as_float(0x7f800000))

// ---------------- problem constants ----------------
#define BQN 16
#define T0 1024
#define CD 256
#define ED 512
#define MAXROWS 131072
#define BN_BLOCKS 256
#define KHVW 768      // KH | V | QH packed width

// ---------------- static device scratch ----------------
__device__ float g_tokens_t[BQN*T0*CD];
__device__ float g_tokens_q[BQN*512*CD];
__device__ float g_tq      [BQN*512*CD];
__device__ float g_KHV     [BQN*T0*KHVW];      // 50MB: [KH | V | QHall]
__device__ float g_mlph    [BQN*512*2*CD];
__device__ float g_wkhv    [3*CD*KHVW];        // packed weights per stage
__device__ float g_cent0   [BQN*512*3];
__device__ float g_cent1   [BQN*256*3];
__device__ float g_cent2   [BQN*128*3];
__device__ int   g_rep[3*BQN*512];
__device__ int   g_nn [3*MAXROWS];
__device__ float g_psum[BN_BLOCKS*CD];
__device__ float g_psq [BN_BLOCKS*CD];
__device__ float g_stats[2*CD];   // [scale | shift]
__device__ float g_pool[BQN*CD];
__device__ float g_embv[BQN*ED];

// ---------------- FPS ----------------
__global__ void fps_kernel(const float* __restrict__ centers, int Tt, int Tq,
                           int* __restrict__ rep_idx) {
    int b = blockIdx.x;
    const float* P = centers + (size_t)b * Tt * 3;
    __shared__ float sx[1024], sy[1024], sz[1024];
    __shared__ float s_bv[8];
    __shared__ int   s_bi[8];
    __shared__ int   s_cur;
    int tid = threadIdx.x;
    int npt = Tt >> 8;
    float d[4];
#pragma unroll
    for (int j = 0; j < 4; j++) d[j] = INF_F;
    for (int j = tid; j < Tt; j += 256) {
        sx[j] = P[j*3+0]; sy[j] = P[j*3+1]; sz[j] = P[j*3+2];
    }
    if (tid == 0) s_cur = 0;
    __syncthreads();

    for (int step = 0; step < Tq; step++) {
        int cur = s_cur;
        if (tid == 0) rep_idx[b*Tq + step] = cur;
        float cx = sx[cur], cy = sy[cur], cz = sz[cur];
        float bv = -INF_F; int bi = 0x7fffffff;
#pragma unroll
        for (int j = 0; j < 4; j++) {
            if (j < npt) {
                int p = j*256 + tid;
                float dx = sx[p]-cx, dy = sy[p]-cy, dz = sz[p]-cz;
                float dist = dx*dx + dy*dy + dz*dz;
                float dj = fminf(d[j], dist);
                d[j] = dj;
                if (dj > bv || (dj == bv && p < bi)) { bv = dj; bi = p; }
            }
        }
#pragma unroll
        for (int off = 16; off > 0; off >>= 1) {
            float ov = __shfl_down_sync(0xffffffffu, bv, off);
            int   oi = __shfl_down_sync(0xffffffffu, bi, off);
            if (ov > bv || (ov == bv && oi < bi)) { bv = ov; bi = oi; }
        }
        if ((tid & 31) == 0) { s_bv[tid>>5] = bv; s_bi[tid>>5] = bi; }
        __syncthreads();
        if (tid == 0) {
            bv = s_bv[0]; bi = s_bi[0];
            for (int w = 1; w < 8; w++) {
                if (s_bv[w] > bv || (s_bv[w] == bv && s_bi[w] < bi)) { bv = s_bv[w]; bi = s_bi[w]; }
            }
            s_cur = bi;
        }
        __syncthreads();
    }
}

// ---------------- split gathers ----------------
__global__ void gather_cent(const float* __restrict__ cent_t,
                            const int* __restrict__ rep,
                            float* __restrict__ cent_q, int Tt, int Tq, int n3) {
    int idx = blockIdx.x*blockDim.x + threadIdx.x;
    if (idx >= n3) return;
    int p = idx/3, c = idx%3;
    int b = p / Tq;
    cent_q[idx] = cent_t[(size_t)(b*Tt + rep[p])*3 + c];
}

__global__ void gather_tok(const float* __restrict__ tok_t,
                           const int* __restrict__ rep,
                           float* __restrict__ tok_q, int Tt, int Tq) {
    int p = blockIdx.x;
    int b = p / Tq;
    int src = rep[p];
    int c = threadIdx.x;
    tok_q[(size_t)p*CD + c] = tok_t[(size_t)(b*Tt + src)*CD + c];
}

// ---------------- KNN ----------------
__global__ void knn_kernel(const float* __restrict__ cent_q,
                           const float* __restrict__ cent_t,
                           int Tt, int Tq, int k, int* __restrict__ nn) {
    int p = blockIdx.x;
    int b = p / Tq;
    __shared__ float d2s[1024];
    __shared__ float s_bv[8];
    __shared__ int   s_bi[8];
    int tid = threadIdx.x;
    float qx = cent_q[p*3], qy = cent_q[p*3+1], qz = cent_q[p*3+2];
    float qq = qx*qx + qy*qy + qz*qz;
    const float* Pt = cent_t + (size_t)b*Tt*3;
    for (int t = tid; t < Tt; t += 256) {
        float tx = Pt[t*3], ty = Pt[t*3+1], tz = Pt[t*3+2];
        float tt = tx*tx + ty*ty + tz*tz;
        float dt = qx*tx + qy*ty + qz*tz;
        d2s[t] = (qq + tt) - 2.0f*dt;
    }
    __syncthreads();
    for (int sel = 0; sel < k; sel++) {
        float bv = INF_F; int bi = 0x7fffffff;
        for (int t = tid; t < Tt; t += 256) {
            float v = d2s[t];
            if (v < bv || (v == bv && t < bi)) { bv = v; bi = t; }
        }
#pragma unroll
        for (int off = 16; off > 0; off >>= 1) {
            float ov = __shfl_down_sync(0xffffffffu, bv, off);
            int   oi = __shfl_down_sync(0xffffffffu, bi, off);
            if (ov < bv || (ov == bv && oi < bi)) { bv = ov; bi = oi; }
        }
        if ((tid & 31) == 0) { s_bv[tid>>5] = bv; s_bi[tid>>5] = bi; }
        __syncthreads();
        if (tid == 0) {
            bv = s_bv[0]; bi = s_bi[0];
            for (int w = 1; w < 8; w++) {
                if (s_bv[w] < bv || (s_bv[w] == bv && s_bi[w] < bi)) { bv = s_bv[w]; bi = s_bi[w]; }
            }
            nn[p*k + sel] = bi;
            d2s[bi] = INF_F;
        }
        __syncthreads();
    }
}

// ---------------- BN stats ----------------
__global__ void bn_partial(const float* __restrict__ x1, int rows1,
                           const float* __restrict__ x2, int rows2,
                           float* __restrict__ psum, float* __restrict__ psq) {
    __shared__ float ssum[4][CD];
    __shared__ float ssq [4][CD];
    int tid  = threadIdx.x;
    int cg   = (tid & 63) * 4;
    int rsub = tid >> 6;
    int total = rows1 + rows2;
    float4 s  = make_float4(0.f, 0.f, 0.f, 0.f);
    float4 sq = make_float4(0.f, 0.f, 0.f, 0.f);
    for (int r = blockIdx.x*4 + rsub; r < total; r += gridDim.x*4) {
        const float* row = (r < rows1) ? (x1 + (size_t)r*CD) : (x2 + (size_t)(r - rows1)*CD);
        float4 v = *(const float4*)(row + cg);
        s.x += v.x; s.y += v.y; s.z += v.z; s.w += v.w;
        sq.x += v.x*v.x; sq.y += v.y*v.y; sq.z += v.z*v.z; sq.w += v.w*v.w;
    }
    *(float4*)(&ssum[rsub][cg]) = s;
    *(float4*)(&ssq [rsub][cg]) = sq;
    __syncthreads();
    if (rsub == 0) {
#pragma unroll
        for (int j = 0; j < 4; j++) {
            int c = cg + j;
            float a = ssum[0][c] + ssum[1][c] + ssum[2][c] + ssum[3][c];
            float b = ssq [0][c] + ssq [1][c] + ssq [2][c] + ssq [3][c];
            psum[blockIdx.x*CD + c] = a;
            psq [blockIdx.x*CD + c] = b;
        }
    }
}

__global__ void bn_finalize(const float* __restrict__ psum, const float* __restrict__ psq,
                            int nb, int rows,
                            const float* __restrict__ gamma, const float* __restrict__ beta,
                            float* __restrict__ stats) {
    int c = threadIdx.x;
    float s = 0.f, sq = 0.f;
#pragma unroll 8
    for (int b = 0; b < nb; b++) { s += psum[b*CD + c]; sq += psq[b*CD + c]; }
    float m = s / (float)rows;
    float v = sq / (float)rows - m*m;
    float rstd = rsqrtf(v + 1e-5f);
    float sc = gamma[c] * rstd;
    stats[c]      = sc;
    stats[CD + c] = beta[c] - m * sc;
}

// ---------------- exact-fp32 weight product (strided output) ----------------
__global__ void wprod_kernel(const float* __restrict__ A, int lda,
                             const float* __restrict__ B, int ldb,
                             float* __restrict__ C, int ldc) {
    __shared__ float arow[2][CD];
    int r0 = blockIdx.x*2;
    int tid = threadIdx.x;
    arow[0][tid] = A[(size_t)(r0+0)*lda + tid];
    arow[1][tid] = A[(size_t)(r0+1)*lda + tid];
    __syncthreads();
    float acc0 = 0.f, acc1 = 0.f;
#pragma unroll 16
    for (int c = 0; c < CD; c++) {
        float bv = __ldg(&B[(size_t)c*ldb + tid]);
        acc0 += arow[0][c]*bv;
        acc1 += arow[1][c]*bv;
    }
    C[(size_t)(r0+0)*ldc + tid] = acc0;
    C[(size_t)(r0+1)*ldc + tid] = acc1;
}

// pack wkv V-half into wkhv columns [256, 512)
__global__ void pack_wv(const float* __restrict__ wkv, float* __restrict__ wkhv) {
    int r = blockIdx.x, c = threadIdx.x;
    wkhv[(size_t)r*KHVW + CD + c] = wkv[(size_t)r*2*CD + CD + c];
}

// ---------------- TF32 tensor-core GEMM, TBK=32, 2-stage cp.async ----------------
#define TBM 128
#define TBN 128
#define TBK 32
#define AS_STRIDE 36
#define BS_STRIDE 136
#define A_ELEMS (TBM*AS_STRIDE)
#define B_ELEMS (TBK*BS_STRIDE)

__device__ __forceinline__ void mma_tf32(float* c, const uint32_t* a, const uint32_t* b) {
    asm volatile(
        "mma.sync.aligned.m16n8k8.row.col.f32.tf32.tf32.f32 "
        "{%0,%1,%2,%3}, {%4,%5,%6,%7}, {%8,%9}, {%0,%1,%2,%3};\n"
        : "+f"(c[0]), "+f"(c[1]), "+f"(c[2]), "+f"(c[3])
        : "r"(a[0]), "r"(a[1]), "r"(a[2]), "r"(a[3]),
          "r"(b[0]), "r"(b[1]));
}

__device__ __forceinline__ void cp_async16(uint32_t dst, const void* src) {
    asm volatile("cp.async.cg.shared.global [%0], [%1], 16;" :: "r"(dst), "l"(src));
}
__device__ __forceinline__ void cp_commit() {
    asm volatile("cp.async.commit_group;");
}
__device__ __forceinline__ void cp_wait1() {
    asm volatile("cp.async.wait_group 1;");
}

// MODE 0: plain A. MODE 1: A[r]=relu(QH-KH[nn]+b1) (offsets absolute). MODE 2: A*sc+sh.
template<int MODE>
__device__ __forceinline__ void gemm_mainloop(
    float acc[4][4][4],
    const float* __restrict__ A, int lda,
    const float* __restrict__ QH, const float* __restrict__ KH,
    const int* sQoff, const int* sKoff,
    const float* sc_s, const float* sh_s,
    const float* __restrict__ B, int ldb,
    int K, int row0, int col0,
    float* smem, int STAGE,
    int tid, int lane, int wm, int wn)
{
    int ldrow = tid >> 3;
    int ldcol = (tid & 7) * 4;

    auto load_stage = [&](int s, int kt) {
        float* As_  = smem + s*STAGE;
        float* Akv_ = As_ + A_ELEMS;
        float* Bs_  = As_ + (MODE == 1 ? 2*A_ELEMS : A_ELEMS);
#pragma unroll
        for (int i = 0; i < 4; i++) {
            int arow = ldrow + 32*i;
            uint32_t dA = (uint32_t)__cvta_generic_to_shared(&As_[arow*AS_STRIDE + ldcol]);
            if (MODE == 1) {
                cp_async16(dA, QH + sQoff[arow] + kt + ldcol);
                uint32_t dK = (uint32_t)__cvta_generic_to_shared(&Akv_[arow*AS_STRIDE + ldcol]);
                cp_async16(dK, KH + sKoff[arow] + kt + ldcol);
            } else {
                cp_async16(dA, A + (size_t)(row0 + arow)*lda + kt + ldcol);
            }
        }
#pragma unroll
        for (int i = 0; i < 4; i++) {
            int bcol = ldcol + 32*i;
            uint32_t dB = (uint32_t)__cvta_generic_to_shared(&Bs_[ldrow*BS_STRIDE + bcol]);
            cp_async16(dB, B + (size_t)(kt + ldrow)*ldb + col0 + bcol);
        }
    };

    const int NIT = K / TBK;
    load_stage(0, 0);
    cp_commit();

    for (int it = 0; it < NIT; it++) {
        if (it + 1 < NIT) load_stage((it+1)&1, (it+1)*TBK);
        cp_commit();
        cp_wait1();
        __syncthreads();

        int s = it & 1;
        int ktg = it*TBK;
        const float* As_  = smem + s*STAGE;
        const float* Akv_ = As_ + A_ELEMS;
        const float* Bs_  = As_ + (MODE == 1 ? 2*A_ELEMS : A_ELEMS);

#pragma unroll
        for (int kk = 0; kk < 4; kk++) {
            int kc = kk*8;
            float cA = 0.f, cB = 0.f, hA = 0.f, hB = 0.f;
            if (MODE == 1) {
                cA = sc_s[ktg + kc + (lane&3)];
                cB = sc_s[ktg + kc + 4 + (lane&3)];
            } else if (MODE == 2) {
                cA = sc_s[ktg + kc + (lane&3)];
                cB = sc_s[ktg + kc + 4 + (lane&3)];
                hA = sh_s[ktg + kc + (lane&3)];
                hB = sh_s[ktg + kc + 4 + (lane&3)];
            }
            uint32_t a[4][4];
#pragma unroll
            for (int mf = 0; mf < 4; mf++) {
                int r1 = wm*64 + mf*16 + (lane>>2);
                int i0 = r1*AS_STRIDE      + kc + (lane&3);
                int i1 = (r1+8)*AS_STRIDE  + kc + (lane&3);
                if (MODE == 1) {
                    a[mf][0] = __float_as_uint(fmaxf(As_[i0]     - Akv_[i0]     + cA, 0.f));
                    a[mf][1] = __float_as_uint(fmaxf(As_[i1]     - Akv_[i1]     + cA, 0.f));
                    a[mf][2] = __float_as_uint(fmaxf(As_[i0 + 4] - Akv_[i0 + 4] + cB, 0.f));
                    a[mf][3] = __float_as_uint(fmaxf(As_[i1 + 4] - Akv_[i1 + 4] + cB, 0.f));
                } else if (MODE == 2) {
                    a[mf][0] = __float_as_uint(fmaf(As_[i0],     cA, hA));
                    a[mf][1] = __float_as_uint(fmaf(As_[i1],     cA, hA));
                    a[mf][2] = __float_as_uint(fmaf(As_[i0 + 4], cB, hB));
                    a[mf][3] = __float_as_uint(fmaf(As_[i1 + 4], cB, hB));
                } else {
                    a[mf][0] = __float_as_uint(As_[i0]);
                    a[mf][1] = __float_as_uint(As_[i1]);
                    a[mf][2] = __float_as_uint(As_[i0 + 4]);
                    a[mf][3] = __float_as_uint(As_[i1 + 4]);
                }
            }
            uint32_t b[4][2];
#pragma unroll
            for (int nf = 0; nf < 4; nf++) {
                int ncol = wn*32 + nf*8 + (lane>>2);
                b[nf][0] = __float_as_uint(Bs_[(kc     + (lane&3))*BS_STRIDE + ncol]);
                b[nf][1] = __float_as_uint(Bs_[(kc + 4 + (lane&3))*BS_STRIDE + ncol]);
            }
#pragma unroll
            for (int mf = 0; mf < 4; mf++)
#pragma unroll
                for (int nf = 0; nf < 4; nf++)
                    mma_tf32(acc[mf][nf], a[mf], b[nf]);
        }
        __syncthreads();
    }
}

template<int BN>
__global__ __launch_bounds__(256, 2)
void tf32gemm(int M, int N, int K, int lda, int ldb, int ldc,
              const float* __restrict__ A,
              const float* __restrict__ B,
              const float* __restrict__ bnstats,
              const float* __restrict__ bias, const float* __restrict__ resid,
              float* __restrict__ C, int relu) {
    extern __shared__ float smem[];
    const int STAGE = A_ELEMS + B_ELEMS;
    __shared__ float scs[CD], shs[CD];

    int tid  = threadIdx.x;
    int lane = tid & 31;
    int warp = tid >> 5;
    int wm = warp >> 2;
    int wn = warp & 3;
    int row0 = blockIdx.y*TBM;
    int col0 = blockIdx.x*TBN;

    if (BN) {
        scs[tid] = bnstats[tid];
        shs[tid] = bnstats[CD + tid];
        __syncthreads();
    }

    float acc[4][4][4];
#pragma unroll
    for (int i = 0; i < 4; i++)
#pragma unroll
        for (int j = 0; j < 4; j++)
#pragma unroll
            for (int r = 0; r < 4; r++) acc[i][j][r] = 0.f;

    gemm_mainloop<BN ? 2 : 0>(acc, A, lda, nullptr, nullptr, nullptr, nullptr,
                              scs, shs, B, ldb, K, row0, col0,
                              smem, STAGE, tid, lane, wm, wn);

#pragma unroll
    for (int mf = 0; mf < 4; mf++) {
#pragma unroll
        for (int nf = 0; nf < 4; nf++) {
            int r = row0 + wm*64 + mf*16 + (lane>>2);
            int c = col0 + wn*32 + nf*8 + (lane&3)*2;
#pragma unroll
            for (int half = 0; half < 2; half++) {
                int rr = r + half*8;
                float v0 = acc[mf][nf][half*2+0];
                float v1 = acc[mf][nf][half*2+1];
                if (bias)  { v0 += bias[c]; v1 += bias[c+1]; }
                if (resid) {
                    const float2 rv = *(const float2*)(resid + (size_t)rr*ldc + c);
                    v0 += rv.x; v1 += rv.y;
                }
                if (relu) { v0 = fmaxf(v0, 0.f); v1 = fmaxf(v1, 0.f); }
                float2 out; out.x = v0; out.y = v1;
                *(float2*)(C + (size_t)rr*ldc + c) = out;
            }
        }
    }
}

// fused attention GEMM: Q/K/V packed in KHV (stride KHVW)
#define SIM_STRIDE 132
__global__ __launch_bounds__(256, 2)
void tf32gemm_attn(int M, int N, int K,
                   const float* __restrict__ KHV,
                   const int* __restrict__ rep,
                   const int* __restrict__ nn,
                   const float* __restrict__ b1,
                   const float* __restrict__ B,
                   const float* __restrict__ bias,
                   int Tq, int knn_k, int Tt,
                   const float* __restrict__ skipb,
                   float* __restrict__ out) {
    extern __shared__ float smem[];
    const int STAGE = 2*A_ELEMS + B_ELEMS;
    __shared__ int   sQoff[TBM];
    __shared__ int   sKoff[TBM];
    __shared__ float b1s[CD];

    int tid  = threadIdx.x;
    int lane = tid & 31;
    int warp = tid >> 5;
    int wm = warp >> 2;
    int wn = warp & 3;
    int row0 = blockIdx.y*TBM;
    int col0 = blockIdx.x*TBN;

    if (tid < TBM) {
        int r = row0 + tid;
        int p = r / knn_k;
        int b = p / Tq;
        sQoff[tid] = (b*Tt + rep[p]) * KHVW + 2*CD;   // QHall slice
        sKoff[tid] = (b*Tt + nn[r])  * KHVW;          // KH slice
    }
    b1s[tid] = b1[tid];
    __syncthreads();

    float acc[4][4][4];
#pragma unroll
    for (int i = 0; i < 4; i++)
#pragma unroll
        for (int j = 0; j < 4; j++)
#pragma unroll
            for (int r = 0; r < 4; r++) acc[i][j][r] = 0.f;

    gemm_mainloop<1>(acc, nullptr, 0, KHV, KHV, sQoff, sKoff, b1s, nullptr,
                     B, CD, K, row0, col0, smem, STAGE, tid, lane, wm, wn);

    float* sim_s = smem;
#pragma unroll
    for (int mf = 0; mf < 4; mf++) {
#pragma unroll
        for (int nf = 0; nf < 4; nf++) {
            int r = wm*64 + mf*16 + (lane>>2);
            int c = wn*32 + nf*8 + (lane&3)*2;
#pragma unroll
            for (int half = 0; half < 2; half++) {
                int rr = r + half*8;
                float v0 = acc[mf][nf][half*2+0] + bias[col0 + c];
                float v1 = acc[mf][nf][half*2+1] + bias[col0 + c + 1];
                sim_s[rr*SIM_STRIDE + c]     = v0;
                sim_s[rr*SIM_STRIDE + c + 1] = v1;
            }
        }
    }
    __syncthreads();

    int ppb = TBM / knn_k;
    int col = tid & 127;
    int cg  = col0 + col;
    for (int pp = tid >> 7; pp < ppb; pp += 2) {
        const float* Sp = sim_s + (pp*knn_k)*SIM_STRIDE + col;
        float m = -INF_F;
        for (int n = 0; n < knn_k; n++) m = fmaxf(m, Sp[n*SIM_STRIDE]);
        float den = 0.f, accv = 0.f;
        for (int n = 0; n < knn_k; n++) {
            float e = expf(Sp[n*SIM_STRIDE] - m);
            den += e;
            accv += e * KHV[(size_t)sKoff[pp*knn_k + n] + CD + cg];   // V slice
        }
        int pg = row0/knn_k + pp;
        out[(size_t)pg*CD + cg] = accv/den + skipb[(size_t)pg*CD + cg];
    }
}

// ---------------- final pooling / embedding ----------------
__global__ void pool_kernel(const float* __restrict__ tok, float* __restrict__ g, int Tq) {
    int b = blockIdx.x, c = threadIdx.x;
    float s = 0.f;
    for (int t = 0; t < Tq; t++) s += tok[(size_t)(b*Tq + t)*CD + c];
    g[b*CD + c] = s / (float)Tq;
}

__global__ void emb_kernel(const float* __restrict__ g, const float* __restrict__ W,
                           const float* __restrict__ bias, float* __restrict__ out) {
    int b = blockIdx.x, e = threadIdx.x;
    __shared__ float gs[CD];
    if (e < CD) gs[e] = g[b*CD + e];
    __syncthreads();
    float s = 0.f;
    for (int c = 0; c < CD; c++) s += gs[c] * W[(size_t)c*ED + e];
    out[b*ED + e] = s + bias[e];
}

__global__ void final_bn_kernel(float* __restrict__ x, const float* __restrict__ gamma,
                                const float* __restrict__ beta) {
    int e = threadIdx.x;
    float s = 0.f;
    for (int b = 0; b < BQN; b++) s += x[b*ED + e];
    float m = s / (float)BQN;
    float v = 0.f;
    for (int b = 0; b < BQN; b++) { float d = x[b*ED + e] - m; v += d*d; }
    v /= (float)BQN;
    float rs = rsqrtf(v + 1e-5f);
    for (int b = 0; b < BQN; b++) {
        float val = (x[b*ED + e] - m) * rs * gamma[e] + beta[e];
        x[b*ED + e] = fmaxf(val, 0.f);
    }
}

__global__ void topk_norm_kernel(const float* __restrict__ x, float* __restrict__ out) {
    int b = blockIdx.x, t = threadIdx.x;
    __shared__ float vals[ED], work[ED];
    __shared__ float red[16];
    __shared__ int   redi[16];
    __shared__ float s_thr, s_norm;
    float v = x[b*ED + t];
    vals[t] = v; work[t] = v;
    __syncthreads();
    for (int it = 0; it < 64; it++) {
        float bv = work[t]; int bi = t;
#pragma unroll
        for (int off = 16; off > 0; off >>= 1) {
            float ov = __shfl_down_sync(0xffffffffu, bv, off);
            int   oi = __shfl_down_sync(0xffffffffu, bi, off);
            if (ov > bv) { bv = ov; bi = oi; }
        }
        if ((t & 31) == 0) { red[t>>5] = bv; redi[t>>5] = bi; }
        __syncthreads();
        if (t == 0) {
            bv = red[0]; bi = redi[0];
            for (int w = 1; w < 16; w++) if (red[w] > bv) { bv = red[w]; bi = redi[w]; }
            work[bi] = -INF_F;
            if (it == 63) s_thr = bv;
        }
        __syncthreads();
    }
    float thr = s_thr;
    float kept = (vals[t] >= thr) ? vals[t] : 0.f;
    float sq = kept*kept;
#pragma unroll
    for (int off = 16; off > 0; off >>= 1) sq += __shfl_down_sync(0xffffffffu, sq, off);
    if ((t & 31) == 0) red[t>>5] = sq;
    __syncthreads();
    if (t == 0) {
        float s = 0.f;
        for (int w = 0; w < 16; w++) s += red[w];
        s_norm = fmaxf(sqrtf(s), 1e-12f);
    }
    __syncthreads();
    out[b*ED + t] = kept / s_norm;
}

// ---------------- host orchestration ----------------
extern "C" void kernel_launch(void* const* d_in, const int* in_sizes, int n_in,
                              void* d_out, int out_size) {
    const float* tokens = (const float*)d_in[0];
    const float* centers = (const float*)d_in[1];
    const float* wq     = (const float*)d_in[3];
    const float* wkv    = (const float*)d_in[4];
    const float* mlp_w1 = (const float*)d_in[5];
    const float* mlp_b1 = (const float*)d_in[6];
    const float* mlp_w2 = (const float*)d_in[7];
    const float* mlp_b2 = (const float*)d_in[8];
    const float* bn1_g  = (const float*)d_in[9];
    const float* bn1_b  = (const float*)d_in[10];
    const float* bn2_g  = (const float*)d_in[11];
    const float* bn2_b  = (const float*)d_in[12];
    const float* att_w1 = (const float*)d_in[13];
    const float* att_b1 = (const float*)d_in[14];
    const float* att_w2 = (const float*)d_in[15];
    const float* att_b2 = (const float*)d_in[16];
    const float* emb_w  = (const float*)d_in[17];
    const float* emb_b  = (const float*)d_in[18];
    const float* embn_g = (const float*)d_in[19];
    const float* embn_b = (const float*)d_in[20];

    float *tok_buf, *tok_q, *tq, *KHV, *mlph, *wkhv;
    float *cent0, *cent1, *cent2, *psum, *psq, *stats, *pool, *embv;
    int *rep, *nn;
    cudaGetSymbolAddress((void**)&tok_buf, g_tokens_t);
    cudaGetSymbolAddress((void**)&tok_q,  g_tokens_q);
    cudaGetSymbolAddress((void**)&tq,     g_tq);
    cudaGetSymbolAddress((void**)&KHV,    g_KHV);
    cudaGetSymbolAddress((void**)&mlph,   g_mlph);
    cudaGetSymbolAddress((void**)&wkhv,   g_wkhv);
    cudaGetSymbolAddress((void**)&cent0,  g_cent0);
    cudaGetSymbolAddress((void**)&cent1,  g_cent1);
    cudaGetSymbolAddress((void**)&cent2,  g_cent2);
    cudaGetSymbolAddress((void**)&psum,   g_psum);
    cudaGetSymbolAddress((void**)&psq,    g_psq);
    cudaGetSymbolAddress((void**)&stats,  g_stats);
    cudaGetSymbolAddress((void**)&pool,   g_pool);
    cudaGetSymbolAddress((void**)&embv,   g_embv);
    cudaGetSymbolAddress((void**)&rep,    g_rep);
    cudaGetSymbolAddress((void**)&nn,     g_nn);

    const int SMEM_PLAIN = 2*(A_ELEMS + B_ELEMS)*sizeof(float);
    const int SMEM_ATTN  = 2*(2*A_ELEMS + B_ELEMS)*sizeof(float);
    static cudaStream_t s1, s2;
    static cudaEvent_t evFork, evW0, evW1, evJall, evG[3];
    static bool init_done = false;
    if (!init_done) {
        cudaFuncSetAttribute(tf32gemm<0>,   cudaFuncAttributeMaxDynamicSharedMemorySize, SMEM_PLAIN);
        cudaFuncSetAttribute(tf32gemm<1>,   cudaFuncAttributeMaxDynamicSharedMemorySize, SMEM_PLAIN);
        cudaFuncSetAttribute(tf32gemm_attn, cudaFuncAttributeMaxDynamicSharedMemorySize, SMEM_ATTN);
        cudaStreamCreateWithFlags(&s1, cudaStreamNonBlocking);
        cudaStreamCreateWithFlags(&s2, cudaStreamNonBlocking);
        cudaEventCreateWithFlags(&evFork, cudaEventDisableTiming);
        cudaEventCreateWithFlags(&evW0,   cudaEventDisableTiming);
        cudaEventCreateWithFlags(&evW1,   cudaEventDisableTiming);
        cudaEventCreateWithFlags(&evJall, cudaEventDisableTiming);
        for (int i = 0; i < 3; i++) cudaEventCreateWithFlags(&evG[i], cudaEventDisableTiming);
        init_done = true;
    }

    const int Tts[3] = {1024, 512, 256};
    const int Tqs[3] = {512, 256, 128};
    const int ks [3] = {16, 32, 64};
    float* cents[3] = {cent0, cent1, cent2};

    // ---- fork input-only work ----
    cudaEventRecord(evFork, 0);
    cudaStreamWaitEvent(s1, evFork, 0);
    cudaStreamWaitEvent(s2, evFork, 0);

    // s2: packed weights. Stage 0: wkh (cols 0..255) then wqh (cols 512..767).
    wprod_kernel<<<128, 256, 0, s2>>>(wkv, 2*CD, att_w1, CD, wkhv, KHVW);
    cudaEventRecord(evW0, s2);
    wprod_kernel<<<128, 256, 0, s2>>>(wq, CD, att_w1, CD, wkhv + 2*CD, KHVW);
    cudaEventRecord(evW1, s2);
    for (int i = 1; i < 3; i++) {
        float* wkhv_i = wkhv + (size_t)i*CD*KHVW;
        wprod_kernel<<<128, 256, 0, s2>>>(wkv + (size_t)i*CD*2*CD, 2*CD,
                                          att_w1 + (size_t)i*CD*CD, CD, wkhv_i, KHVW);
        pack_wv<<<CD, 256, 0, s2>>>(wkv + (size_t)i*CD*2*CD, wkhv_i);
        wprod_kernel<<<128, 256, 0, s2>>>(wq + (size_t)i*CD*CD, CD,
                                          att_w1 + (size_t)i*CD*CD, CD, wkhv_i + 2*CD, KHVW);
    }
    cudaEventRecord(evJall, s2);

    // s1: geometry chain (depends only on input centers)
    {
        const float* cs = centers;
        for (int i = 0; i < 3; i++) {
            int Tt = Tts[i], Tq = Tqs[i], k = ks[i];
            int Mq = BQN*Tq;
            fps_kernel<<<BQN, 256, 0, s1>>>(cs, Tt, Tq, rep + i*BQN*512);
            int n3 = Mq*3;
            gather_cent<<<(n3+255)/256, 256, 0, s1>>>(cs, rep + i*BQN*512, cents[i], Tt, Tq, n3);
            knn_kernel<<<Mq, 256, 0, s1>>>(cents[i], cs, Tt, Tq, k, nn + (size_t)i*MAXROWS);
            cudaEventRecord(evG[i], s1);
            cs = cents[i];
        }
    }

    const float* tok_src = tokens;

    for (int i = 0; i < 3; i++) {
        int Tt = Tts[i], Tq = Tqs[i], k = ks[i];
        int Mq = BQN*Tq, Mt = BQN*Tt, Mr = Mq*k;
        const float* wkhv_i = wkhv + (size_t)i*CD*KHVW;
        const int*   rep_i = rep + i*BQN*512;
        const int*   nn_i  = nn + (size_t)i*MAXROWS;

        if (i == 0) {
            // V0 first: raw tokens + wkv only (overlaps wprods + fps0)
            tf32gemm<0><<<dim3(CD/TBN, Mt/TBM), 256, SMEM_PLAIN>>>(Mt, CD, CD, CD, 2*CD, KHVW,
                tok_src, wkv + CD, nullptr, nullptr, nullptr, KHV + CD, 0);
            cudaStreamWaitEvent(0, evW0, 0);
            tf32gemm<0><<<dim3(CD/TBN, Mt/TBM), 256, SMEM_PLAIN>>>(Mt, CD, CD, CD, KHVW, KHVW,
                tok_src, wkhv_i, nullptr, nullptr, nullptr, KHV, 0);
            cudaStreamWaitEvent(0, evG[0], 0);
            gather_tok<<<Mq, 256>>>(tok_src, rep_i, tok_q, Tt, Tq);
            cudaStreamWaitEvent(0, evW1, 0);
            tf32gemm<0><<<dim3(CD/TBN, Mt/TBM), 256, SMEM_PLAIN>>>(Mt, CD, CD, CD, KHVW, KHVW,
                tok_src, wkhv_i + 2*CD, nullptr, nullptr, nullptr, KHV + 2*CD, 0);
        } else {
            if (i == 1) cudaStreamWaitEvent(0, evJall, 0);
            cudaStreamWaitEvent(0, evG[i], 0);
            gather_tok<<<Mq, 256>>>(tok_src, rep_i, tok_q, Tt, Tq);
            bn_partial <<<BN_BLOCKS, 256>>>(tok_q, Mq, tok_src, Mt, psum, psq);
            bn_finalize<<<1, 256>>>(psum, psq, BN_BLOCKS, Mq + Mt, bn1_g + i*CD, bn1_b + i*CD, stats);

            // single merged GEMM: [KH | V | QHall] = bn(tok_src) @ wkhv_i
            tf32gemm<1><<<dim3(KHVW/TBN, Mt/TBM), 256, SMEM_PLAIN>>>(Mt, KHVW, CD, CD, KHVW, KHVW,
                tok_src, wkhv_i, stats, nullptr, nullptr, KHV, 0);
        }

        tf32gemm_attn<<<dim3(CD/TBN, Mr/TBM), 256, SMEM_ATTN>>>(Mr, CD, CD,
            KHV, rep_i, nn_i, att_b1 + i*CD,
            att_w2 + (size_t)i*CD*CD, att_b2 + i*CD,
            Tq, k, Tt, tok_q, tq);

        bn_partial <<<BN_BLOCKS, 256>>>(tq, Mq, nullptr, 0, psum, psq);
        bn_finalize<<<1, 256>>>(psum, psq, BN_BLOCKS, Mq, bn2_g + i*CD, bn2_b + i*CD, stats);

        tf32gemm<1><<<dim3(2*CD/TBN, Mq/TBM), 256, SMEM_PLAIN>>>(Mq, 2*CD, CD, CD, 2*CD, 2*CD,
            tq, mlp_w1 + (size_t)i*CD*2*CD, stats, mlp_b1 + i*2*CD, nullptr, mlph, 1);
        tf32gemm<0><<<dim3(CD/TBN, Mq/TBM), 256, SMEM_PLAIN>>>(Mq, CD, 2*CD, 2*CD, CD, CD,
            mlph, mlp_w2 + (size_t)i*2*CD*CD, nullptr, mlp_b2 + i*CD, tq, tok_buf, 0);

        tok_src = tok_buf;
    }

    pool_kernel     <<<BQN, 256>>>(tok_buf, pool, 128);
    emb_kernel      <<<BQN, 512>>>(pool, emb_w, emb_b, embv);
    final_bn_kernel <<<1, 512>>>(embv, embn_g, embn_b);
    topk_norm_kernel<<<BQN, 512>>>(embv, (float*)d_out);
}